// round 2
// baseline (speedup 1.0000x reference)
#include <cuda_runtime.h>
#include <math.h>

// ---------------- problem constants ----------------
#define BB    4
#define LL    2048
#define HH    1024
#define NQH   8
#define NKVH  2
#define DD    256
#define II    3584
#define VV    16384
#define NTOK  (BB*LL)          // 8192
#define FMIN  (-3.402823466e38f)

// ---------------- static scratch (no cudaMalloc allowed) ----------------
__device__ float g_xcat [ (size_t)NTOK * 2 * HH ];          // 67 MB
__device__ float g_x0   [ (size_t)NTOK * HH ];              // fc out / residual 1
__device__ float g_xn   [ (size_t)NTOK * HH ];
__device__ float g_qg   [ (size_t)NTOK * 4096 ];            // q+gate packed
__device__ float g_kbuf [ (size_t)NTOK * 512 ];
__device__ float g_vbuf [ (size_t)NTOK * 512 ];
__device__ float g_q    [ (size_t)BB * NQH * LL * DD ];
__device__ float g_krep [ (size_t)BB * NQH * LL * DD ];     // GQA-replicated
__device__ float g_vrep [ (size_t)BB * NQH * LL * DD ];
__device__ float g_scores[ (size_t)BB * NQH * LL * LL ];    // 537 MB
__device__ float g_attno[ (size_t)BB * NQH * LL * DD ];
__device__ float g_ao   [ (size_t)NTOK * 2048 ];
__device__ float g_x1   [ (size_t)NTOK * HH ];
__device__ float g_xn2  [ (size_t)NTOK * HH ];
__device__ float g_gbuf [ (size_t)NTOK * II ];
__device__ float g_ubuf [ (size_t)NTOK * II ];
__device__ float g_x2   [ (size_t)NTOK * HH ];
__device__ float g_xn3  [ (size_t)NTOK * HH ];

// ---------------- block reduce helpers (256 threads) ----------------
__device__ __forceinline__ float blk_sum(float v) {
    __shared__ float sh[8];
    __shared__ float res;
    #pragma unroll
    for (int o = 16; o; o >>= 1) v += __shfl_xor_sync(0xffffffffu, v, o);
    if ((threadIdx.x & 31) == 0) sh[threadIdx.x >> 5] = v;
    __syncthreads();
    if (threadIdx.x < 32) {
        float x = (threadIdx.x < 8) ? sh[threadIdx.x] : 0.f;
        #pragma unroll
        for (int o = 4; o; o >>= 1) x += __shfl_xor_sync(0xffffffffu, x, o);
        if (threadIdx.x == 0) res = x;
    }
    __syncthreads();
    return res;
}

__device__ __forceinline__ float blk_max(float v) {
    __shared__ float sh[8];
    __shared__ float res;
    #pragma unroll
    for (int o = 16; o; o >>= 1) v = fmaxf(v, __shfl_xor_sync(0xffffffffu, v, o));
    if ((threadIdx.x & 31) == 0) sh[threadIdx.x >> 5] = v;
    __syncthreads();
    if (threadIdx.x < 32) {
        float x = (threadIdx.x < 8) ? sh[threadIdx.x] : -INFINITY;
        #pragma unroll
        for (int o = 4; o; o >>= 1) x = fmaxf(x, __shfl_xor_sync(0xffffffffu, x, o));
        if (threadIdx.x == 0) res = x;
    }
    __syncthreads();
    return res;
}

// ---------------- rmsnorm: one block per token ----------------
__global__ void rmsnorm_kernel(const float* __restrict__ in, const float* __restrict__ w,
                               float* __restrict__ out, int width, long out_stride) {
    long t = blockIdx.x;
    const float* x = in + t * width;
    float* y = out + t * out_stride;
    float ss = 0.f;
    for (int i = threadIdx.x; i < width; i += 256) { float v = x[i]; ss = fmaf(v, v, ss); }
    float tot = blk_sum(ss);
    float rms = rsqrtf(tot / (float)width + 1e-6f);
    for (int i = threadIdx.x; i < width; i += 256) y[i] = x[i] * rms * w[i];
}

// ---------------- SGEMM  C[M,N] = A[M,K] * B[N,K]^T  (+ epilogues) ----------------
// epilogue 0: plain   1: C = acc + R   2: scores (acc*scale, causal mask)
#define GBM 128
#define GBN 128
#define GBK 8

__global__ __launch_bounds__(256, 2)
void gemm_nt_kernel(const float* __restrict__ A, const float* __restrict__ B,
                    float* __restrict__ C, const float* __restrict__ R,
                    int M, int N, int K,
                    long batchA, long batchB, long batchC,
                    int epilogue, float scale) {
    int z = blockIdx.z;
    const float* Ab = A + (long)z * batchA;
    const float* Bb = B + (long)z * batchB;
    float*       Cb = C + (long)z * batchC;
    int m0 = blockIdx.y * GBM;
    int n0 = blockIdx.x * GBN;

    if (epilogue == 2 && n0 > m0 + GBM - 1) {   // fully masked causal block
        float4 f = make_float4(FMIN, FMIN, FMIN, FMIN);
        for (int i = threadIdx.x; i < (GBM * GBN) / 4; i += 256) {
            int mm = i >> 5;
            int nn = (i & 31) << 2;
            *(float4*)&Cb[(long)(m0 + mm) * N + n0 + nn] = f;
        }
        return;
    }

    __shared__ float As[GBK][GBM + 4];
    __shared__ float Bs[GBK][GBN + 4];

    int tid = threadIdx.x;
    int lr = tid >> 1;
    int lk = (tid & 1) * 4;

    const float* Aptr = Ab + (long)(m0 + lr) * K + lk;
    const float* Bptr = Bb + (long)(n0 + lr) * K + lk;

    int ty = tid >> 4, tx = tid & 15;
    float acc[8][8];
    #pragma unroll
    for (int i = 0; i < 8; i++)
        #pragma unroll
        for (int j = 0; j < 8; j++) acc[i][j] = 0.f;

    float4 ar = *(const float4*)Aptr;
    float4 br = *(const float4*)Bptr;

    int ntiles = K / GBK;
    for (int t = 0; t < ntiles; ++t) {
        As[lk + 0][lr] = ar.x; As[lk + 1][lr] = ar.y; As[lk + 2][lr] = ar.z; As[lk + 3][lr] = ar.w;
        Bs[lk + 0][lr] = br.x; Bs[lk + 1][lr] = br.y; Bs[lk + 2][lr] = br.z; Bs[lk + 3][lr] = br.w;
        __syncthreads();
        if (t + 1 < ntiles) {
            ar = *(const float4*)(Aptr + (long)(t + 1) * GBK);
            br = *(const float4*)(Bptr + (long)(t + 1) * GBK);
        }
        #pragma unroll
        for (int kk = 0; kk < GBK; ++kk) {
            float a[8], b[8];
            #pragma unroll
            for (int i = 0; i < 8; i++) a[i] = As[kk][ty * 8 + i];
            #pragma unroll
            for (int j = 0; j < 8; j++) b[j] = Bs[kk][tx * 8 + j];
            #pragma unroll
            for (int i = 0; i < 8; i++)
                #pragma unroll
                for (int j = 0; j < 8; j++)
                    acc[i][j] = fmaf(a[i], b[j], acc[i][j]);
        }
        __syncthreads();
    }

    #pragma unroll
    for (int i = 0; i < 8; i++) {
        int m = m0 + ty * 8 + i;
        long rowoff = (long)m * N + n0 + tx * 8;
        #pragma unroll
        for (int j = 0; j < 8; j++) {
            float v = acc[i][j];
            if (epilogue == 1) v += R[rowoff + j];
            else if (epilogue == 2) {
                v *= scale;
                if (n0 + tx * 8 + j > m) v = FMIN;
            }
            Cb[rowoff + j] = v;
        }
    }
}

// ---------------- SGEMM  C[M,N] = A[M,K] * B[K,N]  (for P@V, causal K-limit) ----------------
__global__ __launch_bounds__(256, 2)
void gemm_nn_kernel(const float* __restrict__ A, const float* __restrict__ B,
                    float* __restrict__ C,
                    int M, int N, int K,
                    long batchA, long batchB, long batchC,
                    int klimit_causal) {
    int z = blockIdx.z;
    const float* Ab = A + (long)z * batchA;
    const float* Bb = B + (long)z * batchB;
    float*       Cb = C + (long)z * batchC;
    int m0 = blockIdx.y * GBM;
    int n0 = blockIdx.x * GBN;

    int Keff = K;
    if (klimit_causal) Keff = min(K, m0 + GBM);

    __shared__ float As[GBK][GBM + 4];
    __shared__ float Bs[GBK][GBN + 4];

    int tid = threadIdx.x;
    int lr = tid >> 1;
    int lk = (tid & 1) * 4;
    int lbk = tid >> 5;           // 0..7
    int lbn = (tid & 31) * 4;     // 0..124

    const float* Aptr = Ab + (long)(m0 + lr) * K + lk;
    const float* Bptr = Bb + (long)lbk * N + n0 + lbn;

    int ty = tid >> 4, tx = tid & 15;
    float acc[8][8];
    #pragma unroll
    for (int i = 0; i < 8; i++)
        #pragma unroll
        for (int j = 0; j < 8; j++) acc[i][j] = 0.f;

    float4 ar = *(const float4*)Aptr;
    float4 br = *(const float4*)Bptr;

    int ntiles = Keff / GBK;
    for (int t = 0; t < ntiles; ++t) {
        As[lk + 0][lr] = ar.x; As[lk + 1][lr] = ar.y; As[lk + 2][lr] = ar.z; As[lk + 3][lr] = ar.w;
        *(float4*)&Bs[lbk][lbn] = br;
        __syncthreads();
        if (t + 1 < ntiles) {
            ar = *(const float4*)(Aptr + (long)(t + 1) * GBK);
            br = *(const float4*)(Bptr + (long)(t + 1) * GBK * N);
        }
        #pragma unroll
        for (int kk = 0; kk < GBK; ++kk) {
            float a[8], b[8];
            #pragma unroll
            for (int i = 0; i < 8; i++) a[i] = As[kk][ty * 8 + i];
            #pragma unroll
            for (int j = 0; j < 8; j++) b[j] = Bs[kk][tx * 8 + j];
            #pragma unroll
            for (int i = 0; i < 8; i++)
                #pragma unroll
                for (int j = 0; j < 8; j++)
                    acc[i][j] = fmaf(a[i], b[j], acc[i][j]);
        }
        __syncthreads();
    }

    #pragma unroll
    for (int i = 0; i < 8; i++) {
        long rowoff = (long)(m0 + ty * 8 + i) * N + n0 + tx * 8;
        #pragma unroll
        for (int j = 0; j < 8; j++) Cb[rowoff + j] = acc[i][j];
    }
}

// ---------------- Q head post-process: rmsnorm(D=256) + RoPE, scatter ----------------
__global__ void qpost_kernel(const float* __restrict__ qg, const float* __restrict__ qn_w,
                             float* __restrict__ qdst) {
    int t = blockIdx.x;               // token
    int h = blockIdx.y;               // q head
    int b = t / LL, l = t % LL;
    const float* src = qg + (long)t * 4096 + h * 512;
    int tid = threadIdx.x;            // 256 = D
    float v = src[tid];
    float tot = blk_sum(v * v);
    float rms = rsqrtf(tot / (float)DD + 1e-6f);
    __shared__ float sq[DD];
    sq[tid] = v * rms * qn_w[tid];
    __syncthreads();
    if (tid < 32) {
        double inv = exp(-((double)(2 * tid) / 64.0) * log(1.0e7));
        double fr = (double)l * inv;
        double c = cos(fr), s = sin(fr);
        float x0 = sq[2 * tid], x1 = sq[2 * tid + 1];
        sq[2 * tid]     = (float)((double)x0 * c - (double)x1 * s);
        sq[2 * tid + 1] = (float)((double)x0 * s + (double)x1 * c);
    }
    __syncthreads();
    qdst[(((long)(b * NQH + h)) * LL + l) * DD + tid] = sq[tid];
}

// ---------------- K head post-process: rmsnorm + RoPE + GQA-replicate x4 ----------------
__global__ void kpost_kernel(const float* __restrict__ kbuf, const float* __restrict__ kn_w,
                             float* __restrict__ kdst) {
    int t = blockIdx.x;
    int h = blockIdx.y;               // kv head (0..1)
    int b = t / LL, l = t % LL;
    const float* src = kbuf + (long)t * 512 + h * 256;
    int tid = threadIdx.x;
    float v = src[tid];
    float tot = blk_sum(v * v);
    float rms = rsqrtf(tot / (float)DD + 1e-6f);
    __shared__ float sq[DD];
    sq[tid] = v * rms * kn_w[tid];
    __syncthreads();
    if (tid < 32) {
        double inv = exp(-((double)(2 * tid) / 64.0) * log(1.0e7));
        double fr = (double)l * inv;
        double c = cos(fr), s = sin(fr);
        float x0 = sq[2 * tid], x1 = sq[2 * tid + 1];
        sq[2 * tid]     = (float)((double)x0 * c - (double)x1 * s);
        sq[2 * tid + 1] = (float)((double)x0 * s + (double)x1 * c);
    }
    __syncthreads();
    float val = sq[tid];
    #pragma unroll
    for (int r = 0; r < 4; ++r)
        kdst[(((long)(b * NQH + h * 4 + r)) * LL + l) * DD + tid] = val;
}

// ---------------- V GQA replicate ----------------
__global__ void vrep_kernel(const float* __restrict__ vbuf, float* __restrict__ vdst) {
    int t = blockIdx.x;
    int h = blockIdx.y;
    int b = t / LL, l = t % LL;
    int tid = threadIdx.x;
    float v = vbuf[(long)t * 512 + h * 256 + tid];
    #pragma unroll
    for (int r = 0; r < 4; ++r)
        vdst[(((long)(b * NQH + h * 4 + r)) * LL + l) * DD + tid] = v;
}

// ---------------- row softmax over L=2048 ----------------
__global__ void softmax_kernel(float* __restrict__ scores) {
    int q = blockIdx.x;
    int z = blockIdx.y;
    float* row = scores + ((long)z * LL + q) * LL;
    float vals[8];
    float mx = -INFINITY;
    #pragma unroll
    for (int i = 0; i < 8; i++) {
        vals[i] = row[threadIdx.x + i * 256];
        mx = fmaxf(mx, vals[i]);
    }
    mx = blk_max(mx);
    float sum = 0.f;
    #pragma unroll
    for (int i = 0; i < 8; i++) { vals[i] = __expf(vals[i] - mx); sum += vals[i]; }
    sum = blk_sum(sum);
    float invs = 1.f / sum;
    #pragma unroll
    for (int i = 0; i < 8; i++) row[threadIdx.x + i * 256] = vals[i] * invs;
}

// ---------------- gather attn out + sigmoid gate ----------------
__global__ void gather_gate_kernel(const float* __restrict__ attno,
                                   const float* __restrict__ qg,
                                   float* __restrict__ ao) {
    long i = (long)blockIdx.x * 256 + threadIdx.x;   // over NTOK*2048
    int t = (int)(i >> 11);
    int c = (int)(i & 2047);
    int h = c >> 8, d = c & 255;
    int b = t / LL, l = t % LL;
    float o = attno[(((long)(b * NQH + h)) * LL + l) * DD + d];
    float gate = qg[(long)t * 4096 + h * 512 + 256 + d];
    ao[i] = o * (1.f / (1.f + expf(-gate)));
}

// ---------------- silu(g) * u (in place into g) ----------------
__global__ void silu_mul_kernel(float* __restrict__ g, const float* __restrict__ u, long n) {
    long i = (long)blockIdx.x * 256 + threadIdx.x;
    if (i < n) {
        float x = g[i];
        g[i] = x * (1.f / (1.f + expf(-x))) * u[i];
    }
}

// ---------------- launch ----------------
extern "C" void kernel_launch(void* const* d_in, const int* in_sizes, int n_in,
                              void* d_out, int out_size) {
    (void)in_sizes; (void)n_in; (void)out_size;
    const float* embeddings = (const float*)d_in[0];
    const float* hidden     = (const float*)d_in[1];
    const float* pre_emb_w  = (const float*)d_in[2];
    const float* pre_hid_w  = (const float*)d_in[3];
    const float* fc_w       = (const float*)d_in[4];
    const float* in_ln_w    = (const float*)d_in[5];
    const float* q_w        = (const float*)d_in[6];
    const float* k_w        = (const float*)d_in[7];
    const float* v_w        = (const float*)d_in[8];
    const float* o_w        = (const float*)d_in[9];
    const float* qn_w       = (const float*)d_in[10];
    const float* kn_w       = (const float*)d_in[11];
    const float* post_ln_w  = (const float*)d_in[12];
    const float* gate_w     = (const float*)d_in[13];
    const float* up_w       = (const float*)d_in[14];
    const float* down_w     = (const float*)d_in[15];
    const float* norm_w     = (const float*)d_in[16];
    const float* lm_w       = (const float*)d_in[17];
    float* out = (float*)d_out;

    static float *p_xcat = nullptr, *p_x0, *p_xn, *p_qg, *p_kbuf, *p_vbuf,
                 *p_q, *p_krep, *p_vrep, *p_scores, *p_attno, *p_ao,
                 *p_x1, *p_xn2, *p_gbuf, *p_ubuf, *p_x2, *p_xn3;
    if (!p_xcat) {
        cudaGetSymbolAddress((void**)&p_xcat,  g_xcat);
        cudaGetSymbolAddress((void**)&p_x0,    g_x0);
        cudaGetSymbolAddress((void**)&p_xn,    g_xn);
        cudaGetSymbolAddress((void**)&p_qg,    g_qg);
        cudaGetSymbolAddress((void**)&p_kbuf,  g_kbuf);
        cudaGetSymbolAddress((void**)&p_vbuf,  g_vbuf);
        cudaGetSymbolAddress((void**)&p_q,     g_q);
        cudaGetSymbolAddress((void**)&p_krep,  g_krep);
        cudaGetSymbolAddress((void**)&p_vrep,  g_vrep);
        cudaGetSymbolAddress((void**)&p_scores,g_scores);
        cudaGetSymbolAddress((void**)&p_attno, g_attno);
        cudaGetSymbolAddress((void**)&p_ao,    g_ao);
        cudaGetSymbolAddress((void**)&p_x1,    g_x1);
        cudaGetSymbolAddress((void**)&p_xn2,   g_xn2);
        cudaGetSymbolAddress((void**)&p_gbuf,  g_gbuf);
        cudaGetSymbolAddress((void**)&p_ubuf,  g_ubuf);
        cudaGetSymbolAddress((void**)&p_x2,    g_x2);
        cudaGetSymbolAddress((void**)&p_xn3,   g_xn3);
    }

    // 1. pre-norms + concat -> xcat [NTOK, 2048]
    rmsnorm_kernel<<<NTOK, 256>>>(embeddings, pre_emb_w, p_xcat,        HH, 2 * HH);
    rmsnorm_kernel<<<NTOK, 256>>>(hidden,     pre_hid_w, p_xcat + HH,   HH, 2 * HH);

    // 2. fc: x0 = xcat @ fc_w^T   [NTOK,1024]
    gemm_nt_kernel<<<dim3(HH / GBN, NTOK / GBM, 1), 256>>>(
        p_xcat, fc_w, p_x0, nullptr, NTOK, HH, 2 * HH, 0, 0, 0, 0, 1.f);

    // 3. in_ln
    rmsnorm_kernel<<<NTOK, 256>>>(p_x0, in_ln_w, p_xn, HH, HH);

    // 4. q/k/v projections
    gemm_nt_kernel<<<dim3(4096 / GBN, NTOK / GBM, 1), 256>>>(
        p_xn, q_w, p_qg, nullptr, NTOK, 4096, HH, 0, 0, 0, 0, 1.f);
    gemm_nt_kernel<<<dim3(512 / GBN, NTOK / GBM, 1), 256>>>(
        p_xn, k_w, p_kbuf, nullptr, NTOK, 512, HH, 0, 0, 0, 0, 1.f);
    gemm_nt_kernel<<<dim3(512 / GBN, NTOK / GBM, 1), 256>>>(
        p_xn, v_w, p_vbuf, nullptr, NTOK, 512, HH, 0, 0, 0, 0, 1.f);

    // 5. head-norm + rope + layout
    qpost_kernel<<<dim3(NTOK, NQH), 256>>>(p_qg, qn_w, p_q);
    kpost_kernel<<<dim3(NTOK, NKVH), 256>>>(p_kbuf, kn_w, p_krep);
    vrep_kernel <<<dim3(NTOK, NKVH), 256>>>(p_vbuf, p_vrep);

    // 6. scores = Q @ K^T * 1/16 with causal mask   batched (32)
    gemm_nt_kernel<<<dim3(LL / GBN, LL / GBM, BB * NQH), 256>>>(
        p_q, p_krep, p_scores, nullptr, LL, LL, DD,
        (long)LL * DD, (long)LL * DD, (long)LL * LL, 2, 0.0625f);

    // 7. softmax
    softmax_kernel<<<dim3(LL, BB * NQH), 256>>>(p_scores);

    // 8. attno = P @ V   batched, causal K-limit
    gemm_nn_kernel<<<dim3(DD / GBN, LL / GBM, BB * NQH), 256>>>(
        p_scores, p_vrep, p_attno, LL, DD, LL,
        (long)LL * LL, (long)LL * DD, (long)LL * DD, 1);

    // 9. gather + gate
    gather_gate_kernel<<<(NTOK * 2048) / 256, 256>>>(p_attno, p_qg, p_ao);

    // 10. o proj + residual -> x1
    gemm_nt_kernel<<<dim3(HH / GBN, NTOK / GBM, 1), 256>>>(
        p_ao, o_w, p_x1, p_x0, NTOK, HH, 2048, 0, 0, 0, 1, 1.f);

    // 11. post_ln
    rmsnorm_kernel<<<NTOK, 256>>>(p_x1, post_ln_w, p_xn2, HH, HH);

    // 12. MLP gate / up
    gemm_nt_kernel<<<dim3(II / GBN, NTOK / GBM, 1), 256>>>(
        p_xn2, gate_w, p_gbuf, nullptr, NTOK, II, HH, 0, 0, 0, 0, 1.f);
    gemm_nt_kernel<<<dim3(II / GBN, NTOK / GBM, 1), 256>>>(
        p_xn2, up_w, p_ubuf, nullptr, NTOK, II, HH, 0, 0, 0, 0, 1.f);

    // 13. silu * up
    silu_mul_kernel<<<((long)NTOK * II) / 256, 256>>>(p_gbuf, p_ubuf, (long)NTOK * II);

    // 14. down + residual -> x2
    gemm_nt_kernel<<<dim3(HH / GBN, NTOK / GBM, 1), 256>>>(
        p_gbuf, down_w, p_x2, p_x1, NTOK, HH, II, 0, 0, 0, 1, 1.f);

    // 15. final norm
    rmsnorm_kernel<<<NTOK, 256>>>(p_x2, norm_w, p_xn3, HH, HH);

    // 16. lm head -> d_out [NTOK, 16384]
    gemm_nt_kernel<<<dim3(VV / GBN, NTOK / GBM, 1), 256>>>(
        p_xn3, lm_w, out, nullptr, NTOK, VV, HH, 0, 0, 0, 0, 1.f);
}

// round 5
// speedup vs baseline: 2.4449x; 2.4449x over previous
#include <cuda_runtime.h>
#include <cuda_bf16.h>
#include <math.h>
#include <stdint.h>

#define BBATCH 4
#define LL    2048
#define HH    1024
#define NQH   8
#define NKVH  2
#define DD    256
#define II    3584
#define VV    16384
#define NTOK  (BBATCH*LL)
#define FMIN  (-3.402823466e38f)

// fp32 scratch
__device__ __align__(256) float g_x0    [(size_t)NTOK * HH];
__device__ __align__(256) float g_qg    [(size_t)NTOK * 4096];
__device__ __align__(256) float g_kbuf  [(size_t)NTOK * 512];
__device__ __align__(256) float g_vbuf  [(size_t)NTOK * 512];
__device__ __align__(256) float g_scores[(size_t)BBATCH * NQH * LL * LL];
__device__ __align__(256) float g_attno [(size_t)BBATCH * NQH * LL * DD];
__device__ __align__(256) float g_gbuf  [(size_t)NTOK * II];
__device__ __align__(256) float g_ubuf  [(size_t)NTOK * II];
__device__ __align__(256) float g_x1    [(size_t)NTOK * HH];
__device__ __align__(256) float g_x2    [(size_t)NTOK * HH];
// triple-split bf16 buffers: per 32 fp32 elems -> 96 bf16.
// A-format: [hi | hi | lo]   B-format: [hi | lo | hi]
__device__ __align__(256) __nv_bfloat16 h_xcat [(size_t)NTOK * 2048 * 3];
__device__ __align__(256) __nv_bfloat16 h_xn   [(size_t)NTOK * HH * 3];
__device__ __align__(256) __nv_bfloat16 h_q    [(size_t)BBATCH * NQH * LL * DD * 3];
__device__ __align__(256) __nv_bfloat16 h_k    [(size_t)BBATCH * NKVH * LL * DD * 3];
__device__ __align__(256) __nv_bfloat16 h_vt   [(size_t)BBATCH * NKVH * DD * LL * 3];
__device__ __align__(256) __nv_bfloat16 h_p    [(size_t)BBATCH * NQH * LL * LL * 3];
__device__ __align__(256) __nv_bfloat16 h_ao   [(size_t)NTOK * 2048 * 3];
__device__ __align__(256) __nv_bfloat16 h_xn2  [(size_t)NTOK * HH * 3];
__device__ __align__(256) __nv_bfloat16 h_xn3  [(size_t)NTOK * HH * 3];
__device__ __align__(256) __nv_bfloat16 h_gml  [(size_t)NTOK * II * 3];
__device__ __align__(256) __nv_bfloat16 w_fc   [(size_t)HH * 2048 * 3];
__device__ __align__(256) __nv_bfloat16 w_q    [(size_t)4096 * HH * 3];
__device__ __align__(256) __nv_bfloat16 w_k    [(size_t)512 * HH * 3];
__device__ __align__(256) __nv_bfloat16 w_v    [(size_t)512 * HH * 3];
__device__ __align__(256) __nv_bfloat16 w_o    [(size_t)HH * 2048 * 3];
__device__ __align__(256) __nv_bfloat16 w_gate [(size_t)II * HH * 3];
__device__ __align__(256) __nv_bfloat16 w_up   [(size_t)II * HH * 3];
__device__ __align__(256) __nv_bfloat16 w_down [(size_t)HH * II * 3];
__device__ __align__(256) __nv_bfloat16 w_lm   [(size_t)VV * HH * 3];

// ---------------- helpers ----------------
__device__ __forceinline__ uint32_t smem_u32(const void* p) {
    uint32_t a;
    asm("{ .reg .u64 t; cvta.to.shared.u64 t, %1; cvt.u32.u64 %0, t; }" : "=r"(a) : "l"(p));
    return a;
}
#define SWZ(o) ((o) ^ (((o) >> 3) & 0x70))

__device__ __forceinline__ void cp16(uint32_t dst, const void* src) {
    asm volatile("cp.async.cg.shared.global [%0], [%1], 16;" :: "r"(dst), "l"(src));
}
__device__ __forceinline__ void cp_commit() { asm volatile("cp.async.commit_group;"); }
template<int N> __device__ __forceinline__ void cp_wait() {
    asm volatile("cp.async.wait_group %0;" :: "n"(N));
}
__device__ __forceinline__ void ldm_x4(uint32_t* r, uint32_t addr) {
    asm volatile("ldmatrix.sync.aligned.m8n8.x4.shared.b16 {%0,%1,%2,%3}, [%4];"
                 : "=r"(r[0]), "=r"(r[1]), "=r"(r[2]), "=r"(r[3]) : "r"(addr));
}
__device__ __forceinline__ void mma16816(float* c, const uint32_t* a, const uint32_t* b) {
    asm volatile(
        "mma.sync.aligned.m16n8k16.row.col.f32.bf16.bf16.f32 "
        "{%0,%1,%2,%3},{%4,%5,%6,%7},{%8,%9},{%0,%1,%2,%3};"
        : "+f"(c[0]), "+f"(c[1]), "+f"(c[2]), "+f"(c[3])
        : "r"(a[0]), "r"(a[1]), "r"(a[2]), "r"(a[3]), "r"(b[0]), "r"(b[1]));
}

// block reduce (256 thr)
__device__ __forceinline__ float blk_sum(float v) {
    __shared__ float sh[8]; __shared__ float res;
    #pragma unroll
    for (int o = 16; o; o >>= 1) v += __shfl_xor_sync(0xffffffffu, v, o);
    if ((threadIdx.x & 31) == 0) sh[threadIdx.x >> 5] = v;
    __syncthreads();
    if (threadIdx.x < 32) {
        float x = (threadIdx.x < 8) ? sh[threadIdx.x] : 0.f;
        #pragma unroll
        for (int o = 4; o; o >>= 1) x += __shfl_xor_sync(0xffffffffu, x, o);
        if (threadIdx.x == 0) res = x;
    }
    __syncthreads();
    return res;
}
__device__ __forceinline__ float blk_max(float v) {
    __shared__ float sh[8]; __shared__ float res;
    #pragma unroll
    for (int o = 16; o; o >>= 1) v = fmaxf(v, __shfl_xor_sync(0xffffffffu, v, o));
    if ((threadIdx.x & 31) == 0) sh[threadIdx.x >> 5] = v;
    __syncthreads();
    if (threadIdx.x < 32) {
        float x = (threadIdx.x < 8) ? sh[threadIdx.x] : -INFINITY;
        #pragma unroll
        for (int o = 4; o; o >>= 1) x = fmaxf(x, __shfl_xor_sync(0xffffffffu, x, o));
        if (threadIdx.x == 0) res = x;
    }
    __syncthreads();
    return res;
}

// triple-split writers: base index for logical elem k = (k>>5)*96 + (k&31)
__device__ __forceinline__ void split3a(__nv_bfloat16* out, long idx, float x) {
    __nv_bfloat16 hi = __float2bfloat16(x);
    __nv_bfloat16 lo = __float2bfloat16(x - __bfloat162float(hi));
    out[idx] = hi; out[idx + 32] = hi; out[idx + 64] = lo;
}
__device__ __forceinline__ void split3b(__nv_bfloat16* out, long idx, float x) {
    __nv_bfloat16 hi = __float2bfloat16(x);
    __nv_bfloat16 lo = __float2bfloat16(x - __bfloat162float(hi));
    out[idx] = hi; out[idx + 32] = lo; out[idx + 64] = hi;
}

// ---------------- bf16 mma.sync GEMM: C[M,N] f32 = A[M,3K]*B[N,3K]^T ----------------
// epi 0: plain  1: +R  2: scores(scale+causal)   bmode: GQA z->kv map   klimit: causal K cut
#define STAGES 3
#define GEMM_SMEM (STAGES * 32768)

__global__ __launch_bounds__(256)
void gemm_mma_kernel(const uint8_t* __restrict__ A, const uint8_t* __restrict__ B,
                     float* __restrict__ C, const float* __restrict__ R,
                     int M, int N, int K,
                     long long bAby, long long bBby, long long bCel,
                     int bmode, int epi, float scale, int klimit)
{
    extern __shared__ char smch[];
    int tid = threadIdx.x;
    int z = blockIdx.z;
    int m0 = blockIdx.y * 128;
    int n0 = blockIdx.x * 128;
    const uint8_t* Ab = A + (long long)z * bAby;
    long long zb = bmode ? ((long long)(z >> 3) * 2 + ((z & 7) >> 2)) : (long long)z;
    const uint8_t* Bb = B + zb * bBby;
    float* Cb = C + (long long)z * bCel;

    if (epi == 2 && n0 > m0 + 127) {
        float4 f = make_float4(FMIN, FMIN, FMIN, FMIN);
        for (int i = tid; i < 128 * 32; i += 256) {
            int mm = i >> 5, nn = (i & 31) << 2;
            *(float4*)&Cb[(long long)(m0 + mm) * N + n0 + nn] = f;
        }
        return;
    }

    uint32_t smu = smem_u32(smch);
    long long pitch = (long long)K * 6;          // bytes per row (3K bf16)
    int Keff = klimit ? min(K, m0 + 128) : K;
    int ntiles = (Keff * 3) / 64;                // 64 bf16 per k-tile (128B)

    int lr = tid >> 3;              // 0..31
    int lc = (tid & 7) * 16;        // 0..112

    auto issue = [&](int t, int slot) {
        uint32_t bA = smu + slot * 32768;
        uint32_t bB = bA + 16384;
        long long kofs = (long long)t * 128;
        #pragma unroll
        for (int j = 0; j < 4; ++j) {
            int r = lr + j * 32;
            cp16(bA + SWZ(r * 128 + lc), Ab + (long long)(m0 + r) * pitch + kofs + lc);
        }
        #pragma unroll
        for (int j = 0; j < 4; ++j) {
            int r = lr + j * 32;
            cp16(bB + SWZ(r * 128 + lc), Bb + (long long)(n0 + r) * pitch + kofs + lc);
        }
        cp_commit();
    };

    int wid = tid >> 5, lane = tid & 31;
    int warp_m = (wid & 1) * 64;
    int warp_n = (wid >> 1) * 32;
    int blk = lane >> 3;
    int arow = (blk & 1) * 8 + (lane & 7);
    int achk = (blk >> 1) * 16;
    int brow = (blk >> 1) * 8 + (lane & 7);
    int bchk = (blk & 1) * 16;

    float acc[4][4][4];
    #pragma unroll
    for (int i = 0; i < 4; i++)
        #pragma unroll
        for (int j = 0; j < 4; j++)
            #pragma unroll
            for (int q = 0; q < 4; q++) acc[i][j][q] = 0.f;

    int pre = ntiles < (STAGES - 1) ? ntiles : (STAGES - 1);
    for (int s = 0; s < pre; ++s) issue(s, s);

    for (int t = 0; t < ntiles; ++t) {
        cp_wait<STAGES - 2>();
        __syncthreads();
        if (t + STAGES - 1 < ntiles) issue(t + STAGES - 1, (t + STAGES - 1) % STAGES);
        uint32_t bA = smu + (t % STAGES) * 32768;
        uint32_t bB = bA + 16384;
        #pragma unroll
        for (int kk = 0; kk < 4; ++kk) {
            uint32_t af[4][4], bf[4][2];
            #pragma unroll
            for (int mi = 0; mi < 4; ++mi) {
                int row = warp_m + mi * 16 + arow;
                ldm_x4(af[mi], bA + SWZ(row * 128 + kk * 32 + achk));
            }
            #pragma unroll
            for (int nh = 0; nh < 2; ++nh) {
                uint32_t q[4];
                int n = warp_n + nh * 16 + brow;
                ldm_x4(q, bB + SWZ(n * 128 + kk * 32 + bchk));
                bf[nh * 2 + 0][0] = q[0]; bf[nh * 2 + 0][1] = q[1];
                bf[nh * 2 + 1][0] = q[2]; bf[nh * 2 + 1][1] = q[3];
            }
            #pragma unroll
            for (int mi = 0; mi < 4; ++mi)
                #pragma unroll
                for (int ni = 0; ni < 4; ++ni)
                    mma16816(acc[mi][ni], af[mi], bf[ni]);
        }
        __syncthreads();
    }

    // epilogue: direct fragment stores
    int g = lane >> 2, t4 = lane & 3;
    #pragma unroll
    for (int mi = 0; mi < 4; ++mi) {
        int r0 = m0 + warp_m + mi * 16 + g;
        int r1 = r0 + 8;
        #pragma unroll
        for (int ni = 0; ni < 4; ++ni) {
            int col = n0 + warp_n + ni * 8 + t4 * 2;
            float v0 = acc[mi][ni][0], v1 = acc[mi][ni][1];
            float v2 = acc[mi][ni][2], v3 = acc[mi][ni][3];
            if (epi == 2) {
                v0 *= scale; v1 *= scale; v2 *= scale; v3 *= scale;
                if (col     > r0) v0 = FMIN;
                if (col + 1 > r0) v1 = FMIN;
                if (col     > r1) v2 = FMIN;
                if (col + 1 > r1) v3 = FMIN;
            } else if (epi == 1) {
                long long o0 = (long long)r0 * N + col;
                long long o1 = (long long)r1 * N + col;
                v0 += R[o0]; v1 += R[o0 + 1]; v2 += R[o1]; v3 += R[o1 + 1];
            }
            *(float2*)&Cb[(long long)r0 * N + col] = make_float2(v0, v1);
            *(float2*)&Cb[(long long)r1 * N + col] = make_float2(v2, v3);
        }
    }
}

// ---------------- elementwise kernels ----------------
__global__ void rmsnorm_hilo_kernel(const float* __restrict__ in, const float* __restrict__ w,
                                    __nv_bfloat16* __restrict__ out, int width,
                                    long row_stride, long col_off) {
    long t = blockIdx.x;
    const float* x = in + t * width;
    float ss = 0.f;
    for (int i = threadIdx.x; i < width; i += 256) { float v = x[i]; ss = fmaf(v, v, ss); }
    float rms = rsqrtf(blk_sum(ss) / (float)width + 1e-6f);
    long rb = t * row_stride + col_off;
    for (int i = threadIdx.x; i < width; i += 256)
        split3a(out, rb + (long)(i >> 5) * 96 + (i & 31), x[i] * rms * w[i]);
}
__global__ void convert_b_kernel(const float* __restrict__ in, __nv_bfloat16* __restrict__ out, long n) {
    long i = (long)blockIdx.x * 256 + threadIdx.x;
    if (i < n) split3b(out, (i >> 5) * 96 + (i & 31), in[i]);
}
__global__ void qpost_kernel(const float* __restrict__ qg, const float* __restrict__ qn_w,
                             __nv_bfloat16* __restrict__ qdst) {
    int t = blockIdx.x, h = blockIdx.y;
    int b = t / LL, l = t % LL;
    const float* src = qg + (long)t * 4096 + h * 512;
    int tid = threadIdx.x;
    float v = src[tid];
    float rms = rsqrtf(blk_sum(v * v) / (float)DD + 1e-6f);
    __shared__ float sq[DD];
    sq[tid] = v * rms * qn_w[tid];
    __syncthreads();
    if (tid < 32) {
        double inv = exp(-((double)(2 * tid) / 64.0) * log(1.0e7));
        double fr = (double)l * inv, c = cos(fr), s = sin(fr);
        float x0 = sq[2 * tid], x1 = sq[2 * tid + 1];
        sq[2 * tid]     = (float)((double)x0 * c - (double)x1 * s);
        sq[2 * tid + 1] = (float)((double)x0 * s + (double)x1 * c);
    }
    __syncthreads();
    long row = (long)(b * NQH + h) * LL + l;
    split3a(qdst, row * 768 + (long)(tid >> 5) * 96 + (tid & 31), sq[tid]);
}
__global__ void kpost_kernel(const float* __restrict__ kbuf, const float* __restrict__ kn_w,
                             __nv_bfloat16* __restrict__ kdst) {
    int t = blockIdx.x, h = blockIdx.y;
    int b = t / LL, l = t % LL;
    const float* src = kbuf + (long)t * 512 + h * 256;
    int tid = threadIdx.x;
    float v = src[tid];
    float rms = rsqrtf(blk_sum(v * v) / (float)DD + 1e-6f);
    __shared__ float sq[DD];
    sq[tid] = v * rms * kn_w[tid];
    __syncthreads();
    if (tid < 32) {
        double inv = exp(-((double)(2 * tid) / 64.0) * log(1.0e7));
        double fr = (double)l * inv, c = cos(fr), s = sin(fr);
        float x0 = sq[2 * tid], x1 = sq[2 * tid + 1];
        sq[2 * tid]     = (float)((double)x0 * c - (double)x1 * s);
        sq[2 * tid + 1] = (float)((double)x0 * s + (double)x1 * c);
    }
    __syncthreads();
    long row = (long)(b * NKVH + h) * LL + l;
    split3b(kdst, row * 768 + (long)(tid >> 5) * 96 + (tid & 31), sq[tid]);
}
__global__ void vpost_kernel(const float* __restrict__ vbuf, __nv_bfloat16* __restrict__ vt) {
    __shared__ float smv[32][33];
    int l0 = blockIdx.x * 32, d0 = blockIdx.y * 32, z = blockIdx.z;
    int b = z >> 1, h = z & 1;
    int tx = threadIdx.x & 31, ty = threadIdx.x >> 5;
    #pragma unroll
    for (int j = 0; j < 4; ++j) {
        int lloc = ty + j * 8;
        smv[lloc][tx] = vbuf[(long)(b * LL + l0 + lloc) * 512 + h * 256 + d0 + tx];
    }
    __syncthreads();
    #pragma unroll
    for (int j = 0; j < 4; ++j) {
        int dd = ty + j * 8;
        long rowb = (long)(z * DD + d0 + dd) * (3 * LL);
        int l = l0 + tx;
        split3b(vt, rowb + (long)(l >> 5) * 96 + (l & 31), smv[tx][dd]);
    }
}
__global__ void softmax_hilo_kernel(const float* __restrict__ scores, __nv_bfloat16* __restrict__ p) {
    int q = blockIdx.x, z = blockIdx.y;
    const float* row = scores + ((long)z * LL + q) * LL;
    float vals[8], mx = -INFINITY;
    #pragma unroll
    for (int i = 0; i < 8; i++) { vals[i] = row[threadIdx.x + i * 256]; mx = fmaxf(mx, vals[i]); }
    mx = blk_max(mx);
    float sum = 0.f;
    #pragma unroll
    for (int i = 0; i < 8; i++) { vals[i] = __expf(vals[i] - mx); sum += vals[i]; }
    sum = blk_sum(sum);
    float invs = 1.f / sum;
    long base = ((long)z * LL + q) * (3 * LL);
    #pragma unroll
    for (int i = 0; i < 8; i++) {
        int c = threadIdx.x + i * 256;
        split3a(p, base + (long)(c >> 5) * 96 + (c & 31), vals[i] * invs);
    }
}
__global__ void gather_gate_kernel(const float* __restrict__ attno, const float* __restrict__ qg,
                                   __nv_bfloat16* __restrict__ ao) {
    long i = (long)blockIdx.x * 256 + threadIdx.x;
    int t = (int)(i >> 11), c = (int)(i & 2047);
    int h = c >> 8, d = c & 255;
    int b = t / LL, l = t % LL;
    float o = attno[((long)(b * NQH + h) * LL + l) * DD + d];
    float gate = qg[(long)t * 4096 + h * 512 + 256 + d];
    split3a(ao, (i >> 5) * 96 + (i & 31), o * (1.f / (1.f + expf(-gate))));
}
__global__ void silu_mul_kernel(const float* __restrict__ g, const float* __restrict__ u,
                                __nv_bfloat16* __restrict__ out, long n) {
    long i = (long)blockIdx.x * 256 + threadIdx.x;
    if (i < n) {
        float x = g[i];
        split3a(out, (i >> 5) * 96 + (i & 31), x * (1.f / (1.f + expf(-x))) * u[i]);
    }
}

// ---------------- launch ----------------
static void launch_gemm(const void* A, const void* B, float* C, const float* R,
                        int M, int N, int K, long long bAby, long long bBby, long long bCel,
                        int nz, int bmode, int epi, float scale, int klimit) {
    dim3 grid(N / 128, M / 128, nz);
    gemm_mma_kernel<<<grid, 256, GEMM_SMEM>>>((const uint8_t*)A, (const uint8_t*)B, C, R,
                                              M, N, K, bAby, bBby, bCel, bmode, epi, scale, klimit);
}

extern "C" void kernel_launch(void* const* d_in, const int* in_sizes, int n_in,
                              void* d_out, int out_size) {
    (void)in_sizes; (void)n_in; (void)out_size;
    const float* embeddings = (const float*)d_in[0];
    const float* hidden     = (const float*)d_in[1];
    const float* pre_emb_w  = (const float*)d_in[2];
    const float* pre_hid_w  = (const float*)d_in[3];
    const float* fc_w       = (const float*)d_in[4];
    const float* in_ln_w    = (const float*)d_in[5];
    const float* q_w        = (const float*)d_in[6];
    const float* k_w        = (const float*)d_in[7];
    const float* v_w        = (const float*)d_in[8];
    const float* o_w        = (const float*)d_in[9];
    const float* qn_w       = (const float*)d_in[10];
    const float* kn_w       = (const float*)d_in[11];
    const float* post_ln_w  = (const float*)d_in[12];
    const float* gate_w     = (const float*)d_in[13];
    const float* up_w       = (const float*)d_in[14];
    const float* down_w     = (const float*)d_in[15];
    const float* norm_w     = (const float*)d_in[16];
    const float* lm_w       = (const float*)d_in[17];
    float* out = (float*)d_out;

    static bool inited = false;
    static float *p_x0, *p_qg, *p_kbuf, *p_vbuf, *p_scores, *p_attno, *p_gbuf, *p_ubuf, *p_x1, *p_x2;
    static __nv_bfloat16 *ph_xcat, *ph_xn, *ph_q, *ph_k, *ph_vt, *ph_p, *ph_ao, *ph_xn2, *ph_xn3, *ph_gml;
    static __nv_bfloat16 *pw_fc, *pw_q, *pw_k, *pw_v, *pw_o, *pw_gate, *pw_up, *pw_down, *pw_lm;
    if (!inited) {
        cudaGetSymbolAddress((void**)&p_x0, g_x0);      cudaGetSymbolAddress((void**)&p_qg, g_qg);
        cudaGetSymbolAddress((void**)&p_kbuf, g_kbuf);  cudaGetSymbolAddress((void**)&p_vbuf, g_vbuf);
        cudaGetSymbolAddress((void**)&p_scores, g_scores); cudaGetSymbolAddress((void**)&p_attno, g_attno);
        cudaGetSymbolAddress((void**)&p_gbuf, g_gbuf);  cudaGetSymbolAddress((void**)&p_ubuf, g_ubuf);
        cudaGetSymbolAddress((void**)&p_x1, g_x1);      cudaGetSymbolAddress((void**)&p_x2, g_x2);
        cudaGetSymbolAddress((void**)&ph_xcat, h_xcat); cudaGetSymbolAddress((void**)&ph_xn, h_xn);
        cudaGetSymbolAddress((void**)&ph_q, h_q);       cudaGetSymbolAddress((void**)&ph_k, h_k);
        cudaGetSymbolAddress((void**)&ph_vt, h_vt);     cudaGetSymbolAddress((void**)&ph_p, h_p);
        cudaGetSymbolAddress((void**)&ph_ao, h_ao);     cudaGetSymbolAddress((void**)&ph_xn2, h_xn2);
        cudaGetSymbolAddress((void**)&ph_xn3, h_xn3);   cudaGetSymbolAddress((void**)&ph_gml, h_gml);
        cudaGetSymbolAddress((void**)&pw_fc, w_fc);     cudaGetSymbolAddress((void**)&pw_q, w_q);
        cudaGetSymbolAddress((void**)&pw_k, w_k);       cudaGetSymbolAddress((void**)&pw_v, w_v);
        cudaGetSymbolAddress((void**)&pw_o, w_o);       cudaGetSymbolAddress((void**)&pw_gate, w_gate);
        cudaGetSymbolAddress((void**)&pw_up, w_up);     cudaGetSymbolAddress((void**)&pw_down, w_down);
        cudaGetSymbolAddress((void**)&pw_lm, w_lm);
        cudaFuncSetAttribute(gemm_mma_kernel, cudaFuncAttributeMaxDynamicSharedMemorySize, GEMM_SMEM);
        inited = true;
    }

    // weights -> triple-split (B-format)
    long n;
    n = (long)HH * 2048;  convert_b_kernel<<<(n + 255) / 256, 256>>>(fc_w,   pw_fc,   n);
    n = (long)4096 * HH;  convert_b_kernel<<<(n + 255) / 256, 256>>>(q_w,    pw_q,    n);
    n = (long)512 * HH;   convert_b_kernel<<<(n + 255) / 256, 256>>>(k_w,    pw_k,    n);
    n = (long)512 * HH;   convert_b_kernel<<<(n + 255) / 256, 256>>>(v_w,    pw_v,    n);
    n = (long)HH * 2048;  convert_b_kernel<<<(n + 255) / 256, 256>>>(o_w,    pw_o,    n);
    n = (long)II * HH;    convert_b_kernel<<<(n + 255) / 256, 256>>>(gate_w, pw_gate, n);
    n = (long)II * HH;    convert_b_kernel<<<(n + 255) / 256, 256>>>(up_w,   pw_up,   n);
    n = (long)HH * II;    convert_b_kernel<<<(n + 255) / 256, 256>>>(down_w, pw_down, n);
    n = (long)VV * HH;    convert_b_kernel<<<(n + 255) / 256, 256>>>(lm_w,   pw_lm,   n);

    // 1. pre-norms + concat (A-format, row = 2048 logical -> 6144 bf16)
    rmsnorm_hilo_kernel<<<NTOK, 256>>>(embeddings, pre_emb_w, ph_xcat, HH, 6144, 0);
    rmsnorm_hilo_kernel<<<NTOK, 256>>>(hidden,     pre_hid_w, ph_xcat, HH, 6144, 3072);
    // 2. fc
    launch_gemm(ph_xcat, pw_fc, p_x0, nullptr, NTOK, HH, 2048, 0, 0, 0, 1, 0, 0, 1.f, 0);
    // 3. in_ln
    rmsnorm_hilo_kernel<<<NTOK, 256>>>(p_x0, in_ln_w, ph_xn, HH, 3072, 0);
    // 4. qkv
    launch_gemm(ph_xn, pw_q, p_qg,   nullptr, NTOK, 4096, HH, 0, 0, 0, 1, 0, 0, 1.f, 0);
    launch_gemm(ph_xn, pw_k, p_kbuf, nullptr, NTOK, 512,  HH, 0, 0, 0, 1, 0, 0, 1.f, 0);
    launch_gemm(ph_xn, pw_v, p_vbuf, nullptr, NTOK, 512,  HH, 0, 0, 0, 1, 0, 0, 1.f, 0);
    // 5. head post
    qpost_kernel<<<dim3(NTOK, NQH), 256>>>(p_qg, qn_w, ph_q);
    kpost_kernel<<<dim3(NTOK, NKVH), 256>>>(p_kbuf, kn_w, ph_k);
    vpost_kernel<<<dim3(LL / 32, DD / 32, BBATCH * NKVH), 256>>>(p_vbuf, ph_vt);
    // 6. scores = QK^T/16 causal
    launch_gemm(ph_q, ph_k, p_scores, nullptr, LL, LL, DD,
                (long long)LL * 768 * 2, (long long)LL * 768 * 2, (long long)LL * LL,
                BBATCH * NQH, 1, 2, 0.0625f, 0);
    // 7. softmax
    softmax_hilo_kernel<<<dim3(LL, BBATCH * NQH), 256>>>(p_scores, ph_p);
    // 8. attno = P @ V^T (klimit causal)
    launch_gemm(ph_p, ph_vt, p_attno, nullptr, LL, DD, LL,
                (long long)LL * (3 * LL) * 2, (long long)DD * (3 * LL) * 2, (long long)LL * DD,
                BBATCH * NQH, 1, 0, 1.f, 1);
    // 9. gate
    gather_gate_kernel<<<(NTOK * 2048) / 256, 256>>>(p_attno, p_qg, ph_ao);
    // 10. o proj + residual
    launch_gemm(ph_ao, pw_o, p_x1, p_x0, NTOK, HH, 2048, 0, 0, 0, 1, 0, 1, 1.f, 0);
    // 11. post_ln
    rmsnorm_hilo_kernel<<<NTOK, 256>>>(p_x1, post_ln_w, ph_xn2, HH, 3072, 0);
    // 12. MLP
    launch_gemm(ph_xn2, pw_gate, p_gbuf, nullptr, NTOK, II, HH, 0, 0, 0, 1, 0, 0, 1.f, 0);
    launch_gemm(ph_xn2, pw_up,   p_ubuf, nullptr, NTOK, II, HH, 0, 0, 0, 1, 0, 0, 1.f, 0);
    silu_mul_kernel<<<((long)NTOK * II) / 256, 256>>>(p_gbuf, p_ubuf, ph_gml, (long)NTOK * II);
    launch_gemm(ph_gml, pw_down, p_x2, p_x1, NTOK, HH, II, 0, 0, 0, 1, 0, 1, 1.f, 0);
    // 15. final norm + lm head
    rmsnorm_hilo_kernel<<<NTOK, 256>>>(p_x2, norm_w, ph_xn3, HH, 3072, 0);
    launch_gemm(ph_xn3, pw_lm, out, nullptr, NTOK, VV, HH, 0, 0, 0, 1, 0, 0, 1.f, 0);
}

// round 7
// speedup vs baseline: 2.7950x; 1.1432x over previous
#include <cuda_runtime.h>
#include <math.h>
#include <stdint.h>

#define BBATCH 4
#define LL    2048
#define HH    1024
#define NQH   8
#define NKVH  2
#define DD    256
#define II    3584
#define VV    16384
#define NTOK  (BBATCH*LL)
#define FMIN  (-3.402823466e38f)

// fp32 GEMM-output scratch
__device__ __align__(256) float g_x0    [(size_t)NTOK * HH];
__device__ __align__(256) float g_qg    [(size_t)NTOK * 4096];
__device__ __align__(256) float g_kbuf  [(size_t)NTOK * 512];
__device__ __align__(256) float g_vbuf  [(size_t)NTOK * 512];
__device__ __align__(256) float g_scores[(size_t)BBATCH * NQH * LL * LL];
__device__ __align__(256) float g_attno [(size_t)BBATCH * NQH * LL * DD];
__device__ __align__(256) float g_gbuf  [(size_t)NTOK * II];
__device__ __align__(256) float g_ubuf  [(size_t)NTOK * II];
__device__ __align__(256) float g_x1    [(size_t)NTOK * HH];
__device__ __align__(256) float g_x2    [(size_t)NTOK * HH];
// tf32-rounded fp32 GEMM-input buffers
__device__ __align__(256) float t_xcat [(size_t)NTOK * 2048];
__device__ __align__(256) float t_xn   [(size_t)NTOK * HH];
__device__ __align__(256) float t_q    [(size_t)BBATCH * NQH * LL * DD];
__device__ __align__(256) float t_k    [(size_t)BBATCH * NKVH * LL * DD];
__device__ __align__(256) float t_vt   [(size_t)BBATCH * NKVH * DD * LL];
__device__ __align__(256) float t_p    [(size_t)BBATCH * NQH * LL * LL];
__device__ __align__(256) float t_ao   [(size_t)NTOK * 2048];
__device__ __align__(256) float t_xn2  [(size_t)NTOK * HH];
__device__ __align__(256) float t_xn3  [(size_t)NTOK * HH];
__device__ __align__(256) float t_gml  [(size_t)NTOK * II];
// tf32-rounded weights
__device__ __align__(256) float tw_fc   [(size_t)HH * 2048];
__device__ __align__(256) float tw_q    [(size_t)4096 * HH];
__device__ __align__(256) float tw_k    [(size_t)512 * HH];
__device__ __align__(256) float tw_v    [(size_t)512 * HH];
__device__ __align__(256) float tw_o    [(size_t)HH * 2048];
__device__ __align__(256) float tw_gate [(size_t)II * HH];
__device__ __align__(256) float tw_up   [(size_t)II * HH];
__device__ __align__(256) float tw_down [(size_t)HH * II];
__device__ __align__(256) float tw_lm   [(size_t)VV * HH];

// ---------------- helpers ----------------
__device__ __forceinline__ uint32_t smem_u32(const void* p) {
    uint32_t a;
    asm("{ .reg .u64 t; cvta.to.shared.u64 t, %1; cvt.u32.u64 %0, t; }" : "=r"(a) : "l"(p));
    return a;
}
#define SWZ(o) ((o) ^ (((o) >> 3) & 0x70))

__device__ __forceinline__ float tf32r(float x) {
    uint32_t r;
    asm("cvt.rna.tf32.f32 %0, %1;" : "=r"(r) : "f"(x));
    return __uint_as_float(r);
}
__device__ __forceinline__ void cp16(uint32_t dst, const void* src) {
    asm volatile("cp.async.cg.shared.global [%0], [%1], 16;" :: "r"(dst), "l"(src));
}
__device__ __forceinline__ void cp_commit() { asm volatile("cp.async.commit_group;"); }
template<int N> __device__ __forceinline__ void cp_wait() {
    asm volatile("cp.async.wait_group %0;" :: "n"(N));
}
__device__ __forceinline__ uint32_t lds_u(uint32_t a) {
    uint32_t v;
    asm volatile("ld.shared.b32 %0, [%1];" : "=r"(v) : "r"(a));
    return v;
}
__device__ __forceinline__ void mma_tf32(float* c, const uint32_t* a, const uint32_t* b) {
    asm volatile(
        "mma.sync.aligned.m16n8k8.row.col.f32.tf32.tf32.f32 "
        "{%0,%1,%2,%3},{%4,%5,%6,%7},{%8,%9},{%0,%1,%2,%3};"
        : "+f"(c[0]), "+f"(c[1]), "+f"(c[2]), "+f"(c[3])
        : "r"(a[0]), "r"(a[1]), "r"(a[2]), "r"(a[3]), "r"(b[0]), "r"(b[1]));
}

// block reduce (256 thr)
__device__ __forceinline__ float blk_sum(float v) {
    __shared__ float sh[8]; __shared__ float res;
    #pragma unroll
    for (int o = 16; o; o >>= 1) v += __shfl_xor_sync(0xffffffffu, v, o);
    if ((threadIdx.x & 31) == 0) sh[threadIdx.x >> 5] = v;
    __syncthreads();
    if (threadIdx.x < 32) {
        float x = (threadIdx.x < 8) ? sh[threadIdx.x] : 0.f;
        #pragma unroll
        for (int o = 4; o; o >>= 1) x += __shfl_xor_sync(0xffffffffu, x, o);
        if (threadIdx.x == 0) res = x;
    }
    __syncthreads();
    return res;
}
__device__ __forceinline__ float blk_max(float v) {
    __shared__ float sh[8]; __shared__ float res;
    #pragma unroll
    for (int o = 16; o; o >>= 1) v = fmaxf(v, __shfl_xor_sync(0xffffffffu, v, o));
    if ((threadIdx.x & 31) == 0) sh[threadIdx.x >> 5] = v;
    __syncthreads();
    if (threadIdx.x < 32) {
        float x = (threadIdx.x < 8) ? sh[threadIdx.x] : -INFINITY;
        #pragma unroll
        for (int o = 4; o; o >>= 1) x = fmaxf(x, __shfl_xor_sync(0xffffffffu, x, o));
        if (threadIdx.x == 0) res = x;
    }
    __syncthreads();
    return res;
}

// ---------------- tf32 mma GEMM: C[M,N] f32 = A[M,K]*B[N,K]^T ----------------
// epi 0: plain  1: +R  2: scores(scale+causal, skip masked blocks)
// bmode: GQA z->kv map for B.  klimit: causal K cut.
#define STAGES 3
#define GEMM_SMEM (STAGES * 32768)

__global__ __launch_bounds__(256)
void gemm_tf32_kernel(const float* __restrict__ A, const float* __restrict__ B,
                      float* __restrict__ C, const float* __restrict__ R,
                      int M, int N, int K,
                      long long bAel, long long bBel, long long bCel,
                      int bmode, int epi, float scale, int klimit)
{
    extern __shared__ char smch[];
    int tid = threadIdx.x;
    int z = blockIdx.z;
    int m0 = blockIdx.y * 128;
    int n0 = blockIdx.x * 128;
    if (epi == 2 && n0 > m0 + 127) return;    // fully masked: never read downstream

    const float* Ab = A + (long long)z * bAel;
    long long zb = bmode ? ((long long)(z >> 3) * 2 + ((z & 7) >> 2)) : (long long)z;
    const float* Bb = B + zb * bBel;
    float* Cb = C + (long long)z * bCel;

    uint32_t smu = smem_u32(smch);
    int Keff = klimit ? min(K, m0 + 128) : K;
    int ntiles = Keff / 32;                  // 32 fp32 per k-tile (128B rows)

    int lr = tid >> 3;              // 0..31
    int lc = (tid & 7) * 16;        // 0..112 bytes

    auto issue = [&](int t, int slot) {
        uint32_t bA = smu + slot * 32768;
        uint32_t bB = bA + 16384;
        long long kofs = (long long)t * 32;
        #pragma unroll
        for (int j = 0; j < 4; ++j) {
            int r = lr + j * 32;
            cp16(bA + SWZ(r * 128 + lc),
                 (const char*)(Ab + (long long)(m0 + r) * K + kofs) + lc);
        }
        #pragma unroll
        for (int j = 0; j < 4; ++j) {
            int r = lr + j * 32;
            cp16(bB + SWZ(r * 128 + lc),
                 (const char*)(Bb + (long long)(n0 + r) * K + kofs) + lc);
        }
        cp_commit();
    };

    int wid = tid >> 5, lane = tid & 31;
    int warp_m = (wid & 1) * 64;
    int warp_n = (wid >> 1) * 32;
    int rA = lane >> 2;      // 0..7
    int cA = lane & 3;       // 0..3

    float acc[4][4][4];
    #pragma unroll
    for (int i = 0; i < 4; i++)
        #pragma unroll
        for (int j = 0; j < 4; j++)
            #pragma unroll
            for (int q = 0; q < 4; q++) acc[i][j][q] = 0.f;

    int pre = ntiles < (STAGES - 1) ? ntiles : (STAGES - 1);
    for (int s = 0; s < pre; ++s) issue(s, s);

    for (int t = 0; t < ntiles; ++t) {
        cp_wait<STAGES - 2>();
        __syncthreads();
        if (t + STAGES - 1 < ntiles) issue(t + STAGES - 1, (t + STAGES - 1) % STAGES);
        uint32_t bA = smu + (t % STAGES) * 32768;
        uint32_t bB = bA + 16384;
        #pragma unroll
        for (int kk = 0; kk < 4; ++kk) {
            int c0 = kk * 8 + cA;
            uint32_t af[4][4], bf[4][2];
            #pragma unroll
            for (int mi = 0; mi < 4; ++mi) {
                int r = warp_m + mi * 16 + rA;
                // PTX m16n8k8.tf32 A order: a0=(g,k) a1=(g+8,k) a2=(g,k+4) a3=(g+8,k+4)
                af[mi][0] = lds_u(bA + SWZ(r * 128 + c0 * 4));
                af[mi][1] = lds_u(bA + SWZ((r + 8) * 128 + c0 * 4));
                af[mi][2] = lds_u(bA + SWZ(r * 128 + (c0 + 4) * 4));
                af[mi][3] = lds_u(bA + SWZ((r + 8) * 128 + (c0 + 4) * 4));
            }
            #pragma unroll
            for (int ni = 0; ni < 4; ++ni) {
                int nn = warp_n + ni * 8 + rA;
                bf[ni][0] = lds_u(bB + SWZ(nn * 128 + c0 * 4));
                bf[ni][1] = lds_u(bB + SWZ(nn * 128 + (c0 + 4) * 4));
            }
            #pragma unroll
            for (int mi = 0; mi < 4; ++mi)
                #pragma unroll
                for (int ni = 0; ni < 4; ++ni)
                    mma_tf32(acc[mi][ni], af[mi], bf[ni]);
        }
        __syncthreads();
    }

    // epilogue: direct fragment stores
    int g = lane >> 2, t4 = lane & 3;
    #pragma unroll
    for (int mi = 0; mi < 4; ++mi) {
        int r0 = m0 + warp_m + mi * 16 + g;
        int r1 = r0 + 8;
        #pragma unroll
        for (int ni = 0; ni < 4; ++ni) {
            int col = n0 + warp_n + ni * 8 + t4 * 2;
            float v0 = acc[mi][ni][0], v1 = acc[mi][ni][1];
            float v2 = acc[mi][ni][2], v3 = acc[mi][ni][3];
            if (epi == 2) {
                v0 *= scale; v1 *= scale; v2 *= scale; v3 *= scale;
                if (col     > r0) v0 = FMIN;
                if (col + 1 > r0) v1 = FMIN;
                if (col     > r1) v2 = FMIN;
                if (col + 1 > r1) v3 = FMIN;
            } else if (epi == 1) {
                long long o0 = (long long)r0 * N + col;
                long long o1 = (long long)r1 * N + col;
                v0 += R[o0]; v1 += R[o0 + 1]; v2 += R[o1]; v3 += R[o1 + 1];
            }
            *(float2*)&Cb[(long long)r0 * N + col] = make_float2(v0, v1);
            *(float2*)&Cb[(long long)r1 * N + col] = make_float2(v2, v3);
        }
    }
}

// ---------------- elementwise kernels (all GEMM inputs tf32-rounded) ----------------
__global__ void convert_tf32_kernel(const float* __restrict__ in, float* __restrict__ out, long n) {
    long i = (long)blockIdx.x * 256 + threadIdx.x;
    if (i < n) out[i] = tf32r(in[i]);
}
__global__ void rmsnorm_tf32_kernel(const float* __restrict__ in, const float* __restrict__ w,
                                    float* __restrict__ out, int width,
                                    long row_stride, long col_off) {
    long t = blockIdx.x;
    const float* x = in + t * width;
    float ss = 0.f;
    for (int i = threadIdx.x; i < width; i += 256) { float v = x[i]; ss = fmaf(v, v, ss); }
    float rms = rsqrtf(blk_sum(ss) / (float)width + 1e-6f);
    float* y = out + t * row_stride + col_off;
    for (int i = threadIdx.x; i < width; i += 256) y[i] = tf32r(x[i] * rms * w[i]);
}
__global__ void qpost_kernel(const float* __restrict__ qg, const float* __restrict__ qn_w,
                             float* __restrict__ qdst) {
    int t = blockIdx.x, h = blockIdx.y;
    int b = t / LL, l = t % LL;
    const float* src = qg + (long)t * 4096 + h * 512;
    int tid = threadIdx.x;
    float v = src[tid];
    float rms = rsqrtf(blk_sum(v * v) / (float)DD + 1e-6f);
    __shared__ float sq[DD];
    sq[tid] = v * rms * qn_w[tid];
    __syncthreads();
    if (tid < 32) {
        double inv = exp(-((double)(2 * tid) / 64.0) * log(1.0e7));
        double fr = (double)l * inv, c = cos(fr), s = sin(fr);
        float x0 = sq[2 * tid], x1 = sq[2 * tid + 1];
        sq[2 * tid]     = (float)((double)x0 * c - (double)x1 * s);
        sq[2 * tid + 1] = (float)((double)x0 * s + (double)x1 * c);
    }
    __syncthreads();
    long row = (long)(b * NQH + h) * LL + l;
    qdst[row * DD + tid] = tf32r(sq[tid]);
}
__global__ void kpost_kernel(const float* __restrict__ kbuf, const float* __restrict__ kn_w,
                             float* __restrict__ kdst) {
    int t = blockIdx.x, h = blockIdx.y;
    int b = t / LL, l = t % LL;
    const float* src = kbuf + (long)t * 512 + h * 256;
    int tid = threadIdx.x;
    float v = src[tid];
    float rms = rsqrtf(blk_sum(v * v) / (float)DD + 1e-6f);
    __shared__ float sq[DD];
    sq[tid] = v * rms * kn_w[tid];
    __syncthreads();
    if (tid < 32) {
        double inv = exp(-((double)(2 * tid) / 64.0) * log(1.0e7));
        double fr = (double)l * inv, c = cos(fr), s = sin(fr);
        float x0 = sq[2 * tid], x1 = sq[2 * tid + 1];
        sq[2 * tid]     = (float)((double)x0 * c - (double)x1 * s);
        sq[2 * tid + 1] = (float)((double)x0 * s + (double)x1 * c);
    }
    __syncthreads();
    long row = (long)(b * NKVH + h) * LL + l;
    kdst[row * DD + tid] = tf32r(sq[tid]);
}
__global__ void vpost_kernel(const float* __restrict__ vbuf, float* __restrict__ vt) {
    __shared__ float smv[32][33];
    int l0 = blockIdx.x * 32, d0 = blockIdx.y * 32, z = blockIdx.z;
    int b = z >> 1, h = z & 1;
    int tx = threadIdx.x & 31, ty = threadIdx.x >> 5;
    #pragma unroll
    for (int j = 0; j < 4; ++j) {
        int lloc = ty + j * 8;
        smv[lloc][tx] = vbuf[(long)(b * LL + l0 + lloc) * 512 + h * 256 + d0 + tx];
    }
    __syncthreads();
    #pragma unroll
    for (int j = 0; j < 4; ++j) {
        int dd = ty + j * 8;
        vt[(long)(z * DD + d0 + dd) * LL + l0 + tx] = tf32r(smv[tx][dd]);
    }
}
// causal-aware softmax: only the written 128-aligned prefix is touched
__global__ void softmax_tf32_kernel(const float* __restrict__ scores, float* __restrict__ p) {
    int q = blockIdx.x, z = blockIdx.y;
    const float* row = scores + ((long)z * LL + q) * LL;
    float* prow = p + ((long)z * LL + q) * LL;
    int nwrite = ((q >> 7) + 1) << 7;
    float vals[8], mx = -INFINITY;
    #pragma unroll
    for (int i = 0; i < 8; i++) {
        int col = threadIdx.x + i * 256;
        vals[i] = (col < nwrite) ? row[col] : -INFINITY;
        mx = fmaxf(mx, vals[i]);
    }
    mx = blk_max(mx);
    float sum = 0.f;
    #pragma unroll
    for (int i = 0; i < 8; i++) { vals[i] = __expf(vals[i] - mx); sum += vals[i]; }
    sum = blk_sum(sum);
    float invs = 1.f / sum;
    #pragma unroll
    for (int i = 0; i < 8; i++) {
        int col = threadIdx.x + i * 256;
        if (col < nwrite) prow[col] = tf32r(vals[i] * invs);
    }
}
__global__ void gather_gate_kernel(const float* __restrict__ attno, const float* __restrict__ qg,
                                   float* __restrict__ ao) {
    long i = (long)blockIdx.x * 256 + threadIdx.x;
    int t = (int)(i >> 11), c = (int)(i & 2047);
    int h = c >> 8, d = c & 255;
    int b = t / LL, l = t % LL;
    float o = attno[((long)(b * NQH + h) * LL + l) * DD + d];
    float gate = qg[(long)t * 4096 + h * 512 + 256 + d];
    ao[i] = tf32r(o * (1.f / (1.f + expf(-gate))));
}
__global__ void silu_mul_kernel(const float* __restrict__ g, const float* __restrict__ u,
                                float* __restrict__ out, long n) {
    long i = (long)blockIdx.x * 256 + threadIdx.x;
    if (i < n) {
        float x = g[i];
        out[i] = tf32r(x * (1.f / (1.f + expf(-x))) * u[i]);
    }
}

// ---------------- launch ----------------
static void launch_gemm(const float* A, const float* B, float* C, const float* R,
                        int M, int N, int K, long long bAel, long long bBel, long long bCel,
                        int nz, int bmode, int epi, float scale, int klimit) {
    dim3 grid(N / 128, M / 128, nz);
    gemm_tf32_kernel<<<grid, 256, GEMM_SMEM>>>(A, B, C, R, M, N, K,
                                               bAel, bBel, bCel, bmode, epi, scale, klimit);
}

extern "C" void kernel_launch(void* const* d_in, const int* in_sizes, int n_in,
                              void* d_out, int out_size) {
    (void)in_sizes; (void)n_in; (void)out_size;
    const float* embeddings = (const float*)d_in[0];
    const float* hidden     = (const float*)d_in[1];
    const float* pre_emb_w  = (const float*)d_in[2];
    const float* pre_hid_w  = (const float*)d_in[3];
    const float* fc_w       = (const float*)d_in[4];
    const float* in_ln_w    = (const float*)d_in[5];
    const float* q_w        = (const float*)d_in[6];
    const float* k_w        = (const float*)d_in[7];
    const float* v_w        = (const float*)d_in[8];
    const float* o_w        = (const float*)d_in[9];
    const float* qn_w       = (const float*)d_in[10];
    const float* kn_w       = (const float*)d_in[11];
    const float* post_ln_w  = (const float*)d_in[12];
    const float* gate_w     = (const float*)d_in[13];
    const float* up_w       = (const float*)d_in[14];
    const float* down_w     = (const float*)d_in[15];
    const float* norm_w     = (const float*)d_in[16];
    const float* lm_w       = (const float*)d_in[17];
    float* out = (float*)d_out;

    static bool inited = false;
    static float *p_x0, *p_qg, *p_kbuf, *p_vbuf, *p_scores, *p_attno, *p_gbuf, *p_ubuf, *p_x1, *p_x2;
    static float *pt_xcat, *pt_xn, *pt_q, *pt_k, *pt_vt, *pt_p, *pt_ao, *pt_xn2, *pt_xn3, *pt_gml;
    static float *ptw_fc, *ptw_q, *ptw_k, *ptw_v, *ptw_o, *ptw_gate, *ptw_up, *ptw_down, *ptw_lm;
    if (!inited) {
        cudaGetSymbolAddress((void**)&p_x0, g_x0);      cudaGetSymbolAddress((void**)&p_qg, g_qg);
        cudaGetSymbolAddress((void**)&p_kbuf, g_kbuf);  cudaGetSymbolAddress((void**)&p_vbuf, g_vbuf);
        cudaGetSymbolAddress((void**)&p_scores, g_scores); cudaGetSymbolAddress((void**)&p_attno, g_attno);
        cudaGetSymbolAddress((void**)&p_gbuf, g_gbuf);  cudaGetSymbolAddress((void**)&p_ubuf, g_ubuf);
        cudaGetSymbolAddress((void**)&p_x1, g_x1);      cudaGetSymbolAddress((void**)&p_x2, g_x2);
        cudaGetSymbolAddress((void**)&pt_xcat, t_xcat); cudaGetSymbolAddress((void**)&pt_xn, t_xn);
        cudaGetSymbolAddress((void**)&pt_q, t_q);       cudaGetSymbolAddress((void**)&pt_k, t_k);
        cudaGetSymbolAddress((void**)&pt_vt, t_vt);     cudaGetSymbolAddress((void**)&pt_p, t_p);
        cudaGetSymbolAddress((void**)&pt_ao, t_ao);     cudaGetSymbolAddress((void**)&pt_xn2, t_xn2);
        cudaGetSymbolAddress((void**)&pt_xn3, t_xn3);   cudaGetSymbolAddress((void**)&pt_gml, t_gml);
        cudaGetSymbolAddress((void**)&ptw_fc, tw_fc);   cudaGetSymbolAddress((void**)&ptw_q, tw_q);
        cudaGetSymbolAddress((void**)&ptw_k, tw_k);     cudaGetSymbolAddress((void**)&ptw_v, tw_v);
        cudaGetSymbolAddress((void**)&ptw_o, tw_o);     cudaGetSymbolAddress((void**)&ptw_gate, tw_gate);
        cudaGetSymbolAddress((void**)&ptw_up, tw_up);   cudaGetSymbolAddress((void**)&ptw_down, tw_down);
        cudaGetSymbolAddress((void**)&ptw_lm, tw_lm);
        cudaFuncSetAttribute(gemm_tf32_kernel, cudaFuncAttributeMaxDynamicSharedMemorySize, GEMM_SMEM);
        inited = true;
    }

    // weights -> tf32-rounded fp32
    long n;
    n = (long)HH * 2048;  convert_tf32_kernel<<<(n + 255) / 256, 256>>>(fc_w,   ptw_fc,   n);
    n = (long)4096 * HH;  convert_tf32_kernel<<<(n + 255) / 256, 256>>>(q_w,    ptw_q,    n);
    n = (long)512 * HH;   convert_tf32_kernel<<<(n + 255) / 256, 256>>>(k_w,    ptw_k,    n);
    n = (long)512 * HH;   convert_tf32_kernel<<<(n + 255) / 256, 256>>>(v_w,    ptw_v,    n);
    n = (long)HH * 2048;  convert_tf32_kernel<<<(n + 255) / 256, 256>>>(o_w,    ptw_o,    n);
    n = (long)II * HH;    convert_tf32_kernel<<<(n + 255) / 256, 256>>>(gate_w, ptw_gate, n);
    n = (long)II * HH;    convert_tf32_kernel<<<(n + 255) / 256, 256>>>(up_w,   ptw_up,   n);
    n = (long)HH * II;    convert_tf32_kernel<<<(n + 255) / 256, 256>>>(down_w, ptw_down, n);
    n = (long)VV * HH;    convert_tf32_kernel<<<(n + 255) / 256, 256>>>(lm_w,   ptw_lm,   n);

    // 1. pre-norms + concat
    rmsnorm_tf32_kernel<<<NTOK, 256>>>(embeddings, pre_emb_w, pt_xcat, HH, 2048, 0);
    rmsnorm_tf32_kernel<<<NTOK, 256>>>(hidden,     pre_hid_w, pt_xcat, HH, 2048, 1024);
    // 2. fc
    launch_gemm(pt_xcat, ptw_fc, p_x0, nullptr, NTOK, HH, 2048, 0, 0, 0, 1, 0, 0, 1.f, 0);
    // 3. in_ln
    rmsnorm_tf32_kernel<<<NTOK, 256>>>(p_x0, in_ln_w, pt_xn, HH, 1024, 0);
    // 4. qkv
    launch_gemm(pt_xn, ptw_q, p_qg,   nullptr, NTOK, 4096, HH, 0, 0, 0, 1, 0, 0, 1.f, 0);
    launch_gemm(pt_xn, ptw_k, p_kbuf, nullptr, NTOK, 512,  HH, 0, 0, 0, 1, 0, 0, 1.f, 0);
    launch_gemm(pt_xn, ptw_v, p_vbuf, nullptr, NTOK, 512,  HH, 0, 0, 0, 1, 0, 0, 1.f, 0);
    // 5. head post
    qpost_kernel<<<dim3(NTOK, NQH), 256>>>(p_qg, qn_w, pt_q);
    kpost_kernel<<<dim3(NTOK, NKVH), 256>>>(p_kbuf, kn_w, pt_k);
    vpost_kernel<<<dim3(LL / 32, DD / 32, BBATCH * NKVH), 256>>>(p_vbuf, pt_vt);
    // 6. scores = QK^T/16 causal (skip masked blocks)
    launch_gemm(pt_q, pt_k, p_scores, nullptr, LL, LL, DD,
                (long long)LL * DD, (long long)LL * DD, (long long)LL * LL,
                BBATCH * NQH, 1, 2, 0.0625f, 0);
    // 7. softmax (causal-aware)
    softmax_tf32_kernel<<<dim3(LL, BBATCH * NQH), 256>>>(p_scores, pt_p);
    // 8. attno = P @ V^T (klimit causal)
    launch_gemm(pt_p, pt_vt, p_attno, nullptr, LL, DD, LL,
                (long long)LL * LL, (long long)DD * LL, (long long)LL * DD,
                BBATCH * NQH, 1, 0, 1.f, 1);
    // 9. gate
    gather_gate_kernel<<<(NTOK * 2048) / 256, 256>>>(p_attno, p_qg, pt_ao);
    // 10. o proj + residual
    launch_gemm(pt_ao, ptw_o, p_x1, p_x0, NTOK, HH, 2048, 0, 0, 0, 1, 0, 1, 1.f, 0);
    // 11. post_ln
    rmsnorm_tf32_kernel<<<NTOK, 256>>>(p_x1, post_ln_w, pt_xn2, HH, 1024, 0);
    // 12. MLP
    launch_gemm(pt_xn2, ptw_gate, p_gbuf, nullptr, NTOK, II, HH, 0, 0, 0, 1, 0, 0, 1.f, 0);
    launch_gemm(pt_xn2, ptw_up,   p_ubuf, nullptr, NTOK, II, HH, 0, 0, 0, 1, 0, 0, 1.f, 0);
    silu_mul_kernel<<<((long)NTOK * II) / 256, 256>>>(p_gbuf, p_ubuf, pt_gml, (long)NTOK * II);
    launch_gemm(pt_gml, ptw_down, p_x2, p_x1, NTOK, HH, II, 0, 0, 0, 1, 0, 1, 1.f, 0);
    // 15. final norm + lm head
    rmsnorm_tf32_kernel<<<NTOK, 256>>>(p_x2, norm_w, pt_xn3, HH, 1024, 0);
    launch_gemm(pt_xn3, ptw_lm, out, nullptr, NTOK, VV, HH, 0, 0, 0, 1, 0, 0, 1.f, 0);
}

// round 8
// speedup vs baseline: 2.9961x; 1.0720x over previous
#include <cuda_runtime.h>
#include <math.h>
#include <stdint.h>

#define BBATCH 4
#define LL    2048
#define HH    1024
#define NQH   8
#define NKVH  2
#define DD    256
#define II    3584
#define VV    16384
#define NTOK  (BBATCH*LL)
#define FMIN  (-3.402823466e38f)

// fp32 GEMM-output scratch
__device__ __align__(256) float g_x0    [(size_t)NTOK * HH];
__device__ __align__(256) float g_qg    [(size_t)NTOK * 4096];
__device__ __align__(256) float g_kbuf  [(size_t)NTOK * 512];
__device__ __align__(256) float g_vbuf  [(size_t)NTOK * 512];
__device__ __align__(256) float g_scores[(size_t)BBATCH * NQH * LL * LL];
__device__ __align__(256) float g_attno [(size_t)BBATCH * NQH * LL * DD];
__device__ __align__(256) float g_gbuf  [(size_t)NTOK * II];
__device__ __align__(256) float g_ubuf  [(size_t)NTOK * II];
__device__ __align__(256) float g_x1    [(size_t)NTOK * HH];
__device__ __align__(256) float g_x2    [(size_t)NTOK * HH];
// tf32-rounded fp32 GEMM-input buffers
__device__ __align__(256) float t_xcat [(size_t)NTOK * 2048];
__device__ __align__(256) float t_xn   [(size_t)NTOK * HH];
__device__ __align__(256) float t_q    [(size_t)BBATCH * NQH * LL * DD];
__device__ __align__(256) float t_k    [(size_t)BBATCH * NKVH * LL * DD];
__device__ __align__(256) float t_vt   [(size_t)BBATCH * NKVH * DD * LL];
__device__ __align__(256) float t_p    [(size_t)BBATCH * NQH * LL * LL];
__device__ __align__(256) float t_ao   [(size_t)NTOK * 2048];
__device__ __align__(256) float t_xn2  [(size_t)NTOK * HH];
__device__ __align__(256) float t_xn3  [(size_t)NTOK * HH];
__device__ __align__(256) float t_gml  [(size_t)NTOK * II];
// tf32-rounded weights
__device__ __align__(256) float tw_fc   [(size_t)HH * 2048];
__device__ __align__(256) float tw_q    [(size_t)4096 * HH];
__device__ __align__(256) float tw_k    [(size_t)512 * HH];
__device__ __align__(256) float tw_v    [(size_t)512 * HH];
__device__ __align__(256) float tw_o    [(size_t)HH * 2048];
__device__ __align__(256) float tw_gate [(size_t)II * HH];
__device__ __align__(256) float tw_up   [(size_t)II * HH];
__device__ __align__(256) float tw_down [(size_t)HH * II];
__device__ __align__(256) float tw_lm   [(size_t)VV * HH];

// ---------------- helpers ----------------
__device__ __forceinline__ uint32_t smem_u32(const void* p) {
    uint32_t a;
    asm("{ .reg .u64 t; cvta.to.shared.u64 t, %1; cvt.u32.u64 %0, t; }" : "=r"(a) : "l"(p));
    return a;
}
#define SWZ(o) ((o) ^ (((o) >> 3) & 0x70))

__device__ __forceinline__ float tf32r(float x) {
    uint32_t r;
    asm("cvt.rna.tf32.f32 %0, %1;" : "=r"(r) : "f"(x));
    return __uint_as_float(r);
}
__device__ __forceinline__ void cp16(uint32_t dst, const void* src) {
    asm volatile("cp.async.cg.shared.global [%0], [%1], 16;" :: "r"(dst), "l"(src));
}
__device__ __forceinline__ void cp_commit() { asm volatile("cp.async.commit_group;"); }
template<int N> __device__ __forceinline__ void cp_wait() {
    asm volatile("cp.async.wait_group %0;" :: "n"(N));
}
__device__ __forceinline__ uint32_t lds_u(uint32_t a) {
    uint32_t v;
    asm volatile("ld.shared.b32 %0, [%1];" : "=r"(v) : "r"(a));
    return v;
}
__device__ __forceinline__ void mma_tf32(float* c, const uint32_t* a, const uint32_t* b) {
    asm volatile(
        "mma.sync.aligned.m16n8k8.row.col.f32.tf32.tf32.f32 "
        "{%0,%1,%2,%3},{%4,%5,%6,%7},{%8,%9},{%0,%1,%2,%3};"
        : "+f"(c[0]), "+f"(c[1]), "+f"(c[2]), "+f"(c[3])
        : "r"(a[0]), "r"(a[1]), "r"(a[2]), "r"(a[3]), "r"(b[0]), "r"(b[1]));
}

// block reduce (256 thr)
__device__ __forceinline__ float blk_sum(float v) {
    __shared__ float sh[8]; __shared__ float res;
    #pragma unroll
    for (int o = 16; o; o >>= 1) v += __shfl_xor_sync(0xffffffffu, v, o);
    if ((threadIdx.x & 31) == 0) sh[threadIdx.x >> 5] = v;
    __syncthreads();
    if (threadIdx.x < 32) {
        float x = (threadIdx.x < 8) ? sh[threadIdx.x] : 0.f;
        #pragma unroll
        for (int o = 4; o; o >>= 1) x += __shfl_xor_sync(0xffffffffu, x, o);
        if (threadIdx.x == 0) res = x;
    }
    __syncthreads();
    return res;
}
__device__ __forceinline__ float blk_max(float v) {
    __shared__ float sh[8]; __shared__ float res;
    #pragma unroll
    for (int o = 16; o; o >>= 1) v = fmaxf(v, __shfl_xor_sync(0xffffffffu, v, o));
    if ((threadIdx.x & 31) == 0) sh[threadIdx.x >> 5] = v;
    __syncthreads();
    if (threadIdx.x < 32) {
        float x = (threadIdx.x < 8) ? sh[threadIdx.x] : -INFINITY;
        #pragma unroll
        for (int o = 4; o; o >>= 1) x = fmaxf(x, __shfl_xor_sync(0xffffffffu, x, o));
        if (threadIdx.x == 0) res = x;
    }
    __syncthreads();
    return res;
}

// ---------------- tf32 mma GEMM: C[M,N] f32 = A[M,K]*B[N,K]^T ----------------
// CTA tile 128x256, warp tile 64x64 (8 warps, 2x4).
// epi 0: plain  1: +R  2: scores(scale+causal, skip masked blocks)
// bmode: GQA z->kv map for B.  klimit: causal K cut.
#define STAGES 3
#define STAGE_BYTES (16384 + 32768)
#define GEMM_SMEM (STAGES * STAGE_BYTES)

__global__ __launch_bounds__(256)
void gemm_tf32_kernel(const float* __restrict__ A, const float* __restrict__ B,
                      float* __restrict__ C, const float* __restrict__ R,
                      int M, int N, int K,
                      long long bAel, long long bBel, long long bCel,
                      int bmode, int epi, float scale, int klimit)
{
    extern __shared__ char smch[];
    int tid = threadIdx.x;
    int z = blockIdx.z;
    int m0 = blockIdx.y * 128;
    int n0 = blockIdx.x * 256;
    if (epi == 2 && n0 > m0 + 127) return;    // fully masked: never read downstream

    const float* Ab = A + (long long)z * bAel;
    long long zb = bmode ? ((long long)(z >> 3) * 2 + ((z & 7) >> 2)) : (long long)z;
    const float* Bb = B + zb * bBel;
    float* Cb = C + (long long)z * bCel;

    uint32_t smu = smem_u32(smch);
    int Keff = klimit ? min(K, m0 + 128) : K;
    int ntiles = Keff / 32;                  // 32 fp32 per k-tile (128B rows)

    int lr = tid >> 3;              // 0..31
    int lc = (tid & 7) * 16;        // 0..112 bytes

    auto issue = [&](int t, int slot) {
        uint32_t bA = smu + slot * STAGE_BYTES;
        uint32_t bB = bA + 16384;
        long long kofs = (long long)t * 32;
        #pragma unroll
        for (int j = 0; j < 4; ++j) {
            int r = lr + j * 32;
            cp16(bA + SWZ(r * 128 + lc),
                 (const char*)(Ab + (long long)(m0 + r) * K + kofs) + lc);
        }
        #pragma unroll
        for (int j = 0; j < 8; ++j) {
            int r = lr + j * 32;
            cp16(bB + SWZ(r * 128 + lc),
                 (const char*)(Bb + (long long)(n0 + r) * K + kofs) + lc);
        }
        cp_commit();
    };

    int wid = tid >> 5, lane = tid & 31;
    int warp_m = (wid & 1) * 64;
    int warp_n = (wid >> 1) * 64;
    int rA = lane >> 2;      // 0..7
    int cA = lane & 3;       // 0..3

    float acc[4][8][4];
    #pragma unroll
    for (int i = 0; i < 4; i++)
        #pragma unroll
        for (int j = 0; j < 8; j++)
            #pragma unroll
            for (int q = 0; q < 4; q++) acc[i][j][q] = 0.f;

    int pre = ntiles < (STAGES - 1) ? ntiles : (STAGES - 1);
    for (int s = 0; s < pre; ++s) issue(s, s);

    for (int t = 0; t < ntiles; ++t) {
        cp_wait<STAGES - 2>();
        __syncthreads();
        if (t + STAGES - 1 < ntiles) issue(t + STAGES - 1, (t + STAGES - 1) % STAGES);
        uint32_t bA = smu + (t % STAGES) * STAGE_BYTES;
        uint32_t bB = bA + 16384;
        #pragma unroll
        for (int kk = 0; kk < 4; ++kk) {
            int c0 = kk * 8 + cA;
            uint32_t af[4][4], bf[8][2];
            #pragma unroll
            for (int mi = 0; mi < 4; ++mi) {
                int r = warp_m + mi * 16 + rA;
                // PTX m16n8k8.tf32 A order: a0=(g,k) a1=(g+8,k) a2=(g,k+4) a3=(g+8,k+4)
                af[mi][0] = lds_u(bA + SWZ(r * 128 + c0 * 4));
                af[mi][1] = lds_u(bA + SWZ((r + 8) * 128 + c0 * 4));
                af[mi][2] = lds_u(bA + SWZ(r * 128 + (c0 + 4) * 4));
                af[mi][3] = lds_u(bA + SWZ((r + 8) * 128 + (c0 + 4) * 4));
            }
            #pragma unroll
            for (int ni = 0; ni < 8; ++ni) {
                int nn = warp_n + ni * 8 + rA;
                bf[ni][0] = lds_u(bB + SWZ(nn * 128 + c0 * 4));
                bf[ni][1] = lds_u(bB + SWZ(nn * 128 + (c0 + 4) * 4));
            }
            #pragma unroll
            for (int mi = 0; mi < 4; ++mi)
                #pragma unroll
                for (int ni = 0; ni < 8; ++ni)
                    mma_tf32(acc[mi][ni], af[mi], bf[ni]);
        }
        __syncthreads();
    }

    // epilogue: direct fragment stores
    int g = lane >> 2, t4 = lane & 3;
    #pragma unroll
    for (int mi = 0; mi < 4; ++mi) {
        int r0 = m0 + warp_m + mi * 16 + g;
        int r1 = r0 + 8;
        #pragma unroll
        for (int ni = 0; ni < 8; ++ni) {
            int col = n0 + warp_n + ni * 8 + t4 * 2;
            float v0 = acc[mi][ni][0], v1 = acc[mi][ni][1];
            float v2 = acc[mi][ni][2], v3 = acc[mi][ni][3];
            if (epi == 2) {
                v0 *= scale; v1 *= scale; v2 *= scale; v3 *= scale;
                if (col     > r0) v0 = FMIN;
                if (col + 1 > r0) v1 = FMIN;
                if (col     > r1) v2 = FMIN;
                if (col + 1 > r1) v3 = FMIN;
            } else if (epi == 1) {
                long long o0 = (long long)r0 * N + col;
                long long o1 = (long long)r1 * N + col;
                v0 += R[o0]; v1 += R[o0 + 1]; v2 += R[o1]; v3 += R[o1 + 1];
            }
            *(float2*)&Cb[(long long)r0 * N + col] = make_float2(v0, v1);
            *(float2*)&Cb[(long long)r1 * N + col] = make_float2(v2, v3);
        }
    }
}

// ---------------- elementwise kernels (all GEMM inputs tf32-rounded) ----------------
__global__ void convert_tf32_kernel(const float* __restrict__ in, float* __restrict__ out, long n) {
    long i = (long)blockIdx.x * 256 + threadIdx.x;
    if (i < n) out[i] = tf32r(in[i]);
}
__global__ void rmsnorm_tf32_kernel(const float* __restrict__ in, const float* __restrict__ w,
                                    float* __restrict__ out, int width,
                                    long row_stride, long col_off) {
    long t = blockIdx.x;
    const float* x = in + t * width;
    float ss = 0.f;
    for (int i = threadIdx.x; i < width; i += 256) { float v = x[i]; ss = fmaf(v, v, ss); }
    float rms = rsqrtf(blk_sum(ss) / (float)width + 1e-6f);
    float* y = out + t * row_stride + col_off;
    for (int i = threadIdx.x; i < width; i += 256) y[i] = tf32r(x[i] * rms * w[i]);
}
__global__ void qpost_kernel(const float* __restrict__ qg, const float* __restrict__ qn_w,
                             float* __restrict__ qdst) {
    int t = blockIdx.x, h = blockIdx.y;
    int b = t / LL, l = t % LL;
    const float* src = qg + (long)t * 4096 + h * 512;
    int tid = threadIdx.x;
    float v = src[tid];
    float rms = rsqrtf(blk_sum(v * v) / (float)DD + 1e-6f);
    __shared__ float sq[DD];
    sq[tid] = v * rms * qn_w[tid];
    __syncthreads();
    if (tid < 32) {
        double inv = exp(-((double)(2 * tid) / 64.0) * log(1.0e7));
        double fr = (double)l * inv, c = cos(fr), s = sin(fr);
        float x0 = sq[2 * tid], x1 = sq[2 * tid + 1];
        sq[2 * tid]     = (float)((double)x0 * c - (double)x1 * s);
        sq[2 * tid + 1] = (float)((double)x0 * s + (double)x1 * c);
    }
    __syncthreads();
    long row = (long)(b * NQH + h) * LL + l;
    qdst[row * DD + tid] = tf32r(sq[tid]);
}
__global__ void kpost_kernel(const float* __restrict__ kbuf, const float* __restrict__ kn_w,
                             float* __restrict__ kdst) {
    int t = blockIdx.x, h = blockIdx.y;
    int b = t / LL, l = t % LL;
    const float* src = kbuf + (long)t * 512 + h * 256;
    int tid = threadIdx.x;
    float v = src[tid];
    float rms = rsqrtf(blk_sum(v * v) / (float)DD + 1e-6f);
    __shared__ float sq[DD];
    sq[tid] = v * rms * kn_w[tid];
    __syncthreads();
    if (tid < 32) {
        double inv = exp(-((double)(2 * tid) / 64.0) * log(1.0e7));
        double fr = (double)l * inv, c = cos(fr), s = sin(fr);
        float x0 = sq[2 * tid], x1 = sq[2 * tid + 1];
        sq[2 * tid]     = (float)((double)x0 * c - (double)x1 * s);
        sq[2 * tid + 1] = (float)((double)x0 * s + (double)x1 * c);
    }
    __syncthreads();
    long row = (long)(b * NKVH + h) * LL + l;
    kdst[row * DD + tid] = tf32r(sq[tid]);
}
__global__ void vpost_kernel(const float* __restrict__ vbuf, float* __restrict__ vt) {
    __shared__ float smv[32][33];
    int l0 = blockIdx.x * 32, d0 = blockIdx.y * 32, z = blockIdx.z;
    int b = z >> 1, h = z & 1;
    int tx = threadIdx.x & 31, ty = threadIdx.x >> 5;
    #pragma unroll
    for (int j = 0; j < 4; ++j) {
        int lloc = ty + j * 8;
        smv[lloc][tx] = vbuf[(long)(b * LL + l0 + lloc) * 512 + h * 256 + d0 + tx];
    }
    __syncthreads();
    #pragma unroll
    for (int j = 0; j < 4; ++j) {
        int dd = ty + j * 8;
        vt[(long)(z * DD + d0 + dd) * LL + l0 + tx] = tf32r(smv[tx][dd]);
    }
}
// causal-aware softmax: only the written 128-aligned prefix is touched
__global__ void softmax_tf32_kernel(const float* __restrict__ scores, float* __restrict__ p) {
    int q = blockIdx.x, z = blockIdx.y;
    const float* row = scores + ((long)z * LL + q) * LL;
    float* prow = p + ((long)z * LL + q) * LL;
    int nwrite = ((q >> 7) + 1) << 7;
    float vals[8], mx = -INFINITY;
    #pragma unroll
    for (int i = 0; i < 8; i++) {
        int col = threadIdx.x + i * 256;
        vals[i] = (col < nwrite) ? row[col] : -INFINITY;
        mx = fmaxf(mx, vals[i]);
    }
    mx = blk_max(mx);
    float sum = 0.f;
    #pragma unroll
    for (int i = 0; i < 8; i++) { vals[i] = __expf(vals[i] - mx); sum += vals[i]; }
    sum = blk_sum(sum);
    float invs = 1.f / sum;
    #pragma unroll
    for (int i = 0; i < 8; i++) {
        int col = threadIdx.x + i * 256;
        if (col < nwrite) prow[col] = tf32r(vals[i] * invs);
    }
}
__global__ void gather_gate_kernel(const float* __restrict__ attno, const float* __restrict__ qg,
                                   float* __restrict__ ao) {
    long i = (long)blockIdx.x * 256 + threadIdx.x;
    int t = (int)(i >> 11), c = (int)(i & 2047);
    int h = c >> 8, d = c & 255;
    int b = t / LL, l = t % LL;
    float o = attno[((long)(b * NQH + h) * LL + l) * DD + d];
    float gate = qg[(long)t * 4096 + h * 512 + 256 + d];
    ao[i] = tf32r(o * (1.f / (1.f + expf(-gate))));
}
__global__ void silu_mul_kernel(const float* __restrict__ g, const float* __restrict__ u,
                                float* __restrict__ out, long n) {
    long i = (long)blockIdx.x * 256 + threadIdx.x;
    if (i < n) {
        float x = g[i];
        out[i] = tf32r(x * (1.f / (1.f + expf(-x))) * u[i]);
    }
}

// ---------------- launch ----------------
static void launch_gemm(const float* A, const float* B, float* C, const float* R,
                        int M, int N, int K, long long bAel, long long bBel, long long bCel,
                        int nz, int bmode, int epi, float scale, int klimit) {
    dim3 grid(N / 256, M / 128, nz);
    gemm_tf32_kernel<<<grid, 256, GEMM_SMEM>>>(A, B, C, R, M, N, K,
                                               bAel, bBel, bCel, bmode, epi, scale, klimit);
}

extern "C" void kernel_launch(void* const* d_in, const int* in_sizes, int n_in,
                              void* d_out, int out_size) {
    (void)in_sizes; (void)n_in; (void)out_size;
    const float* embeddings = (const float*)d_in[0];
    const float* hidden     = (const float*)d_in[1];
    const float* pre_emb_w  = (const float*)d_in[2];
    const float* pre_hid_w  = (const float*)d_in[3];
    const float* fc_w       = (const float*)d_in[4];
    const float* in_ln_w    = (const float*)d_in[5];
    const float* q_w        = (const float*)d_in[6];
    const float* k_w        = (const float*)d_in[7];
    const float* v_w        = (const float*)d_in[8];
    const float* o_w        = (const float*)d_in[9];
    const float* qn_w       = (const float*)d_in[10];
    const float* kn_w       = (const float*)d_in[11];
    const float* post_ln_w  = (const float*)d_in[12];
    const float* gate_w     = (const float*)d_in[13];
    const float* up_w       = (const float*)d_in[14];
    const float* down_w     = (const float*)d_in[15];
    const float* norm_w     = (const float*)d_in[16];
    const float* lm_w       = (const float*)d_in[17];
    float* out = (float*)d_out;

    static bool inited = false;
    static float *p_x0, *p_qg, *p_kbuf, *p_vbuf, *p_scores, *p_attno, *p_gbuf, *p_ubuf, *p_x1, *p_x2;
    static float *pt_xcat, *pt_xn, *pt_q, *pt_k, *pt_vt, *pt_p, *pt_ao, *pt_xn2, *pt_xn3, *pt_gml;
    static float *ptw_fc, *ptw_q, *ptw_k, *ptw_v, *ptw_o, *ptw_gate, *ptw_up, *ptw_down, *ptw_lm;
    if (!inited) {
        cudaGetSymbolAddress((void**)&p_x0, g_x0);      cudaGetSymbolAddress((void**)&p_qg, g_qg);
        cudaGetSymbolAddress((void**)&p_kbuf, g_kbuf);  cudaGetSymbolAddress((void**)&p_vbuf, g_vbuf);
        cudaGetSymbolAddress((void**)&p_scores, g_scores); cudaGetSymbolAddress((void**)&p_attno, g_attno);
        cudaGetSymbolAddress((void**)&p_gbuf, g_gbuf);  cudaGetSymbolAddress((void**)&p_ubuf, g_ubuf);
        cudaGetSymbolAddress((void**)&p_x1, g_x1);      cudaGetSymbolAddress((void**)&p_x2, g_x2);
        cudaGetSymbolAddress((void**)&pt_xcat, t_xcat); cudaGetSymbolAddress((void**)&pt_xn, t_xn);
        cudaGetSymbolAddress((void**)&pt_q, t_q);       cudaGetSymbolAddress((void**)&pt_k, t_k);
        cudaGetSymbolAddress((void**)&pt_vt, t_vt);     cudaGetSymbolAddress((void**)&pt_p, t_p);
        cudaGetSymbolAddress((void**)&pt_ao, t_ao);     cudaGetSymbolAddress((void**)&pt_xn2, t_xn2);
        cudaGetSymbolAddress((void**)&pt_xn3, t_xn3);   cudaGetSymbolAddress((void**)&pt_gml, t_gml);
        cudaGetSymbolAddress((void**)&ptw_fc, tw_fc);   cudaGetSymbolAddress((void**)&ptw_q, tw_q);
        cudaGetSymbolAddress((void**)&ptw_k, tw_k);     cudaGetSymbolAddress((void**)&ptw_v, tw_v);
        cudaGetSymbolAddress((void**)&ptw_o, tw_o);     cudaGetSymbolAddress((void**)&ptw_gate, tw_gate);
        cudaGetSymbolAddress((void**)&ptw_up, tw_up);   cudaGetSymbolAddress((void**)&ptw_down, tw_down);
        cudaGetSymbolAddress((void**)&ptw_lm, tw_lm);
        cudaFuncSetAttribute(gemm_tf32_kernel, cudaFuncAttributeMaxDynamicSharedMemorySize, GEMM_SMEM);
        inited = true;
    }

    // weights -> tf32-rounded fp32
    long n;
    n = (long)HH * 2048;  convert_tf32_kernel<<<(n + 255) / 256, 256>>>(fc_w,   ptw_fc,   n);
    n = (long)4096 * HH;  convert_tf32_kernel<<<(n + 255) / 256, 256>>>(q_w,    ptw_q,    n);
    n = (long)512 * HH;   convert_tf32_kernel<<<(n + 255) / 256, 256>>>(k_w,    ptw_k,    n);
    n = (long)512 * HH;   convert_tf32_kernel<<<(n + 255) / 256, 256>>>(v_w,    ptw_v,    n);
    n = (long)HH * 2048;  convert_tf32_kernel<<<(n + 255) / 256, 256>>>(o_w,    ptw_o,    n);
    n = (long)II * HH;    convert_tf32_kernel<<<(n + 255) / 256, 256>>>(gate_w, ptw_gate, n);
    n = (long)II * HH;    convert_tf32_kernel<<<(n + 255) / 256, 256>>>(up_w,   ptw_up,   n);
    n = (long)HH * II;    convert_tf32_kernel<<<(n + 255) / 256, 256>>>(down_w, ptw_down, n);
    n = (long)VV * HH;    convert_tf32_kernel<<<(n + 255) / 256, 256>>>(lm_w,   ptw_lm,   n);

    // 1. pre-norms + concat
    rmsnorm_tf32_kernel<<<NTOK, 256>>>(embeddings, pre_emb_w, pt_xcat, HH, 2048, 0);
    rmsnorm_tf32_kernel<<<NTOK, 256>>>(hidden,     pre_hid_w, pt_xcat, HH, 2048, 1024);
    // 2. fc
    launch_gemm(pt_xcat, ptw_fc, p_x0, nullptr, NTOK, HH, 2048, 0, 0, 0, 1, 0, 0, 1.f, 0);
    // 3. in_ln
    rmsnorm_tf32_kernel<<<NTOK, 256>>>(p_x0, in_ln_w, pt_xn, HH, 1024, 0);
    // 4. qkv
    launch_gemm(pt_xn, ptw_q, p_qg,   nullptr, NTOK, 4096, HH, 0, 0, 0, 1, 0, 0, 1.f, 0);
    launch_gemm(pt_xn, ptw_k, p_kbuf, nullptr, NTOK, 512,  HH, 0, 0, 0, 1, 0, 0, 1.f, 0);
    launch_gemm(pt_xn, ptw_v, p_vbuf, nullptr, NTOK, 512,  HH, 0, 0, 0, 1, 0, 0, 1.f, 0);
    // 5. head post
    qpost_kernel<<<dim3(NTOK, NQH), 256>>>(p_qg, qn_w, pt_q);
    kpost_kernel<<<dim3(NTOK, NKVH), 256>>>(p_kbuf, kn_w, pt_k);
    vpost_kernel<<<dim3(LL / 32, DD / 32, BBATCH * NKVH), 256>>>(p_vbuf, pt_vt);
    // 6. scores = QK^T/16 causal (skip masked blocks)
    launch_gemm(pt_q, pt_k, p_scores, nullptr, LL, LL, DD,
                (long long)LL * DD, (long long)LL * DD, (long long)LL * LL,
                BBATCH * NQH, 1, 2, 0.0625f, 0);
    // 7. softmax (causal-aware)
    softmax_tf32_kernel<<<dim3(LL, BBATCH * NQH), 256>>>(p_scores, pt_p);
    // 8. attno = P @ V^T (klimit causal)
    launch_gemm(pt_p, pt_vt, p_attno, nullptr, LL, DD, LL,
                (long long)LL * LL, (long long)DD * LL, (long long)LL * DD,
                BBATCH * NQH, 1, 0, 1.f, 1);
    // 9. gate
    gather_gate_kernel<<<(NTOK * 2048) / 256, 256>>>(p_attno, p_qg, pt_ao);
    // 10. o proj + residual
    launch_gemm(pt_ao, ptw_o, p_x1, p_x0, NTOK, HH, 2048, 0, 0, 0, 1, 0, 1, 1.f, 0);
    // 11. post_ln
    rmsnorm_tf32_kernel<<<NTOK, 256>>>(p_x1, post_ln_w, pt_xn2, HH, 1024, 0);
    // 12. MLP
    launch_gemm(pt_xn2, ptw_gate, p_gbuf, nullptr, NTOK, II, HH, 0, 0, 0, 1, 0, 0, 1.f, 0);
    launch_gemm(pt_xn2, ptw_up,   p_ubuf, nullptr, NTOK, II, HH, 0, 0, 0, 1, 0, 0, 1.f, 0);
    silu_mul_kernel<<<((long)NTOK * II) / 256, 256>>>(p_gbuf, p_ubuf, pt_gml, (long)NTOK * II);
    launch_gemm(pt_gml, ptw_down, p_x2, p_x1, NTOK, HH, II, 0, 0, 0, 1, 0, 1, 1.f, 0);
    // 15. final norm + lm head
    rmsnorm_tf32_kernel<<<NTOK, 256>>>(p_x2, norm_w, pt_xn3, HH, 1024, 0);
    launch_gemm(pt_xn3, ptw_lm, out, nullptr, NTOK, VV, HH, 0, 0, 0, 1, 0, 0, 1.f, 0);
}

// round 9
// speedup vs baseline: 3.0760x; 1.0267x over previous
#include <cuda_runtime.h>
#include <cuda_bf16.h>
#include <math.h>
#include <stdint.h>

#define BBATCH 4
#define LL    2048
#define HH    1024
#define NQH   8
#define NKVH  2
#define DD    256
#define II    3584
#define VV    16384
#define NTOK  (BBATCH*LL)
#define FMIN  (-3.402823466e38f)

// fp32 scratch
__device__ __align__(256) float g_xcat  [(size_t)NTOK * 2048];
__device__ __align__(256) float g_x0    [(size_t)NTOK * HH];
__device__ __align__(256) float g_xn    [(size_t)NTOK * HH];
__device__ __align__(256) float g_qg    [(size_t)NTOK * 4096];
__device__ __align__(256) float g_kbuf  [(size_t)NTOK * 512];
__device__ __align__(256) float g_vbuf  [(size_t)NTOK * 512];
__device__ __align__(256) float g_scores[(size_t)BBATCH * NQH * LL * LL];
__device__ __align__(256) float g_attno [(size_t)BBATCH * NQH * LL * DD];
__device__ __align__(256) float g_ao    [(size_t)NTOK * 2048];
__device__ __align__(256) float g_x1    [(size_t)NTOK * HH];
__device__ __align__(256) float g_xn2   [(size_t)NTOK * HH];
__device__ __align__(256) float g_gbuf  [(size_t)NTOK * II];
__device__ __align__(256) float g_ubuf  [(size_t)NTOK * II];
__device__ __align__(256) float g_gml   [(size_t)NTOK * II];
__device__ __align__(256) float g_x2    [(size_t)NTOK * HH];
__device__ __align__(256) float g_xn3   [(size_t)NTOK * HH];
// bf16 attention buffers
__device__ __align__(256) __nv_bfloat16 h_q [(size_t)BBATCH * NQH * LL * DD];
__device__ __align__(256) __nv_bfloat16 h_k [(size_t)BBATCH * NKVH * LL * DD];
__device__ __align__(256) __nv_bfloat16 h_vt[(size_t)BBATCH * NKVH * DD * LL];
__device__ __align__(256) __nv_bfloat16 h_p [(size_t)BBATCH * NQH * LL * LL];

// ---------------- helpers ----------------
__device__ __forceinline__ uint32_t smem_u32(const void* p) {
    uint32_t a;
    asm("{ .reg .u64 t; cvta.to.shared.u64 t, %1; cvt.u32.u64 %0, t; }" : "=r"(a) : "l"(p));
    return a;
}
#define SWZ(o) ((o) ^ (((o) >> 3) & 0x70))

__device__ __forceinline__ uint32_t rnd_tf32(uint32_t x) {
    uint32_t r;
    asm("cvt.rna.tf32.f32 %0, %1;" : "=r"(r) : "f"(__uint_as_float(x)));
    return r;
}
__device__ __forceinline__ void cp16(uint32_t dst, const void* src) {
    asm volatile("cp.async.cg.shared.global [%0], [%1], 16;" :: "r"(dst), "l"(src));
}
__device__ __forceinline__ void cp_commit() { asm volatile("cp.async.commit_group;"); }
template<int N> __device__ __forceinline__ void cp_wait() {
    asm volatile("cp.async.wait_group %0;" :: "n"(N));
}
__device__ __forceinline__ uint32_t lds_u(uint32_t a) {
    uint32_t v;
    asm volatile("ld.shared.b32 %0, [%1];" : "=r"(v) : "r"(a));
    return v;
}
__device__ __forceinline__ void ldm_x4(uint32_t* r, uint32_t addr) {
    asm volatile("ldmatrix.sync.aligned.m8n8.x4.shared.b16 {%0,%1,%2,%3}, [%4];"
                 : "=r"(r[0]), "=r"(r[1]), "=r"(r[2]), "=r"(r[3]) : "r"(addr));
}
__device__ __forceinline__ void mma_tf32(float* c, const uint32_t* a, const uint32_t* b) {
    asm volatile(
        "mma.sync.aligned.m16n8k8.row.col.f32.tf32.tf32.f32 "
        "{%0,%1,%2,%3},{%4,%5,%6,%7},{%8,%9},{%0,%1,%2,%3};"
        : "+f"(c[0]), "+f"(c[1]), "+f"(c[2]), "+f"(c[3])
        : "r"(a[0]), "r"(a[1]), "r"(a[2]), "r"(a[3]), "r"(b[0]), "r"(b[1]));
}
__device__ __forceinline__ void mma_bf16(float* c, const uint32_t* a, const uint32_t* b) {
    asm volatile(
        "mma.sync.aligned.m16n8k16.row.col.f32.bf16.bf16.f32 "
        "{%0,%1,%2,%3},{%4,%5,%6,%7},{%8,%9},{%0,%1,%2,%3};"
        : "+f"(c[0]), "+f"(c[1]), "+f"(c[2]), "+f"(c[3])
        : "r"(a[0]), "r"(a[1]), "r"(a[2]), "r"(a[3]), "r"(b[0]), "r"(b[1]));
}

// block reduce (256 thr)
__device__ __forceinline__ float blk_sum(float v) {
    __shared__ float sh[8]; __shared__ float res;
    #pragma unroll
    for (int o = 16; o; o >>= 1) v += __shfl_xor_sync(0xffffffffu, v, o);
    if ((threadIdx.x & 31) == 0) sh[threadIdx.x >> 5] = v;
    __syncthreads();
    if (threadIdx.x < 32) {
        float x = (threadIdx.x < 8) ? sh[threadIdx.x] : 0.f;
        #pragma unroll
        for (int o = 4; o; o >>= 1) x += __shfl_xor_sync(0xffffffffu, x, o);
        if (threadIdx.x == 0) res = x;
    }
    __syncthreads();
    return res;
}
__device__ __forceinline__ float blk_max(float v) {
    __shared__ float sh[8]; __shared__ float res;
    #pragma unroll
    for (int o = 16; o; o >>= 1) v = fmaxf(v, __shfl_xor_sync(0xffffffffu, v, o));
    if ((threadIdx.x & 31) == 0) sh[threadIdx.x >> 5] = v;
    __syncthreads();
    if (threadIdx.x < 32) {
        float x = (threadIdx.x < 8) ? sh[threadIdx.x] : -INFINITY;
        #pragma unroll
        for (int o = 4; o; o >>= 1) x = fmaxf(x, __shfl_xor_sync(0xffffffffu, x, o));
        if (threadIdx.x == 0) res = x;
    }
    __syncthreads();
    return res;
}

// ---------------- tf32 mma GEMM (in-register rna rounding of raw fp32) ----------------
// C[M,N] f32 = A[M,K]*B[N,K]^T.  CTA 128x256, warp 64x64.
// epi 0: plain  1: +R
#define STAGES 3
#define STAGE_BYTES (16384 + 32768)
#define GEMM_SMEM (STAGES * STAGE_BYTES)

__global__ __launch_bounds__(256)
void gemm_tf32_kernel(const float* __restrict__ A, const float* __restrict__ B,
                      float* __restrict__ C, const float* __restrict__ R,
                      int M, int N, int K, int epi)
{
    extern __shared__ char smch[];
    int tid = threadIdx.x;
    int m0 = blockIdx.y * 128;
    int n0 = blockIdx.x * 256;

    uint32_t smu = smem_u32(smch);
    int ntiles = K / 32;

    int lr = tid >> 3;
    int lc = (tid & 7) * 16;

    auto issue = [&](int t, int slot) {
        uint32_t bA = smu + slot * STAGE_BYTES;
        uint32_t bB = bA + 16384;
        long long kofs = (long long)t * 32;
        #pragma unroll
        for (int j = 0; j < 4; ++j) {
            int r = lr + j * 32;
            cp16(bA + SWZ(r * 128 + lc),
                 (const char*)(A + (long long)(m0 + r) * K + kofs) + lc);
        }
        #pragma unroll
        for (int j = 0; j < 8; ++j) {
            int r = lr + j * 32;
            cp16(bB + SWZ(r * 128 + lc),
                 (const char*)(B + (long long)(n0 + r) * K + kofs) + lc);
        }
        cp_commit();
    };

    int wid = tid >> 5, lane = tid & 31;
    int warp_m = (wid & 1) * 64;
    int warp_n = (wid >> 1) * 64;
    int rA = lane >> 2;
    int cA = lane & 3;

    float acc[4][8][4];
    #pragma unroll
    for (int i = 0; i < 4; i++)
        #pragma unroll
        for (int j = 0; j < 8; j++)
            #pragma unroll
            for (int q = 0; q < 4; q++) acc[i][j][q] = 0.f;

    int pre = ntiles < (STAGES - 1) ? ntiles : (STAGES - 1);
    for (int s = 0; s < pre; ++s) issue(s, s);

    for (int t = 0; t < ntiles; ++t) {
        cp_wait<STAGES - 2>();
        __syncthreads();
        if (t + STAGES - 1 < ntiles) issue(t + STAGES - 1, (t + STAGES - 1) % STAGES);
        uint32_t bA = smu + (t % STAGES) * STAGE_BYTES;
        uint32_t bB = bA + 16384;
        #pragma unroll
        for (int kk = 0; kk < 4; ++kk) {
            int c0 = kk * 8 + cA;
            uint32_t af[4][4], bf[8][2];
            #pragma unroll
            for (int mi = 0; mi < 4; ++mi) {
                int r = warp_m + mi * 16 + rA;
                af[mi][0] = rnd_tf32(lds_u(bA + SWZ(r * 128 + c0 * 4)));
                af[mi][1] = rnd_tf32(lds_u(bA + SWZ((r + 8) * 128 + c0 * 4)));
                af[mi][2] = rnd_tf32(lds_u(bA + SWZ(r * 128 + (c0 + 4) * 4)));
                af[mi][3] = rnd_tf32(lds_u(bA + SWZ((r + 8) * 128 + (c0 + 4) * 4)));
            }
            #pragma unroll
            for (int ni = 0; ni < 8; ++ni) {
                int nn = warp_n + ni * 8 + rA;
                bf[ni][0] = rnd_tf32(lds_u(bB + SWZ(nn * 128 + c0 * 4)));
                bf[ni][1] = rnd_tf32(lds_u(bB + SWZ(nn * 128 + (c0 + 4) * 4)));
            }
            #pragma unroll
            for (int mi = 0; mi < 4; ++mi)
                #pragma unroll
                for (int ni = 0; ni < 8; ++ni)
                    mma_tf32(acc[mi][ni], af[mi], bf[ni]);
        }
        __syncthreads();
    }

    int g = lane >> 2, t4 = lane & 3;
    #pragma unroll
    for (int mi = 0; mi < 4; ++mi) {
        int r0 = m0 + warp_m + mi * 16 + g;
        int r1 = r0 + 8;
        #pragma unroll
        for (int ni = 0; ni < 8; ++ni) {
            int col = n0 + warp_n + ni * 8 + t4 * 2;
            float v0 = acc[mi][ni][0], v1 = acc[mi][ni][1];
            float v2 = acc[mi][ni][2], v3 = acc[mi][ni][3];
            if (epi == 1) {
                long long o0 = (long long)r0 * N + col;
                long long o1 = (long long)r1 * N + col;
                v0 += R[o0]; v1 += R[o0 + 1]; v2 += R[o1]; v3 += R[o1 + 1];
            }
            *(float2*)&C[(long long)r0 * N + col] = make_float2(v0, v1);
            *(float2*)&C[(long long)r1 * N + col] = make_float2(v2, v3);
        }
    }
}

// ---------------- bf16 mma GEMM (attention): C[M,N] f32 = A[M,K]*B[N,K]^T ----------------
// CTA 128x128, warp 64x32 (proven R5 structure).
// epi 0: plain  2: scores (scale+causal, skip masked blocks)
// bmode: GQA z->kv map for B.  klimit: causal K cut.
#define BSTAGE_BYTES 32768
#define BGEMM_SMEM (STAGES * BSTAGE_BYTES)

__global__ __launch_bounds__(256)
void gemm_bf16_kernel(const __nv_bfloat16* __restrict__ A, const __nv_bfloat16* __restrict__ B,
                      float* __restrict__ C,
                      int M, int N, int K,
                      long long bAel, long long bBel, long long bCel,
                      int bmode, int epi, float scale, int klimit)
{
    extern __shared__ char smch[];
    int tid = threadIdx.x;
    int z = blockIdx.z;
    int m0 = blockIdx.y * 128;
    int n0 = blockIdx.x * 128;
    if (epi == 2 && n0 > m0 + 127) return;

    const __nv_bfloat16* Ab = A + (long long)z * bAel;
    long long zb = bmode ? ((long long)(z >> 3) * 2 + ((z & 7) >> 2)) : (long long)z;
    const __nv_bfloat16* Bb = B + zb * bBel;
    float* Cb = C + (long long)z * bCel;

    uint32_t smu = smem_u32(smch);
    int Keff = klimit ? min(K, m0 + 128) : K;
    int ntiles = Keff / 64;                 // 64 bf16 per 128B k-tile

    int lr = tid >> 3;
    int lc = (tid & 7) * 16;

    auto issue = [&](int t, int slot) {
        uint32_t bA = smu + slot * BSTAGE_BYTES;
        uint32_t bB = bA + 16384;
        long long kofs = (long long)t * 128;   // bytes
        #pragma unroll
        for (int j = 0; j < 4; ++j) {
            int r = lr + j * 32;
            cp16(bA + SWZ(r * 128 + lc),
                 (const char*)(Ab + (long long)(m0 + r) * K) + kofs + lc);
        }
        #pragma unroll
        for (int j = 0; j < 4; ++j) {
            int r = lr + j * 32;
            cp16(bB + SWZ(r * 128 + lc),
                 (const char*)(Bb + (long long)(n0 + r) * K) + kofs + lc);
        }
        cp_commit();
    };

    int wid = tid >> 5, lane = tid & 31;
    int warp_m = (wid & 1) * 64;
    int warp_n = (wid >> 1) * 32;
    int blk = lane >> 3;
    int arow = (blk & 1) * 8 + (lane & 7);
    int achk = (blk >> 1) * 16;
    int brow = (blk >> 1) * 8 + (lane & 7);
    int bchk = (blk & 1) * 16;

    float acc[4][4][4];
    #pragma unroll
    for (int i = 0; i < 4; i++)
        #pragma unroll
        for (int j = 0; j < 4; j++)
            #pragma unroll
            for (int q = 0; q < 4; q++) acc[i][j][q] = 0.f;

    int pre = ntiles < (STAGES - 1) ? ntiles : (STAGES - 1);
    for (int s = 0; s < pre; ++s) issue(s, s);

    for (int t = 0; t < ntiles; ++t) {
        cp_wait<STAGES - 2>();
        __syncthreads();
        if (t + STAGES - 1 < ntiles) issue(t + STAGES - 1, (t + STAGES - 1) % STAGES);
        uint32_t bA = smu + (t % STAGES) * BSTAGE_BYTES;
        uint32_t bB = bA + 16384;
        #pragma unroll
        for (int kk = 0; kk < 4; ++kk) {
            uint32_t af[4][4], bf[4][2];
            #pragma unroll
            for (int mi = 0; mi < 4; ++mi) {
                int row = warp_m + mi * 16 + arow;
                ldm_x4(af[mi], bA + SWZ(row * 128 + kk * 32 + achk));
            }
            #pragma unroll
            for (int nh = 0; nh < 2; ++nh) {
                uint32_t q[4];
                int n = warp_n + nh * 16 + brow;
                ldm_x4(q, bB + SWZ(n * 128 + kk * 32 + bchk));
                bf[nh * 2 + 0][0] = q[0]; bf[nh * 2 + 0][1] = q[1];
                bf[nh * 2 + 1][0] = q[2]; bf[nh * 2 + 1][1] = q[3];
            }
            #pragma unroll
            for (int mi = 0; mi < 4; ++mi)
                #pragma unroll
                for (int ni = 0; ni < 4; ++ni)
                    mma_bf16(acc[mi][ni], af[mi], bf[ni]);
        }
        __syncthreads();
    }

    int g = lane >> 2, t4 = lane & 3;
    #pragma unroll
    for (int mi = 0; mi < 4; ++mi) {
        int r0 = m0 + warp_m + mi * 16 + g;
        int r1 = r0 + 8;
        #pragma unroll
        for (int ni = 0; ni < 4; ++ni) {
            int col = n0 + warp_n + ni * 8 + t4 * 2;
            float v0 = acc[mi][ni][0], v1 = acc[mi][ni][1];
            float v2 = acc[mi][ni][2], v3 = acc[mi][ni][3];
            if (epi == 2) {
                v0 *= scale; v1 *= scale; v2 *= scale; v3 *= scale;
                if (col     > r0) v0 = FMIN;
                if (col + 1 > r0) v1 = FMIN;
                if (col     > r1) v2 = FMIN;
                if (col + 1 > r1) v3 = FMIN;
            }
            *(float2*)&Cb[(long long)r0 * N + col] = make_float2(v0, v1);
            *(float2*)&Cb[(long long)r1 * N + col] = make_float2(v2, v3);
        }
    }
}

// ---------------- elementwise kernels ----------------
__global__ void rmsnorm_kernel(const float* __restrict__ in, const float* __restrict__ w,
                               float* __restrict__ out, int width,
                               long row_stride, long col_off) {
    long t = blockIdx.x;
    const float* x = in + t * width;
    float ss = 0.f;
    for (int i = threadIdx.x; i < width; i += 256) { float v = x[i]; ss = fmaf(v, v, ss); }
    float rms = rsqrtf(blk_sum(ss) / (float)width + 1e-6f);
    float* y = out + t * row_stride + col_off;
    for (int i = threadIdx.x; i < width; i += 256) y[i] = x[i] * rms * w[i];
}
__global__ void qpost_kernel(const float* __restrict__ qg, const float* __restrict__ qn_w,
                             __nv_bfloat16* __restrict__ qdst) {
    int t = blockIdx.x, h = blockIdx.y;
    int b = t / LL, l = t % LL;
    const float* src = qg + (long)t * 4096 + h * 512;
    int tid = threadIdx.x;
    float v = src[tid];
    float rms = rsqrtf(blk_sum(v * v) / (float)DD + 1e-6f);
    __shared__ float sq[DD];
    sq[tid] = v * rms * qn_w[tid];
    __syncthreads();
    if (tid < 32) {
        double inv = exp(-((double)(2 * tid) / 64.0) * log(1.0e7));
        double fr = (double)l * inv, c = cos(fr), s = sin(fr);
        float x0 = sq[2 * tid], x1 = sq[2 * tid + 1];
        sq[2 * tid]     = (float)((double)x0 * c - (double)x1 * s);
        sq[2 * tid + 1] = (float)((double)x0 * s + (double)x1 * c);
    }
    __syncthreads();
    long row = (long)(b * NQH + h) * LL + l;
    qdst[row * DD + tid] = __float2bfloat16(sq[tid]);
}
__global__ void kpost_kernel(const float* __restrict__ kbuf, const float* __restrict__ kn_w,
                             __nv_bfloat16* __restrict__ kdst) {
    int t = blockIdx.x, h = blockIdx.y;
    int b = t / LL, l = t % LL;
    const float* src = kbuf + (long)t * 512 + h * 256;
    int tid = threadIdx.x;
    float v = src[tid];
    float rms = rsqrtf(blk_sum(v * v) / (float)DD + 1e-6f);
    __shared__ float sq[DD];
    sq[tid] = v * rms * kn_w[tid];
    __syncthreads();
    if (tid < 32) {
        double inv = exp(-((double)(2 * tid) / 64.0) * log(1.0e7));
        double fr = (double)l * inv, c = cos(fr), s = sin(fr);
        float x0 = sq[2 * tid], x1 = sq[2 * tid + 1];
        sq[2 * tid]     = (float)((double)x0 * c - (double)x1 * s);
        sq[2 * tid + 1] = (float)((double)x0 * s + (double)x1 * c);
    }
    __syncthreads();
    long row = (long)(b * NKVH + h) * LL + l;
    kdst[row * DD + tid] = __float2bfloat16(sq[tid]);
}
__global__ void vpost_kernel(const float* __restrict__ vbuf, __nv_bfloat16* __restrict__ vt) {
    __shared__ float smv[32][33];
    int l0 = blockIdx.x * 32, d0 = blockIdx.y * 32, z = blockIdx.z;
    int b = z >> 1, h = z & 1;
    int tx = threadIdx.x & 31, ty = threadIdx.x >> 5;
    #pragma unroll
    for (int j = 0; j < 4; ++j) {
        int lloc = ty + j * 8;
        smv[lloc][tx] = vbuf[(long)(b * LL + l0 + lloc) * 512 + h * 256 + d0 + tx];
    }
    __syncthreads();
    #pragma unroll
    for (int j = 0; j < 4; ++j) {
        int dd = ty + j * 8;
        vt[(long)(z * DD + d0 + dd) * LL + l0 + tx] = __float2bfloat16(smv[tx][dd]);
    }
}
// causal-aware softmax: fp32 scores -> bf16 P, only written prefix
__global__ void softmax_kernel(const float* __restrict__ scores, __nv_bfloat16* __restrict__ p) {
    int q = blockIdx.x, z = blockIdx.y;
    const float* row = scores + ((long)z * LL + q) * LL;
    __nv_bfloat16* prow = p + ((long)z * LL + q) * LL;
    int nwrite = ((q >> 7) + 1) << 7;
    float vals[8], mx = -INFINITY;
    #pragma unroll
    for (int i = 0; i < 8; i++) {
        int col = threadIdx.x + i * 256;
        vals[i] = (col < nwrite) ? row[col] : -INFINITY;
        mx = fmaxf(mx, vals[i]);
    }
    mx = blk_max(mx);
    float sum = 0.f;
    #pragma unroll
    for (int i = 0; i < 8; i++) { vals[i] = __expf(vals[i] - mx); sum += vals[i]; }
    sum = blk_sum(sum);
    float invs = 1.f / sum;
    #pragma unroll
    for (int i = 0; i < 8; i++) {
        int col = threadIdx.x + i * 256;
        if (col < nwrite) prow[col] = __float2bfloat16(vals[i] * invs);
    }
}
__global__ void gather_gate_kernel(const float* __restrict__ attno, const float* __restrict__ qg,
                                   float* __restrict__ ao) {
    long i = (long)blockIdx.x * 256 + threadIdx.x;
    int t = (int)(i >> 11), c = (int)(i & 2047);
    int h = c >> 8, d = c & 255;
    int b = t / LL, l = t % LL;
    float o = attno[((long)(b * NQH + h) * LL + l) * DD + d];
    float gate = qg[(long)t * 4096 + h * 512 + 256 + d];
    ao[i] = o * (1.f / (1.f + expf(-gate)));
}
__global__ void silu_mul_kernel(const float* __restrict__ g, const float* __restrict__ u,
                                float* __restrict__ out, long n) {
    long i = (long)blockIdx.x * 256 + threadIdx.x;
    if (i < n) {
        float x = g[i];
        out[i] = x * (1.f / (1.f + expf(-x))) * u[i];
    }
}

// ---------------- launch ----------------
static void launch_tf32(const float* A, const float* B, float* C, const float* R,
                        int M, int N, int K, int epi) {
    dim3 grid(N / 256, M / 128, 1);
    gemm_tf32_kernel<<<grid, 256, GEMM_SMEM>>>(A, B, C, R, M, N, K, epi);
}
static void launch_bf16(const __nv_bfloat16* A, const __nv_bfloat16* B, float* C,
                        int M, int N, int K, long long bAel, long long bBel, long long bCel,
                        int nz, int bmode, int epi, float scale, int klimit) {
    dim3 grid(N / 128, M / 128, nz);
    gemm_bf16_kernel<<<grid, 256, BGEMM_SMEM>>>(A, B, C, M, N, K,
                                                bAel, bBel, bCel, bmode, epi, scale, klimit);
}

extern "C" void kernel_launch(void* const* d_in, const int* in_sizes, int n_in,
                              void* d_out, int out_size) {
    (void)in_sizes; (void)n_in; (void)out_size;
    const float* embeddings = (const float*)d_in[0];
    const float* hidden     = (const float*)d_in[1];
    const float* pre_emb_w  = (const float*)d_in[2];
    const float* pre_hid_w  = (const float*)d_in[3];
    const float* fc_w       = (const float*)d_in[4];
    const float* in_ln_w    = (const float*)d_in[5];
    const float* q_w        = (const float*)d_in[6];
    const float* k_w        = (const float*)d_in[7];
    const float* v_w        = (const float*)d_in[8];
    const float* o_w        = (const float*)d_in[9];
    const float* qn_w       = (const float*)d_in[10];
    const float* kn_w       = (const float*)d_in[11];
    const float* post_ln_w  = (const float*)d_in[12];
    const float* gate_w     = (const float*)d_in[13];
    const float* up_w       = (const float*)d_in[14];
    const float* down_w     = (const float*)d_in[15];
    const float* norm_w     = (const float*)d_in[16];
    const float* lm_w       = (const float*)d_in[17];
    float* out = (float*)d_out;

    static bool inited = false;
    static float *p_xcat, *p_x0, *p_xn, *p_qg, *p_kbuf, *p_vbuf, *p_scores, *p_attno,
                 *p_ao, *p_x1, *p_xn2, *p_gbuf, *p_ubuf, *p_gml, *p_x2, *p_xn3;
    static __nv_bfloat16 *ph_q, *ph_k, *ph_vt, *ph_p;
    if (!inited) {
        cudaGetSymbolAddress((void**)&p_xcat, g_xcat);  cudaGetSymbolAddress((void**)&p_x0, g_x0);
        cudaGetSymbolAddress((void**)&p_xn, g_xn);      cudaGetSymbolAddress((void**)&p_qg, g_qg);
        cudaGetSymbolAddress((void**)&p_kbuf, g_kbuf);  cudaGetSymbolAddress((void**)&p_vbuf, g_vbuf);
        cudaGetSymbolAddress((void**)&p_scores, g_scores); cudaGetSymbolAddress((void**)&p_attno, g_attno);
        cudaGetSymbolAddress((void**)&p_ao, g_ao);      cudaGetSymbolAddress((void**)&p_x1, g_x1);
        cudaGetSymbolAddress((void**)&p_xn2, g_xn2);    cudaGetSymbolAddress((void**)&p_gbuf, g_gbuf);
        cudaGetSymbolAddress((void**)&p_ubuf, g_ubuf);  cudaGetSymbolAddress((void**)&p_gml, g_gml);
        cudaGetSymbolAddress((void**)&p_x2, g_x2);      cudaGetSymbolAddress((void**)&p_xn3, g_xn3);
        cudaGetSymbolAddress((void**)&ph_q, h_q);       cudaGetSymbolAddress((void**)&ph_k, h_k);
        cudaGetSymbolAddress((void**)&ph_vt, h_vt);     cudaGetSymbolAddress((void**)&ph_p, h_p);
        cudaFuncSetAttribute(gemm_tf32_kernel, cudaFuncAttributeMaxDynamicSharedMemorySize, GEMM_SMEM);
        cudaFuncSetAttribute(gemm_bf16_kernel, cudaFuncAttributeMaxDynamicSharedMemorySize, BGEMM_SMEM);
        inited = true;
    }

    // 1. pre-norms + concat -> xcat
    rmsnorm_kernel<<<NTOK, 256>>>(embeddings, pre_emb_w, p_xcat, HH, 2048, 0);
    rmsnorm_kernel<<<NTOK, 256>>>(hidden,     pre_hid_w, p_xcat, HH, 2048, 1024);
    // 2. fc (raw fp32 weights, rounded in-GEMM)
    launch_tf32(p_xcat, fc_w, p_x0, nullptr, NTOK, HH, 2048, 0);
    // 3. in_ln
    rmsnorm_kernel<<<NTOK, 256>>>(p_x0, in_ln_w, p_xn, HH, 1024, 0);
    // 4. qkv
    launch_tf32(p_xn, q_w, p_qg,   nullptr, NTOK, 4096, HH, 0);
    launch_tf32(p_xn, k_w, p_kbuf, nullptr, NTOK, 512,  HH, 0);
    launch_tf32(p_xn, v_w, p_vbuf, nullptr, NTOK, 512,  HH, 0);
    // 5. head post -> bf16
    qpost_kernel<<<dim3(NTOK, NQH), 256>>>(p_qg, qn_w, ph_q);
    kpost_kernel<<<dim3(NTOK, NKVH), 256>>>(p_kbuf, kn_w, ph_k);
    vpost_kernel<<<dim3(LL / 32, DD / 32, BBATCH * NKVH), 256>>>(p_vbuf, ph_vt);
    // 6. scores = QK^T/16 causal (bf16, skip masked blocks)
    launch_bf16(ph_q, ph_k, p_scores, LL, LL, DD,
                (long long)LL * DD, (long long)LL * DD, (long long)LL * LL,
                BBATCH * NQH, 1, 2, 0.0625f, 0);
    // 7. softmax -> bf16 P
    softmax_kernel<<<dim3(LL, BBATCH * NQH), 256>>>(p_scores, ph_p);
    // 8. attno = P @ V^T (bf16, klimit causal)
    launch_bf16(ph_p, ph_vt, p_attno, LL, DD, LL,
                (long long)LL * LL, (long long)DD * LL, (long long)LL * DD,
                BBATCH * NQH, 1, 0, 1.f, 1);
    // 9. gate
    gather_gate_kernel<<<(NTOK * 2048) / 256, 256>>>(p_attno, p_qg, p_ao);
    // 10. o proj + residual
    launch_tf32(p_ao, o_w, p_x1, p_x0, NTOK, HH, 2048, 1);
    // 11. post_ln
    rmsnorm_kernel<<<NTOK, 256>>>(p_x1, post_ln_w, p_xn2, HH, 1024, 0);
    // 12. MLP
    launch_tf32(p_xn2, gate_w, p_gbuf, nullptr, NTOK, II, HH, 0);
    launch_tf32(p_xn2, up_w,   p_ubuf, nullptr, NTOK, II, HH, 0);
    silu_mul_kernel<<<((long)NTOK * II) / 256, 256>>>(p_gbuf, p_ubuf, p_gml, (long)NTOK * II);
    launch_tf32(p_gml, down_w, p_x2, p_x1, NTOK, HH, II, 1);
    // 15. final norm + lm head
    rmsnorm_kernel<<<NTOK, 256>>>(p_x2, norm_w, p_xn3, HH, 1024, 0);
    launch_tf32(p_xn3, lm_w, out, nullptr, NTOK, VV, HH, 0);
}

// round 10
// speedup vs baseline: 5.7515x; 1.8698x over previous
#include <cuda_runtime.h>
#include <cuda_bf16.h>
#include <cuda_fp16.h>
#include <math.h>
#include <stdint.h>

#define BBATCH 4
#define LL    2048
#define HH    1024
#define NQH   8
#define NKVH  2
#define DD    256
#define II    3584
#define VV    16384
#define NTOK  (BBATCH*LL)
#define FMIN  (-3.402823466e38f)

// fp32 scratch
__device__ __align__(256) float g_x0    [(size_t)NTOK * HH];
__device__ __align__(256) float g_qg    [(size_t)NTOK * 4096];
__device__ __align__(256) float g_kbuf  [(size_t)NTOK * 512];
__device__ __align__(256) float g_vbuf  [(size_t)NTOK * 512];
__device__ __align__(256) float g_scores[(size_t)BBATCH * NQH * LL * LL];
__device__ __align__(256) float g_attno [(size_t)BBATCH * NQH * LL * DD];
__device__ __align__(256) float g_gbuf  [(size_t)NTOK * II];
__device__ __align__(256) float g_ubuf  [(size_t)NTOK * II];
__device__ __align__(256) float g_x1    [(size_t)NTOK * HH];
__device__ __align__(256) float g_x2    [(size_t)NTOK * HH];
// fp16 GEMM activation inputs
__device__ __align__(256) __half a_xcat [(size_t)NTOK * 2048];
__device__ __align__(256) __half a_xn   [(size_t)NTOK * HH];
__device__ __align__(256) __half a_ao   [(size_t)NTOK * 2048];
__device__ __align__(256) __half a_xn2  [(size_t)NTOK * HH];
__device__ __align__(256) __half a_gml  [(size_t)NTOK * II];
__device__ __align__(256) __half a_xn3  [(size_t)NTOK * HH];
// fp16 weights
__device__ __align__(256) __half w_fc   [(size_t)HH * 2048];
__device__ __align__(256) __half w_q    [(size_t)4096 * HH];
__device__ __align__(256) __half w_k    [(size_t)512 * HH];
__device__ __align__(256) __half w_v    [(size_t)512 * HH];
__device__ __align__(256) __half w_o    [(size_t)HH * 2048];
__device__ __align__(256) __half w_gate [(size_t)II * HH];
__device__ __align__(256) __half w_up   [(size_t)II * HH];
__device__ __align__(256) __half w_down [(size_t)HH * II];
__device__ __align__(256) __half w_lm   [(size_t)VV * HH];
// bf16 attention buffers
__device__ __align__(256) __nv_bfloat16 h_q [(size_t)BBATCH * NQH * LL * DD];
__device__ __align__(256) __nv_bfloat16 h_k [(size_t)BBATCH * NKVH * LL * DD];
__device__ __align__(256) __nv_bfloat16 h_vt[(size_t)BBATCH * NKVH * DD * LL];
__device__ __align__(256) __nv_bfloat16 h_p [(size_t)BBATCH * NQH * LL * LL];

// ---------------- helpers ----------------
__device__ __forceinline__ uint32_t smem_u32(const void* p) {
    uint32_t a;
    asm("{ .reg .u64 t; cvta.to.shared.u64 t, %1; cvt.u32.u64 %0, t; }" : "=r"(a) : "l"(p));
    return a;
}
#define SWZ(o) ((o) ^ (((o) >> 3) & 0x70))

__device__ __forceinline__ void cp16(uint32_t dst, const void* src) {
    asm volatile("cp.async.cg.shared.global [%0], [%1], 16;" :: "r"(dst), "l"(src));
}
__device__ __forceinline__ void cp_commit() { asm volatile("cp.async.commit_group;"); }
template<int N> __device__ __forceinline__ void cp_wait() {
    asm volatile("cp.async.wait_group %0;" :: "n"(N));
}
__device__ __forceinline__ void ldm_x4(uint32_t* r, uint32_t addr) {
    asm volatile("ldmatrix.sync.aligned.m8n8.x4.shared.b16 {%0,%1,%2,%3}, [%4];"
                 : "=r"(r[0]), "=r"(r[1]), "=r"(r[2]), "=r"(r[3]) : "r"(addr));
}
__device__ __forceinline__ void mma_fp16(float* c, const uint32_t* a, const uint32_t* b) {
    asm volatile(
        "mma.sync.aligned.m16n8k16.row.col.f32.f16.f16.f32 "
        "{%0,%1,%2,%3},{%4,%5,%6,%7},{%8,%9},{%0,%1,%2,%3};"
        : "+f"(c[0]), "+f"(c[1]), "+f"(c[2]), "+f"(c[3])
        : "r"(a[0]), "r"(a[1]), "r"(a[2]), "r"(a[3]), "r"(b[0]), "r"(b[1]));
}
__device__ __forceinline__ void mma_bf16(float* c, const uint32_t* a, const uint32_t* b) {
    asm volatile(
        "mma.sync.aligned.m16n8k16.row.col.f32.bf16.bf16.f32 "
        "{%0,%1,%2,%3},{%4,%5,%6,%7},{%8,%9},{%0,%1,%2,%3};"
        : "+f"(c[0]), "+f"(c[1]), "+f"(c[2]), "+f"(c[3])
        : "r"(a[0]), "r"(a[1]), "r"(a[2]), "r"(a[3]), "r"(b[0]), "r"(b[1]));
}

// block reduce (256 thr)
__device__ __forceinline__ float blk_sum(float v) {
    __shared__ float sh[8]; __shared__ float res;
    #pragma unroll
    for (int o = 16; o; o >>= 1) v += __shfl_xor_sync(0xffffffffu, v, o);
    if ((threadIdx.x & 31) == 0) sh[threadIdx.x >> 5] = v;
    __syncthreads();
    if (threadIdx.x < 32) {
        float x = (threadIdx.x < 8) ? sh[threadIdx.x] : 0.f;
        #pragma unroll
        for (int o = 4; o; o >>= 1) x += __shfl_xor_sync(0xffffffffu, x, o);
        if (threadIdx.x == 0) res = x;
    }
    __syncthreads();
    return res;
}
__device__ __forceinline__ float blk_max(float v) {
    __shared__ float sh[8]; __shared__ float res;
    #pragma unroll
    for (int o = 16; o; o >>= 1) v = fmaxf(v, __shfl_xor_sync(0xffffffffu, v, o));
    if ((threadIdx.x & 31) == 0) sh[threadIdx.x >> 5] = v;
    __syncthreads();
    if (threadIdx.x < 32) {
        float x = (threadIdx.x < 8) ? sh[threadIdx.x] : -INFINITY;
        #pragma unroll
        for (int o = 4; o; o >>= 1) x = fmaxf(x, __shfl_xor_sync(0xffffffffu, x, o));
        if (threadIdx.x == 0) res = x;
    }
    __syncthreads();
    return res;
}

// ---------------- fp16 mma GEMM: C[M,N] f32 = A[M,K]*B[N,K]^T ----------------
// CTA 128x256, warp 64x64 (2x4 warps), ldmatrix fragments. epi 0: plain  1: +R
#define STAGES 3
#define FSTAGE_BYTES (16384 + 32768)
#define FGEMM_SMEM (STAGES * FSTAGE_BYTES)

__global__ __launch_bounds__(256)
void gemm_fp16_kernel(const __half* __restrict__ A, const __half* __restrict__ B,
                      float* __restrict__ C, const float* __restrict__ R,
                      int M, int N, int K, int epi)
{
    extern __shared__ char smch[];
    int tid = threadIdx.x;
    int m0 = blockIdx.y * 128;
    int n0 = blockIdx.x * 256;

    uint32_t smu = smem_u32(smch);
    int ntiles = K / 64;                 // 64 halves = 128B per k-tile row

    int lr = tid >> 3;
    int lc = (tid & 7) * 16;

    auto issue = [&](int t, int slot) {
        uint32_t bA = smu + slot * FSTAGE_BYTES;
        uint32_t bB = bA + 16384;
        long long kofs = (long long)t * 128;   // bytes
        #pragma unroll
        for (int j = 0; j < 4; ++j) {
            int r = lr + j * 32;
            cp16(bA + SWZ(r * 128 + lc),
                 (const char*)(A + (long long)(m0 + r) * K) + kofs + lc);
        }
        #pragma unroll
        for (int j = 0; j < 8; ++j) {
            int r = lr + j * 32;
            cp16(bB + SWZ(r * 128 + lc),
                 (const char*)(B + (long long)(n0 + r) * K) + kofs + lc);
        }
        cp_commit();
    };

    int wid = tid >> 5, lane = tid & 31;
    int warp_m = (wid & 1) * 64;
    int warp_n = (wid >> 1) * 64;
    int blk = lane >> 3;
    int arow = (blk & 1) * 8 + (lane & 7);
    int achk = (blk >> 1) * 16;
    int brow = (blk >> 1) * 8 + (lane & 7);
    int bchk = (blk & 1) * 16;

    float acc[4][8][4];
    #pragma unroll
    for (int i = 0; i < 4; i++)
        #pragma unroll
        for (int j = 0; j < 8; j++)
            #pragma unroll
            for (int q = 0; q < 4; q++) acc[i][j][q] = 0.f;

    int pre = ntiles < (STAGES - 1) ? ntiles : (STAGES - 1);
    for (int s = 0; s < pre; ++s) issue(s, s);

    for (int t = 0; t < ntiles; ++t) {
        cp_wait<STAGES - 2>();
        __syncthreads();
        if (t + STAGES - 1 < ntiles) issue(t + STAGES - 1, (t + STAGES - 1) % STAGES);
        uint32_t bA = smu + (t % STAGES) * FSTAGE_BYTES;
        uint32_t bB = bA + 16384;
        #pragma unroll
        for (int kk = 0; kk < 4; ++kk) {
            uint32_t af[4][4], bf[8][2];
            #pragma unroll
            for (int mi = 0; mi < 4; ++mi) {
                int row = warp_m + mi * 16 + arow;
                ldm_x4(af[mi], bA + SWZ(row * 128 + kk * 32 + achk));
            }
            #pragma unroll
            for (int nh = 0; nh < 4; ++nh) {
                uint32_t q[4];
                int n = warp_n + nh * 16 + brow;
                ldm_x4(q, bB + SWZ(n * 128 + kk * 32 + bchk));
                bf[nh * 2 + 0][0] = q[0]; bf[nh * 2 + 0][1] = q[1];
                bf[nh * 2 + 1][0] = q[2]; bf[nh * 2 + 1][1] = q[3];
            }
            #pragma unroll
            for (int mi = 0; mi < 4; ++mi)
                #pragma unroll
                for (int ni = 0; ni < 8; ++ni)
                    mma_fp16(acc[mi][ni], af[mi], bf[ni]);
        }
        __syncthreads();
    }

    int g = lane >> 2, t4 = lane & 3;
    #pragma unroll
    for (int mi = 0; mi < 4; ++mi) {
        int r0 = m0 + warp_m + mi * 16 + g;
        int r1 = r0 + 8;
        #pragma unroll
        for (int ni = 0; ni < 8; ++ni) {
            int col = n0 + warp_n + ni * 8 + t4 * 2;
            float v0 = acc[mi][ni][0], v1 = acc[mi][ni][1];
            float v2 = acc[mi][ni][2], v3 = acc[mi][ni][3];
            if (epi == 1) {
                long long o0 = (long long)r0 * N + col;
                long long o1 = (long long)r1 * N + col;
                v0 += R[o0]; v1 += R[o0 + 1]; v2 += R[o1]; v3 += R[o1 + 1];
            }
            *(float2*)&C[(long long)r0 * N + col] = make_float2(v0, v1);
            *(float2*)&C[(long long)r1 * N + col] = make_float2(v2, v3);
        }
    }
}

// ---------------- bf16 mma GEMM (attention, proven): CTA 128x128, warp 64x32 ----------------
#define BSTAGE_BYTES 32768
#define BGEMM_SMEM (STAGES * BSTAGE_BYTES)

__global__ __launch_bounds__(256)
void gemm_bf16_kernel(const __nv_bfloat16* __restrict__ A, const __nv_bfloat16* __restrict__ B,
                      float* __restrict__ C,
                      int M, int N, int K,
                      long long bAel, long long bBel, long long bCel,
                      int bmode, int epi, float scale, int klimit)
{
    extern __shared__ char smch[];
    int tid = threadIdx.x;
    int z = blockIdx.z;
    int m0 = blockIdx.y * 128;
    int n0 = blockIdx.x * 128;
    if (epi == 2 && n0 > m0 + 127) return;

    const __nv_bfloat16* Ab = A + (long long)z * bAel;
    long long zb = bmode ? ((long long)(z >> 3) * 2 + ((z & 7) >> 2)) : (long long)z;
    const __nv_bfloat16* Bb = B + zb * bBel;
    float* Cb = C + (long long)z * bCel;

    uint32_t smu = smem_u32(smch);
    int Keff = klimit ? min(K, m0 + 128) : K;
    int ntiles = Keff / 64;

    int lr = tid >> 3;
    int lc = (tid & 7) * 16;

    auto issue = [&](int t, int slot) {
        uint32_t bA = smu + slot * BSTAGE_BYTES;
        uint32_t bB = bA + 16384;
        long long kofs = (long long)t * 128;
        #pragma unroll
        for (int j = 0; j < 4; ++j) {
            int r = lr + j * 32;
            cp16(bA + SWZ(r * 128 + lc),
                 (const char*)(Ab + (long long)(m0 + r) * K) + kofs + lc);
        }
        #pragma unroll
        for (int j = 0; j < 4; ++j) {
            int r = lr + j * 32;
            cp16(bB + SWZ(r * 128 + lc),
                 (const char*)(Bb + (long long)(n0 + r) * K) + kofs + lc);
        }
        cp_commit();
    };

    int wid = tid >> 5, lane = tid & 31;
    int warp_m = (wid & 1) * 64;
    int warp_n = (wid >> 1) * 32;
    int blk = lane >> 3;
    int arow = (blk & 1) * 8 + (lane & 7);
    int achk = (blk >> 1) * 16;
    int brow = (blk >> 1) * 8 + (lane & 7);
    int bchk = (blk & 1) * 16;

    float acc[4][4][4];
    #pragma unroll
    for (int i = 0; i < 4; i++)
        #pragma unroll
        for (int j = 0; j < 4; j++)
            #pragma unroll
            for (int q = 0; q < 4; q++) acc[i][j][q] = 0.f;

    int pre = ntiles < (STAGES - 1) ? ntiles : (STAGES - 1);
    for (int s = 0; s < pre; ++s) issue(s, s);

    for (int t = 0; t < ntiles; ++t) {
        cp_wait<STAGES - 2>();
        __syncthreads();
        if (t + STAGES - 1 < ntiles) issue(t + STAGES - 1, (t + STAGES - 1) % STAGES);
        uint32_t bA = smu + (t % STAGES) * BSTAGE_BYTES;
        uint32_t bB = bA + 16384;
        #pragma unroll
        for (int kk = 0; kk < 4; ++kk) {
            uint32_t af[4][4], bf[4][2];
            #pragma unroll
            for (int mi = 0; mi < 4; ++mi) {
                int row = warp_m + mi * 16 + arow;
                ldm_x4(af[mi], bA + SWZ(row * 128 + kk * 32 + achk));
            }
            #pragma unroll
            for (int nh = 0; nh < 2; ++nh) {
                uint32_t q[4];
                int n = warp_n + nh * 16 + brow;
                ldm_x4(q, bB + SWZ(n * 128 + kk * 32 + bchk));
                bf[nh * 2 + 0][0] = q[0]; bf[nh * 2 + 0][1] = q[1];
                bf[nh * 2 + 1][0] = q[2]; bf[nh * 2 + 1][1] = q[3];
            }
            #pragma unroll
            for (int mi = 0; mi < 4; ++mi)
                #pragma unroll
                for (int ni = 0; ni < 4; ++ni)
                    mma_bf16(acc[mi][ni], af[mi], bf[ni]);
        }
        __syncthreads();
    }

    int g = lane >> 2, t4 = lane & 3;
    #pragma unroll
    for (int mi = 0; mi < 4; ++mi) {
        int r0 = m0 + warp_m + mi * 16 + g;
        int r1 = r0 + 8;
        #pragma unroll
        for (int ni = 0; ni < 4; ++ni) {
            int col = n0 + warp_n + ni * 8 + t4 * 2;
            float v0 = acc[mi][ni][0], v1 = acc[mi][ni][1];
            float v2 = acc[mi][ni][2], v3 = acc[mi][ni][3];
            if (epi == 2) {
                v0 *= scale; v1 *= scale; v2 *= scale; v3 *= scale;
                if (col     > r0) v0 = FMIN;
                if (col + 1 > r0) v1 = FMIN;
                if (col     > r1) v2 = FMIN;
                if (col + 1 > r1) v3 = FMIN;
            }
            *(float2*)&Cb[(long long)r0 * N + col] = make_float2(v0, v1);
            *(float2*)&Cb[(long long)r1 * N + col] = make_float2(v2, v3);
        }
    }
}

// ---------------- elementwise kernels ----------------
__global__ void convert_fp16_kernel(const float* __restrict__ in, __half* __restrict__ out, long n) {
    long i = (long)blockIdx.x * 256 + threadIdx.x;
    if (i < n) out[i] = __float2half(in[i]);
}
__global__ void rmsnorm_h_kernel(const float* __restrict__ in, const float* __restrict__ w,
                                 __half* __restrict__ out, int width,
                                 long row_stride, long col_off) {
    long t = blockIdx.x;
    const float* x = in + t * width;
    float ss = 0.f;
    for (int i = threadIdx.x; i < width; i += 256) { float v = x[i]; ss = fmaf(v, v, ss); }
    float rms = rsqrtf(blk_sum(ss) / (float)width + 1e-6f);
    __half* y = out + t * row_stride + col_off;
    for (int i = threadIdx.x; i < width; i += 256) y[i] = __float2half(x[i] * rms * w[i]);
}
__global__ void qpost_kernel(const float* __restrict__ qg, const float* __restrict__ qn_w,
                             __nv_bfloat16* __restrict__ qdst) {
    int t = blockIdx.x, h = blockIdx.y;
    int b = t / LL, l = t % LL;
    const float* src = qg + (long)t * 4096 + h * 512;
    int tid = threadIdx.x;
    float v = src[tid];
    float rms = rsqrtf(blk_sum(v * v) / (float)DD + 1e-6f);
    __shared__ float sq[DD];
    sq[tid] = v * rms * qn_w[tid];
    __syncthreads();
    if (tid < 32) {
        double inv = exp(-((double)(2 * tid) / 64.0) * log(1.0e7));
        double fr = (double)l * inv, c = cos(fr), s = sin(fr);
        float x0 = sq[2 * tid], x1 = sq[2 * tid + 1];
        sq[2 * tid]     = (float)((double)x0 * c - (double)x1 * s);
        sq[2 * tid + 1] = (float)((double)x0 * s + (double)x1 * c);
    }
    __syncthreads();
    long row = (long)(b * NQH + h) * LL + l;
    qdst[row * DD + tid] = __float2bfloat16(sq[tid]);
}
__global__ void kpost_kernel(const float* __restrict__ kbuf, const float* __restrict__ kn_w,
                             __nv_bfloat16* __restrict__ kdst) {
    int t = blockIdx.x, h = blockIdx.y;
    int b = t / LL, l = t % LL;
    const float* src = kbuf + (long)t * 512 + h * 256;
    int tid = threadIdx.x;
    float v = src[tid];
    float rms = rsqrtf(blk_sum(v * v) / (float)DD + 1e-6f);
    __shared__ float sq[DD];
    sq[tid] = v * rms * kn_w[tid];
    __syncthreads();
    if (tid < 32) {
        double inv = exp(-((double)(2 * tid) / 64.0) * log(1.0e7));
        double fr = (double)l * inv, c = cos(fr), s = sin(fr);
        float x0 = sq[2 * tid], x1 = sq[2 * tid + 1];
        sq[2 * tid]     = (float)((double)x0 * c - (double)x1 * s);
        sq[2 * tid + 1] = (float)((double)x0 * s + (double)x1 * c);
    }
    __syncthreads();
    long row = (long)(b * NKVH + h) * LL + l;
    kdst[row * DD + tid] = __float2bfloat16(sq[tid]);
}
__global__ void vpost_kernel(const float* __restrict__ vbuf, __nv_bfloat16* __restrict__ vt) {
    __shared__ float smv[32][33];
    int l0 = blockIdx.x * 32, d0 = blockIdx.y * 32, z = blockIdx.z;
    int b = z >> 1, h = z & 1;
    int tx = threadIdx.x & 31, ty = threadIdx.x >> 5;
    #pragma unroll
    for (int j = 0; j < 4; ++j) {
        int lloc = ty + j * 8;
        smv[lloc][tx] = vbuf[(long)(b * LL + l0 + lloc) * 512 + h * 256 + d0 + tx];
    }
    __syncthreads();
    #pragma unroll
    for (int j = 0; j < 4; ++j) {
        int dd = ty + j * 8;
        vt[(long)(z * DD + d0 + dd) * LL + l0 + tx] = __float2bfloat16(smv[tx][dd]);
    }
}
__global__ void softmax_kernel(const float* __restrict__ scores, __nv_bfloat16* __restrict__ p) {
    int q = blockIdx.x, z = blockIdx.y;
    const float* row = scores + ((long)z * LL + q) * LL;
    __nv_bfloat16* prow = p + ((long)z * LL + q) * LL;
    int nwrite = ((q >> 7) + 1) << 7;
    float vals[8], mx = -INFINITY;
    #pragma unroll
    for (int i = 0; i < 8; i++) {
        int col = threadIdx.x + i * 256;
        vals[i] = (col < nwrite) ? row[col] : -INFINITY;
        mx = fmaxf(mx, vals[i]);
    }
    mx = blk_max(mx);
    float sum = 0.f;
    #pragma unroll
    for (int i = 0; i < 8; i++) { vals[i] = __expf(vals[i] - mx); sum += vals[i]; }
    sum = blk_sum(sum);
    float invs = 1.f / sum;
    #pragma unroll
    for (int i = 0; i < 8; i++) {
        int col = threadIdx.x + i * 256;
        if (col < nwrite) prow[col] = __float2bfloat16(vals[i] * invs);
    }
}
__global__ void gather_gate_kernel(const float* __restrict__ attno, const float* __restrict__ qg,
                                   __half* __restrict__ ao) {
    long i = (long)blockIdx.x * 256 + threadIdx.x;
    int t = (int)(i >> 11), c = (int)(i & 2047);
    int h = c >> 8, d = c & 255;
    int b = t / LL, l = t % LL;
    float o = attno[((long)(b * NQH + h) * LL + l) * DD + d];
    float gate = qg[(long)t * 4096 + h * 512 + 256 + d];
    ao[i] = __float2half(o * (1.f / (1.f + expf(-gate))));
}
__global__ void silu_mul_kernel(const float* __restrict__ g, const float* __restrict__ u,
                                __half* __restrict__ out, long n) {
    long i = (long)blockIdx.x * 256 + threadIdx.x;
    if (i < n) {
        float x = g[i];
        out[i] = __float2half(x * (1.f / (1.f + expf(-x))) * u[i]);
    }
}

// ---------------- launch ----------------
static void launch_fp16(const __half* A, const __half* B, float* C, const float* R,
                        int M, int N, int K, int epi) {
    dim3 grid(N / 256, M / 128, 1);
    gemm_fp16_kernel<<<grid, 256, FGEMM_SMEM>>>(A, B, C, R, M, N, K, epi);
}
static void launch_bf16(const __nv_bfloat16* A, const __nv_bfloat16* B, float* C,
                        int M, int N, int K, long long bAel, long long bBel, long long bCel,
                        int nz, int bmode, int epi, float scale, int klimit) {
    dim3 grid(N / 128, M / 128, nz);
    gemm_bf16_kernel<<<grid, 256, BGEMM_SMEM>>>(A, B, C, M, N, K,
                                                bAel, bBel, bCel, bmode, epi, scale, klimit);
}

extern "C" void kernel_launch(void* const* d_in, const int* in_sizes, int n_in,
                              void* d_out, int out_size) {
    (void)in_sizes; (void)n_in; (void)out_size;
    const float* embeddings = (const float*)d_in[0];
    const float* hidden     = (const float*)d_in[1];
    const float* pre_emb_w  = (const float*)d_in[2];
    const float* pre_hid_w  = (const float*)d_in[3];
    const float* fc_w       = (const float*)d_in[4];
    const float* in_ln_w    = (const float*)d_in[5];
    const float* q_w        = (const float*)d_in[6];
    const float* k_w        = (const float*)d_in[7];
    const float* v_w        = (const float*)d_in[8];
    const float* o_w        = (const float*)d_in[9];
    const float* qn_w       = (const float*)d_in[10];
    const float* kn_w       = (const float*)d_in[11];
    const float* post_ln_w  = (const float*)d_in[12];
    const float* gate_w     = (const float*)d_in[13];
    const float* up_w       = (const float*)d_in[14];
    const float* down_w     = (const float*)d_in[15];
    const float* norm_w     = (const float*)d_in[16];
    const float* lm_w       = (const float*)d_in[17];
    float* out = (float*)d_out;

    static bool inited = false;
    static float *p_x0, *p_qg, *p_kbuf, *p_vbuf, *p_scores, *p_attno, *p_gbuf, *p_ubuf, *p_x1, *p_x2;
    static __half *pa_xcat, *pa_xn, *pa_ao, *pa_xn2, *pa_gml, *pa_xn3;
    static __half *pw_fc, *pw_q, *pw_k, *pw_v, *pw_o, *pw_gate, *pw_up, *pw_down, *pw_lm;
    static __nv_bfloat16 *ph_q, *ph_k, *ph_vt, *ph_p;
    if (!inited) {
        cudaGetSymbolAddress((void**)&p_x0, g_x0);      cudaGetSymbolAddress((void**)&p_qg, g_qg);
        cudaGetSymbolAddress((void**)&p_kbuf, g_kbuf);  cudaGetSymbolAddress((void**)&p_vbuf, g_vbuf);
        cudaGetSymbolAddress((void**)&p_scores, g_scores); cudaGetSymbolAddress((void**)&p_attno, g_attno);
        cudaGetSymbolAddress((void**)&p_gbuf, g_gbuf);  cudaGetSymbolAddress((void**)&p_ubuf, g_ubuf);
        cudaGetSymbolAddress((void**)&p_x1, g_x1);      cudaGetSymbolAddress((void**)&p_x2, g_x2);
        cudaGetSymbolAddress((void**)&pa_xcat, a_xcat); cudaGetSymbolAddress((void**)&pa_xn, a_xn);
        cudaGetSymbolAddress((void**)&pa_ao, a_ao);     cudaGetSymbolAddress((void**)&pa_xn2, a_xn2);
        cudaGetSymbolAddress((void**)&pa_gml, a_gml);   cudaGetSymbolAddress((void**)&pa_xn3, a_xn3);
        cudaGetSymbolAddress((void**)&pw_fc, w_fc);     cudaGetSymbolAddress((void**)&pw_q, w_q);
        cudaGetSymbolAddress((void**)&pw_k, w_k);       cudaGetSymbolAddress((void**)&pw_v, w_v);
        cudaGetSymbolAddress((void**)&pw_o, w_o);       cudaGetSymbolAddress((void**)&pw_gate, w_gate);
        cudaGetSymbolAddress((void**)&pw_up, w_up);     cudaGetSymbolAddress((void**)&pw_down, w_down);
        cudaGetSymbolAddress((void**)&pw_lm, w_lm);
        cudaGetSymbolAddress((void**)&ph_q, h_q);       cudaGetSymbolAddress((void**)&ph_k, h_k);
        cudaGetSymbolAddress((void**)&ph_vt, h_vt);     cudaGetSymbolAddress((void**)&ph_p, h_p);
        cudaFuncSetAttribute(gemm_fp16_kernel, cudaFuncAttributeMaxDynamicSharedMemorySize, FGEMM_SMEM);
        cudaFuncSetAttribute(gemm_bf16_kernel, cudaFuncAttributeMaxDynamicSharedMemorySize, BGEMM_SMEM);
        inited = true;
    }

    // weights -> fp16
    long n;
    n = (long)HH * 2048;  convert_fp16_kernel<<<(n + 255) / 256, 256>>>(fc_w,   pw_fc,   n);
    n = (long)4096 * HH;  convert_fp16_kernel<<<(n + 255) / 256, 256>>>(q_w,    pw_q,    n);
    n = (long)512 * HH;   convert_fp16_kernel<<<(n + 255) / 256, 256>>>(k_w,    pw_k,    n);
    n = (long)512 * HH;   convert_fp16_kernel<<<(n + 255) / 256, 256>>>(v_w,    pw_v,    n);
    n = (long)HH * 2048;  convert_fp16_kernel<<<(n + 255) / 256, 256>>>(o_w,    pw_o,    n);
    n = (long)II * HH;    convert_fp16_kernel<<<(n + 255) / 256, 256>>>(gate_w, pw_gate, n);
    n = (long)II * HH;    convert_fp16_kernel<<<(n + 255) / 256, 256>>>(up_w,   pw_up,   n);
    n = (long)HH * II;    convert_fp16_kernel<<<(n + 255) / 256, 256>>>(down_w, pw_down, n);
    n = (long)VV * HH;    convert_fp16_kernel<<<(n + 255) / 256, 256>>>(lm_w,   pw_lm,   n);

    // 1. pre-norms + concat -> fp16 xcat
    rmsnorm_h_kernel<<<NTOK, 256>>>(embeddings, pre_emb_w, pa_xcat, HH, 2048, 0);
    rmsnorm_h_kernel<<<NTOK, 256>>>(hidden,     pre_hid_w, pa_xcat, HH, 2048, 1024);
    // 2. fc
    launch_fp16(pa_xcat, pw_fc, p_x0, nullptr, NTOK, HH, 2048, 0);
    // 3. in_ln
    rmsnorm_h_kernel<<<NTOK, 256>>>(p_x0, in_ln_w, pa_xn, HH, 1024, 0);
    // 4. qkv
    launch_fp16(pa_xn, pw_q, p_qg,   nullptr, NTOK, 4096, HH, 0);
    launch_fp16(pa_xn, pw_k, p_kbuf, nullptr, NTOK, 512,  HH, 0);
    launch_fp16(pa_xn, pw_v, p_vbuf, nullptr, NTOK, 512,  HH, 0);
    // 5. head post -> bf16
    qpost_kernel<<<dim3(NTOK, NQH), 256>>>(p_qg, qn_w, ph_q);
    kpost_kernel<<<dim3(NTOK, NKVH), 256>>>(p_kbuf, kn_w, ph_k);
    vpost_kernel<<<dim3(LL / 32, DD / 32, BBATCH * NKVH), 256>>>(p_vbuf, ph_vt);
    // 6. scores = QK^T/16 causal (bf16, skip masked blocks)
    launch_bf16(ph_q, ph_k, p_scores, LL, LL, DD,
                (long long)LL * DD, (long long)LL * DD, (long long)LL * LL,
                BBATCH * NQH, 1, 2, 0.0625f, 0);
    // 7. softmax -> bf16 P
    softmax_kernel<<<dim3(LL, BBATCH * NQH), 256>>>(p_scores, ph_p);
    // 8. attno = P @ V^T (bf16, klimit causal)
    launch_bf16(ph_p, ph_vt, p_attno, LL, DD, LL,
                (long long)LL * LL, (long long)DD * LL, (long long)LL * DD,
                BBATCH * NQH, 1, 0, 1.f, 1);
    // 9. gate -> fp16 ao
    gather_gate_kernel<<<(NTOK * 2048) / 256, 256>>>(p_attno, p_qg, pa_ao);
    // 10. o proj + residual
    launch_fp16(pa_ao, pw_o, p_x1, p_x0, NTOK, HH, 2048, 1);
    // 11. post_ln
    rmsnorm_h_kernel<<<NTOK, 256>>>(p_x1, post_ln_w, pa_xn2, HH, 1024, 0);
    // 12. MLP
    launch_fp16(pa_xn2, pw_gate, p_gbuf, nullptr, NTOK, II, HH, 0);
    launch_fp16(pa_xn2, pw_up,   p_ubuf, nullptr, NTOK, II, HH, 0);
    silu_mul_kernel<<<((long)NTOK * II) / 256, 256>>>(p_gbuf, p_ubuf, pa_gml, (long)NTOK * II);
    launch_fp16(pa_gml, pw_down, p_x2, p_x1, NTOK, HH, II, 1);
    // 15. final norm + lm head
    rmsnorm_h_kernel<<<NTOK, 256>>>(p_x2, norm_w, pa_xn3, HH, 1024, 0);
    launch_fp16(pa_xn3, pw_lm, out, nullptr, NTOK, VV, HH, 0);
}

// round 11
// speedup vs baseline: 5.9758x; 1.0390x over previous
#include <cuda_runtime.h>
#include <cuda_bf16.h>
#include <cuda_fp16.h>
#include <math.h>
#include <stdint.h>

#define BBATCH 4
#define LL    2048
#define HH    1024
#define NQH   8
#define NKVH  2
#define DD    256
#define II    3584
#define VV    16384
#define NTOK  (BBATCH*LL)
#define FMIN  (-3.402823466e38f)
#define NQKV  5120          // 4096 q+gate | 512 k | 512 v
#define NGU   7168          // 3584 gate | 3584 up

// fp32 scratch
__device__ __align__(256) float g_x0    [(size_t)NTOK * HH];
__device__ __align__(256) float g_qkv   [(size_t)NTOK * NQKV];
__device__ __align__(256) float g_scores[(size_t)BBATCH * NQH * LL * LL];
__device__ __align__(256) float g_gu    [(size_t)NTOK * NGU];
__device__ __align__(256) float g_x1    [(size_t)NTOK * HH];
__device__ __align__(256) float g_x2    [(size_t)NTOK * HH];
// fp16 GEMM activation inputs
__device__ __align__(256) __half a_xcat [(size_t)NTOK * 2048];
__device__ __align__(256) __half a_xn   [(size_t)NTOK * HH];
__device__ __align__(256) __half a_ao   [(size_t)NTOK * 2048];
__device__ __align__(256) __half a_xn2  [(size_t)NTOK * HH];
__device__ __align__(256) __half a_gml  [(size_t)NTOK * II];
__device__ __align__(256) __half a_xn3  [(size_t)NTOK * HH];
// fp16 weights (qkv and gate/up packed)
__device__ __align__(256) __half w_fc   [(size_t)HH * 2048];
__device__ __align__(256) __half w_qkv  [(size_t)NQKV * HH];
__device__ __align__(256) __half w_o    [(size_t)HH * 2048];
__device__ __align__(256) __half w_gu   [(size_t)NGU * HH];
__device__ __align__(256) __half w_down [(size_t)HH * II];
__device__ __align__(256) __half w_lm   [(size_t)VV * HH];
// bf16 attention buffers
__device__ __align__(256) __nv_bfloat16 h_q [(size_t)BBATCH * NQH * LL * DD];
__device__ __align__(256) __nv_bfloat16 h_k [(size_t)BBATCH * NKVH * LL * DD];
__device__ __align__(256) __nv_bfloat16 h_vt[(size_t)BBATCH * NKVH * DD * LL];
__device__ __align__(256) __nv_bfloat16 h_p [(size_t)BBATCH * NQH * LL * LL];

// ---------------- helpers ----------------
__device__ __forceinline__ uint32_t smem_u32(const void* p) {
    uint32_t a;
    asm("{ .reg .u64 t; cvta.to.shared.u64 t, %1; cvt.u32.u64 %0, t; }" : "=r"(a) : "l"(p));
    return a;
}
#define SWZ(o) ((o) ^ (((o) >> 3) & 0x70))

__device__ __forceinline__ void cp16(uint32_t dst, const void* src) {
    asm volatile("cp.async.cg.shared.global [%0], [%1], 16;" :: "r"(dst), "l"(src));
}
__device__ __forceinline__ void cp_commit() { asm volatile("cp.async.commit_group;"); }
template<int N> __device__ __forceinline__ void cp_wait() {
    asm volatile("cp.async.wait_group %0;" :: "n"(N));
}
__device__ __forceinline__ void ldm_x4(uint32_t* r, uint32_t addr) {
    asm volatile("ldmatrix.sync.aligned.m8n8.x4.shared.b16 {%0,%1,%2,%3}, [%4];"
                 : "=r"(r[0]), "=r"(r[1]), "=r"(r[2]), "=r"(r[3]) : "r"(addr));
}
__device__ __forceinline__ void mma_fp16(float* c, const uint32_t* a, const uint32_t* b) {
    asm volatile(
        "mma.sync.aligned.m16n8k16.row.col.f32.f16.f16.f32 "
        "{%0,%1,%2,%3},{%4,%5,%6,%7},{%8,%9},{%0,%1,%2,%3};"
        : "+f"(c[0]), "+f"(c[1]), "+f"(c[2]), "+f"(c[3])
        : "r"(a[0]), "r"(a[1]), "r"(a[2]), "r"(a[3]), "r"(b[0]), "r"(b[1]));
}
__device__ __forceinline__ void mma_bf16(float* c, const uint32_t* a, const uint32_t* b) {
    asm volatile(
        "mma.sync.aligned.m16n8k16.row.col.f32.bf16.bf16.f32 "
        "{%0,%1,%2,%3},{%4,%5,%6,%7},{%8,%9},{%0,%1,%2,%3};"
        : "+f"(c[0]), "+f"(c[1]), "+f"(c[2]), "+f"(c[3])
        : "r"(a[0]), "r"(a[1]), "r"(a[2]), "r"(a[3]), "r"(b[0]), "r"(b[1]));
}

// block reduce (256 thr)
__device__ __forceinline__ float blk_sum(float v) {
    __shared__ float sh[8]; __shared__ float res;
    #pragma unroll
    for (int o = 16; o; o >>= 1) v += __shfl_xor_sync(0xffffffffu, v, o);
    if ((threadIdx.x & 31) == 0) sh[threadIdx.x >> 5] = v;
    __syncthreads();
    if (threadIdx.x < 32) {
        float x = (threadIdx.x < 8) ? sh[threadIdx.x] : 0.f;
        #pragma unroll
        for (int o = 4; o; o >>= 1) x += __shfl_xor_sync(0xffffffffu, x, o);
        if (threadIdx.x == 0) res = x;
    }
    __syncthreads();
    return res;
}
__device__ __forceinline__ float blk_max(float v) {
    __shared__ float sh[8]; __shared__ float res;
    #pragma unroll
    for (int o = 16; o; o >>= 1) v = fmaxf(v, __shfl_xor_sync(0xffffffffu, v, o));
    if ((threadIdx.x & 31) == 0) sh[threadIdx.x >> 5] = v;
    __syncthreads();
    if (threadIdx.x < 32) {
        float x = (threadIdx.x < 8) ? sh[threadIdx.x] : -INFINITY;
        #pragma unroll
        for (int o = 4; o; o >>= 1) x = fmaxf(x, __shfl_xor_sync(0xffffffffu, x, o));
        if (threadIdx.x == 0) res = x;
    }
    __syncthreads();
    return res;
}

// ---------------- fp16 mma GEMM: C[M,N] f32 = A[M,K]*B[N,K]^T ----------------
// CTA 128x256, warp 64x64. epi 0: plain  1: +R
#define STAGES 3
#define FSTAGE_BYTES (16384 + 32768)
#define FGEMM_SMEM (STAGES * FSTAGE_BYTES)

__global__ __launch_bounds__(256)
void gemm_fp16_kernel(const __half* __restrict__ A, const __half* __restrict__ B,
                      float* __restrict__ C, const float* __restrict__ R,
                      int M, int N, int K, int epi)
{
    extern __shared__ char smch[];
    int tid = threadIdx.x;
    int m0 = blockIdx.y * 128;
    int n0 = blockIdx.x * 256;

    uint32_t smu = smem_u32(smch);
    int ntiles = K / 64;

    int lr = tid >> 3;
    int lc = (tid & 7) * 16;

    auto issue = [&](int t, int slot) {
        uint32_t bA = smu + slot * FSTAGE_BYTES;
        uint32_t bB = bA + 16384;
        long long kofs = (long long)t * 128;
        #pragma unroll
        for (int j = 0; j < 4; ++j) {
            int r = lr + j * 32;
            cp16(bA + SWZ(r * 128 + lc),
                 (const char*)(A + (long long)(m0 + r) * K) + kofs + lc);
        }
        #pragma unroll
        for (int j = 0; j < 8; ++j) {
            int r = lr + j * 32;
            cp16(bB + SWZ(r * 128 + lc),
                 (const char*)(B + (long long)(n0 + r) * K) + kofs + lc);
        }
        cp_commit();
    };

    int wid = tid >> 5, lane = tid & 31;
    int warp_m = (wid & 1) * 64;
    int warp_n = (wid >> 1) * 64;
    int blk = lane >> 3;
    int arow = (blk & 1) * 8 + (lane & 7);
    int achk = (blk >> 1) * 16;
    int brow = (blk >> 1) * 8 + (lane & 7);
    int bchk = (blk & 1) * 16;

    float acc[4][8][4];
    #pragma unroll
    for (int i = 0; i < 4; i++)
        #pragma unroll
        for (int j = 0; j < 8; j++)
            #pragma unroll
            for (int q = 0; q < 4; q++) acc[i][j][q] = 0.f;

    int pre = ntiles < (STAGES - 1) ? ntiles : (STAGES - 1);
    for (int s = 0; s < pre; ++s) issue(s, s);

    for (int t = 0; t < ntiles; ++t) {
        cp_wait<STAGES - 2>();
        __syncthreads();
        if (t + STAGES - 1 < ntiles) issue(t + STAGES - 1, (t + STAGES - 1) % STAGES);
        uint32_t bA = smu + (t % STAGES) * FSTAGE_BYTES;
        uint32_t bB = bA + 16384;
        #pragma unroll
        for (int kk = 0; kk < 4; ++kk) {
            uint32_t af[4][4], bf[8][2];
            #pragma unroll
            for (int mi = 0; mi < 4; ++mi) {
                int row = warp_m + mi * 16 + arow;
                ldm_x4(af[mi], bA + SWZ(row * 128 + kk * 32 + achk));
            }
            #pragma unroll
            for (int nh = 0; nh < 4; ++nh) {
                uint32_t q[4];
                int n = warp_n + nh * 16 + brow;
                ldm_x4(q, bB + SWZ(n * 128 + kk * 32 + bchk));
                bf[nh * 2 + 0][0] = q[0]; bf[nh * 2 + 0][1] = q[1];
                bf[nh * 2 + 1][0] = q[2]; bf[nh * 2 + 1][1] = q[3];
            }
            #pragma unroll
            for (int mi = 0; mi < 4; ++mi)
                #pragma unroll
                for (int ni = 0; ni < 8; ++ni)
                    mma_fp16(acc[mi][ni], af[mi], bf[ni]);
        }
        __syncthreads();
    }

    int g = lane >> 2, t4 = lane & 3;
    #pragma unroll
    for (int mi = 0; mi < 4; ++mi) {
        int r0 = m0 + warp_m + mi * 16 + g;
        int r1 = r0 + 8;
        #pragma unroll
        for (int ni = 0; ni < 8; ++ni) {
            int col = n0 + warp_n + ni * 8 + t4 * 2;
            float v0 = acc[mi][ni][0], v1 = acc[mi][ni][1];
            float v2 = acc[mi][ni][2], v3 = acc[mi][ni][3];
            if (epi == 1) {
                long long o0 = (long long)r0 * N + col;
                long long o1 = (long long)r1 * N + col;
                v0 += R[o0]; v1 += R[o0 + 1]; v2 += R[o1]; v3 += R[o1 + 1];
            }
            *(float2*)&C[(long long)r0 * N + col] = make_float2(v0, v1);
            *(float2*)&C[(long long)r1 * N + col] = make_float2(v2, v3);
        }
    }
}

// ---------------- bf16 mma GEMM (attention): CTA 128x128, warp 64x32 ----------------
// epi 0: plain f32   2: scores (scale+causal, skip masked)   3: PV + sigmoid-gate -> fp16 ao
#define BSTAGE_BYTES 32768
#define BGEMM_SMEM (STAGES * BSTAGE_BYTES)

__global__ __launch_bounds__(256)
void gemm_bf16_kernel(const __nv_bfloat16* __restrict__ A, const __nv_bfloat16* __restrict__ B,
                      float* __restrict__ C,
                      const float* __restrict__ QKV, __half* __restrict__ AO,
                      int M, int N, int K,
                      long long bAel, long long bBel, long long bCel,
                      int bmode, int epi, float scale, int klimit)
{
    extern __shared__ char smch[];
    int tid = threadIdx.x;
    int z = blockIdx.z;
    int m0 = blockIdx.y * 128;
    int n0 = blockIdx.x * 128;
    if (epi == 2 && n0 > m0 + 127) return;

    const __nv_bfloat16* Ab = A + (long long)z * bAel;
    long long zb = bmode ? ((long long)(z >> 3) * 2 + ((z & 7) >> 2)) : (long long)z;
    const __nv_bfloat16* Bb = B + zb * bBel;
    float* Cb = C + (long long)z * bCel;

    uint32_t smu = smem_u32(smch);
    int Keff = klimit ? min(K, m0 + 128) : K;
    int ntiles = Keff / 64;

    int lr = tid >> 3;
    int lc = (tid & 7) * 16;

    auto issue = [&](int t, int slot) {
        uint32_t bA = smu + slot * BSTAGE_BYTES;
        uint32_t bB = bA + 16384;
        long long kofs = (long long)t * 128;
        #pragma unroll
        for (int j = 0; j < 4; ++j) {
            int r = lr + j * 32;
            cp16(bA + SWZ(r * 128 + lc),
                 (const char*)(Ab + (long long)(m0 + r) * K) + kofs + lc);
        }
        #pragma unroll
        for (int j = 0; j < 4; ++j) {
            int r = lr + j * 32;
            cp16(bB + SWZ(r * 128 + lc),
                 (const char*)(Bb + (long long)(n0 + r) * K) + kofs + lc);
        }
        cp_commit();
    };

    int wid = tid >> 5, lane = tid & 31;
    int warp_m = (wid & 1) * 64;
    int warp_n = (wid >> 1) * 32;
    int blk = lane >> 3;
    int arow = (blk & 1) * 8 + (lane & 7);
    int achk = (blk >> 1) * 16;
    int brow = (blk >> 1) * 8 + (lane & 7);
    int bchk = (blk & 1) * 16;

    float acc[4][4][4];
    #pragma unroll
    for (int i = 0; i < 4; i++)
        #pragma unroll
        for (int j = 0; j < 4; j++)
            #pragma unroll
            for (int q = 0; q < 4; q++) acc[i][j][q] = 0.f;

    int pre = ntiles < (STAGES - 1) ? ntiles : (STAGES - 1);
    for (int s = 0; s < pre; ++s) issue(s, s);

    for (int t = 0; t < ntiles; ++t) {
        cp_wait<STAGES - 2>();
        __syncthreads();
        if (t + STAGES - 1 < ntiles) issue(t + STAGES - 1, (t + STAGES - 1) % STAGES);
        uint32_t bA = smu + (t % STAGES) * BSTAGE_BYTES;
        uint32_t bB = bA + 16384;
        #pragma unroll
        for (int kk = 0; kk < 4; ++kk) {
            uint32_t af[4][4], bf[4][2];
            #pragma unroll
            for (int mi = 0; mi < 4; ++mi) {
                int row = warp_m + mi * 16 + arow;
                ldm_x4(af[mi], bA + SWZ(row * 128 + kk * 32 + achk));
            }
            #pragma unroll
            for (int nh = 0; nh < 2; ++nh) {
                uint32_t q[4];
                int n = warp_n + nh * 16 + brow;
                ldm_x4(q, bB + SWZ(n * 128 + kk * 32 + bchk));
                bf[nh * 2 + 0][0] = q[0]; bf[nh * 2 + 0][1] = q[1];
                bf[nh * 2 + 1][0] = q[2]; bf[nh * 2 + 1][1] = q[3];
            }
            #pragma unroll
            for (int mi = 0; mi < 4; ++mi)
                #pragma unroll
                for (int ni = 0; ni < 4; ++ni)
                    mma_bf16(acc[mi][ni], af[mi], bf[ni]);
        }
        __syncthreads();
    }

    int g = lane >> 2, t4 = lane & 3;
    int bb = z >> 3, hh = z & 7;       // for epi 3
    #pragma unroll
    for (int mi = 0; mi < 4; ++mi) {
        int r0 = m0 + warp_m + mi * 16 + g;
        int r1 = r0 + 8;
        #pragma unroll
        for (int ni = 0; ni < 4; ++ni) {
            int col = n0 + warp_n + ni * 8 + t4 * 2;
            float v0 = acc[mi][ni][0], v1 = acc[mi][ni][1];
            float v2 = acc[mi][ni][2], v3 = acc[mi][ni][3];
            if (epi == 2) {
                v0 *= scale; v1 *= scale; v2 *= scale; v3 *= scale;
                if (col     > r0) v0 = FMIN;
                if (col + 1 > r0) v1 = FMIN;
                if (col     > r1) v2 = FMIN;
                if (col + 1 > r1) v3 = FMIN;
                *(float2*)&Cb[(long long)r0 * N + col] = make_float2(v0, v1);
                *(float2*)&Cb[(long long)r1 * N + col] = make_float2(v2, v3);
            } else if (epi == 3) {
                // PV output row r = l, col = d.  t = bb*LL + l.
                long long t0 = (long long)bb * LL + r0;
                long long t1 = (long long)bb * LL + r1;
                float g0 = QKV[t0 * NQKV + hh * 512 + 256 + col];
                float g1 = QKV[t0 * NQKV + hh * 512 + 256 + col + 1];
                float g2 = QKV[t1 * NQKV + hh * 512 + 256 + col];
                float g3 = QKV[t1 * NQKV + hh * 512 + 256 + col + 1];
                __half2 o0 = __floats2half2_rn(v0 * (1.f / (1.f + expf(-g0))),
                                               v1 * (1.f / (1.f + expf(-g1))));
                __half2 o1 = __floats2half2_rn(v2 * (1.f / (1.f + expf(-g2))),
                                               v3 * (1.f / (1.f + expf(-g3))));
                *(__half2*)&AO[t0 * 2048 + hh * 256 + col] = o0;
                *(__half2*)&AO[t1 * 2048 + hh * 256 + col] = o1;
            } else {
                *(float2*)&Cb[(long long)r0 * N + col] = make_float2(v0, v1);
                *(float2*)&Cb[(long long)r1 * N + col] = make_float2(v2, v3);
            }
        }
    }
}

// ---------------- elementwise kernels ----------------
__global__ void convert_fp16_kernel(const float* __restrict__ in, __half* __restrict__ out, long n4) {
    long i = (long)blockIdx.x * 256 + threadIdx.x;   // over float4 groups
    if (i < n4) {
        float4 v = ((const float4*)in)[i];
        __half2 lo = __floats2half2_rn(v.x, v.y);
        __half2 hi = __floats2half2_rn(v.z, v.w);
        ((__half2*)out)[i * 2]     = lo;
        ((__half2*)out)[i * 2 + 1] = hi;
    }
}
__global__ void rmsnorm_h_kernel(const float* __restrict__ in, const float* __restrict__ w,
                                 __half* __restrict__ out, int width,
                                 long row_stride, long col_off) {
    long t = blockIdx.x;
    const float* x = in + t * width;
    float ss = 0.f;
    for (int i = threadIdx.x; i < width; i += 256) { float v = x[i]; ss = fmaf(v, v, ss); }
    float rms = rsqrtf(blk_sum(ss) / (float)width + 1e-6f);
    __half* y = out + t * row_stride + col_off;
    for (int i = threadIdx.x; i < width; i += 256) y[i] = __float2half(x[i] * rms * w[i]);
}
__global__ void qpost_kernel(const float* __restrict__ qkv, const float* __restrict__ qn_w,
                             __nv_bfloat16* __restrict__ qdst) {
    int t = blockIdx.x, h = blockIdx.y;
    int b = t / LL, l = t % LL;
    const float* src = qkv + (long)t * NQKV + h * 512;
    int tid = threadIdx.x;
    float v = src[tid];
    float rms = rsqrtf(blk_sum(v * v) / (float)DD + 1e-6f);
    __shared__ float sq[DD];
    sq[tid] = v * rms * qn_w[tid];
    __syncthreads();
    if (tid < 32) {
        double inv = exp(-((double)(2 * tid) / 64.0) * log(1.0e7));
        double fr = (double)l * inv, c = cos(fr), s = sin(fr);
        float x0 = sq[2 * tid], x1 = sq[2 * tid + 1];
        sq[2 * tid]     = (float)((double)x0 * c - (double)x1 * s);
        sq[2 * tid + 1] = (float)((double)x0 * s + (double)x1 * c);
    }
    __syncthreads();
    long row = (long)(b * NQH + h) * LL + l;
    qdst[row * DD + tid] = __float2bfloat16(sq[tid]);
}
__global__ void kpost_kernel(const float* __restrict__ qkv, const float* __restrict__ kn_w,
                             __nv_bfloat16* __restrict__ kdst) {
    int t = blockIdx.x, h = blockIdx.y;
    int b = t / LL, l = t % LL;
    const float* src = qkv + (long)t * NQKV + 4096 + h * 256;
    int tid = threadIdx.x;
    float v = src[tid];
    float rms = rsqrtf(blk_sum(v * v) / (float)DD + 1e-6f);
    __shared__ float sq[DD];
    sq[tid] = v * rms * kn_w[tid];
    __syncthreads();
    if (tid < 32) {
        double inv = exp(-((double)(2 * tid) / 64.0) * log(1.0e7));
        double fr = (double)l * inv, c = cos(fr), s = sin(fr);
        float x0 = sq[2 * tid], x1 = sq[2 * tid + 1];
        sq[2 * tid]     = (float)((double)x0 * c - (double)x1 * s);
        sq[2 * tid + 1] = (float)((double)x0 * s + (double)x1 * c);
    }
    __syncthreads();
    long row = (long)(b * NKVH + h) * LL + l;
    kdst[row * DD + tid] = __float2bfloat16(sq[tid]);
}
__global__ void vpost_kernel(const float* __restrict__ qkv, __nv_bfloat16* __restrict__ vt) {
    __shared__ float smv[32][33];
    int l0 = blockIdx.x * 32, d0 = blockIdx.y * 32, z = blockIdx.z;
    int b = z >> 1, h = z & 1;
    int tx = threadIdx.x & 31, ty = threadIdx.x >> 5;
    #pragma unroll
    for (int j = 0; j < 4; ++j) {
        int lloc = ty + j * 8;
        smv[lloc][tx] = qkv[(long)(b * LL + l0 + lloc) * NQKV + 4608 + h * 256 + d0 + tx];
    }
    __syncthreads();
    #pragma unroll
    for (int j = 0; j < 4; ++j) {
        int dd = ty + j * 8;
        vt[(long)(z * DD + d0 + dd) * LL + l0 + tx] = __float2bfloat16(smv[tx][dd]);
    }
}
__global__ void softmax_kernel(const float* __restrict__ scores, __nv_bfloat16* __restrict__ p) {
    int q = blockIdx.x, z = blockIdx.y;
    const float* row = scores + ((long)z * LL + q) * LL;
    __nv_bfloat16* prow = p + ((long)z * LL + q) * LL;
    int nwrite = ((q >> 7) + 1) << 7;
    float vals[8], mx = -INFINITY;
    #pragma unroll
    for (int i = 0; i < 8; i++) {
        int col = threadIdx.x + i * 256;
        vals[i] = (col < nwrite) ? row[col] : -INFINITY;
        mx = fmaxf(mx, vals[i]);
    }
    mx = blk_max(mx);
    float sum = 0.f;
    #pragma unroll
    for (int i = 0; i < 8; i++) { vals[i] = __expf(vals[i] - mx); sum += vals[i]; }
    sum = blk_sum(sum);
    float invs = 1.f / sum;
    #pragma unroll
    for (int i = 0; i < 8; i++) {
        int col = threadIdx.x + i * 256;
        if (col < nwrite) prow[col] = __float2bfloat16(vals[i] * invs);
    }
}
__global__ void silu_mul_kernel(const float* __restrict__ gu, __half* __restrict__ out, long n) {
    long i = (long)blockIdx.x * 256 + threadIdx.x;   // over NTOK*II
    if (i < n) {
        long t = i / II;
        long c = i - t * II;
        float x = gu[t * NGU + c];
        float u = gu[t * NGU + II + c];
        out[i] = __float2half(x * (1.f / (1.f + expf(-x))) * u);
    }
}

// ---------------- launch ----------------
static void launch_fp16(const __half* A, const __half* B, float* C, const float* R,
                        int M, int N, int K, int epi) {
    dim3 grid(N / 256, M / 128, 1);
    gemm_fp16_kernel<<<grid, 256, FGEMM_SMEM>>>(A, B, C, R, M, N, K, epi);
}

extern "C" void kernel_launch(void* const* d_in, const int* in_sizes, int n_in,
                              void* d_out, int out_size) {
    (void)in_sizes; (void)n_in; (void)out_size;
    const float* embeddings = (const float*)d_in[0];
    const float* hidden     = (const float*)d_in[1];
    const float* pre_emb_w  = (const float*)d_in[2];
    const float* pre_hid_w  = (const float*)d_in[3];
    const float* fc_w       = (const float*)d_in[4];
    const float* in_ln_w    = (const float*)d_in[5];
    const float* q_w        = (const float*)d_in[6];
    const float* k_w        = (const float*)d_in[7];
    const float* v_w        = (const float*)d_in[8];
    const float* o_w        = (const float*)d_in[9];
    const float* qn_w       = (const float*)d_in[10];
    const float* kn_w       = (const float*)d_in[11];
    const float* post_ln_w  = (const float*)d_in[12];
    const float* gate_w     = (const float*)d_in[13];
    const float* up_w       = (const float*)d_in[14];
    const float* down_w     = (const float*)d_in[15];
    const float* norm_w     = (const float*)d_in[16];
    const float* lm_w       = (const float*)d_in[17];
    float* out = (float*)d_out;

    static bool inited = false;
    static float *p_x0, *p_qkv, *p_scores, *p_gu, *p_x1, *p_x2;
    static __half *pa_xcat, *pa_xn, *pa_ao, *pa_xn2, *pa_gml, *pa_xn3;
    static __half *pw_fc, *pw_qkv, *pw_o, *pw_gu, *pw_down, *pw_lm;
    static __nv_bfloat16 *ph_q, *ph_k, *ph_vt, *ph_p;
    if (!inited) {
        cudaGetSymbolAddress((void**)&p_x0, g_x0);      cudaGetSymbolAddress((void**)&p_qkv, g_qkv);
        cudaGetSymbolAddress((void**)&p_scores, g_scores);
        cudaGetSymbolAddress((void**)&p_gu, g_gu);
        cudaGetSymbolAddress((void**)&p_x1, g_x1);      cudaGetSymbolAddress((void**)&p_x2, g_x2);
        cudaGetSymbolAddress((void**)&pa_xcat, a_xcat); cudaGetSymbolAddress((void**)&pa_xn, a_xn);
        cudaGetSymbolAddress((void**)&pa_ao, a_ao);     cudaGetSymbolAddress((void**)&pa_xn2, a_xn2);
        cudaGetSymbolAddress((void**)&pa_gml, a_gml);   cudaGetSymbolAddress((void**)&pa_xn3, a_xn3);
        cudaGetSymbolAddress((void**)&pw_fc, w_fc);     cudaGetSymbolAddress((void**)&pw_qkv, w_qkv);
        cudaGetSymbolAddress((void**)&pw_o, w_o);       cudaGetSymbolAddress((void**)&pw_gu, w_gu);
        cudaGetSymbolAddress((void**)&pw_down, w_down); cudaGetSymbolAddress((void**)&pw_lm, w_lm);
        cudaGetSymbolAddress((void**)&ph_q, h_q);       cudaGetSymbolAddress((void**)&ph_k, h_k);
        cudaGetSymbolAddress((void**)&ph_vt, h_vt);     cudaGetSymbolAddress((void**)&ph_p, h_p);
        cudaFuncSetAttribute(gemm_fp16_kernel, cudaFuncAttributeMaxDynamicSharedMemorySize, FGEMM_SMEM);
        cudaFuncSetAttribute(gemm_bf16_kernel, cudaFuncAttributeMaxDynamicSharedMemorySize, BGEMM_SMEM);
        inited = true;
    }

    // weights -> fp16 (qkv and gate/up written packed)
    long n4;
    n4 = (long)HH * 2048 / 4;  convert_fp16_kernel<<<(n4 + 255) / 256, 256>>>(fc_w,   pw_fc,   n4);
    n4 = (long)4096 * HH / 4;  convert_fp16_kernel<<<(n4 + 255) / 256, 256>>>(q_w,    pw_qkv,  n4);
    n4 = (long)512 * HH / 4;   convert_fp16_kernel<<<(n4 + 255) / 256, 256>>>(k_w,    pw_qkv + (size_t)4096 * HH, n4);
    n4 = (long)512 * HH / 4;   convert_fp16_kernel<<<(n4 + 255) / 256, 256>>>(v_w,    pw_qkv + (size_t)4608 * HH, n4);
    n4 = (long)HH * 2048 / 4;  convert_fp16_kernel<<<(n4 + 255) / 256, 256>>>(o_w,    pw_o,    n4);
    n4 = (long)II * HH / 4;    convert_fp16_kernel<<<(n4 + 255) / 256, 256>>>(gate_w, pw_gu,   n4);
    n4 = (long)II * HH / 4;    convert_fp16_kernel<<<(n4 + 255) / 256, 256>>>(up_w,   pw_gu + (size_t)II * HH, n4);
    n4 = (long)HH * II / 4;    convert_fp16_kernel<<<(n4 + 255) / 256, 256>>>(down_w, pw_down, n4);
    n4 = (long)VV * HH / 4;    convert_fp16_kernel<<<(n4 + 255) / 256, 256>>>(lm_w,   pw_lm,   n4);

    // 1. pre-norms + concat -> fp16 xcat
    rmsnorm_h_kernel<<<NTOK, 256>>>(embeddings, pre_emb_w, pa_xcat, HH, 2048, 0);
    rmsnorm_h_kernel<<<NTOK, 256>>>(hidden,     pre_hid_w, pa_xcat, HH, 2048, 1024);
    // 2. fc
    launch_fp16(pa_xcat, pw_fc, p_x0, nullptr, NTOK, HH, 2048, 0);
    // 3. in_ln
    rmsnorm_h_kernel<<<NTOK, 256>>>(p_x0, in_ln_w, pa_xn, HH, 1024, 0);
    // 4. packed qkv GEMM (N=5120)
    launch_fp16(pa_xn, pw_qkv, p_qkv, nullptr, NTOK, NQKV, HH, 0);
    // 5. head post -> bf16
    qpost_kernel<<<dim3(NTOK, NQH), 256>>>(p_qkv, qn_w, ph_q);
    kpost_kernel<<<dim3(NTOK, NKVH), 256>>>(p_qkv, kn_w, ph_k);
    vpost_kernel<<<dim3(LL / 32, DD / 32, BBATCH * NKVH), 256>>>(p_qkv, ph_vt);
    // 6. scores = QK^T/16 causal
    {
        dim3 grid(LL / 128, LL / 128, BBATCH * NQH);
        gemm_bf16_kernel<<<grid, 256, BGEMM_SMEM>>>(ph_q, ph_k, p_scores, nullptr, nullptr,
            LL, LL, DD, (long long)LL * DD, (long long)LL * DD, (long long)LL * LL,
            1, 2, 0.0625f, 0);
    }
    // 7. softmax -> bf16 P
    softmax_kernel<<<dim3(LL, BBATCH * NQH), 256>>>(p_scores, ph_p);
    // 8. PV + fused sigmoid gate -> fp16 ao (epi 3, klimit causal)
    {
        dim3 grid(DD / 128, LL / 128, BBATCH * NQH);
        gemm_bf16_kernel<<<grid, 256, BGEMM_SMEM>>>(ph_p, ph_vt, nullptr, p_qkv, pa_ao,
            LL, DD, LL, (long long)LL * LL, (long long)DD * LL, 0,
            1, 3, 1.f, 1);
    }
    // 10. o proj + residual
    launch_fp16(pa_ao, pw_o, p_x1, p_x0, NTOK, HH, 2048, 1);
    // 11. post_ln
    rmsnorm_h_kernel<<<NTOK, 256>>>(p_x1, post_ln_w, pa_xn2, HH, 1024, 0);
    // 12. packed gate/up GEMM (N=7168) + silu
    launch_fp16(pa_xn2, pw_gu, p_gu, nullptr, NTOK, NGU, HH, 0);
    silu_mul_kernel<<<((long)NTOK * II + 255) / 256, 256>>>(p_gu, pa_gml, (long)NTOK * II);
    launch_fp16(pa_gml, pw_down, p_x2, p_x1, NTOK, HH, II, 1);
    // 15. final norm + lm head
    rmsnorm_h_kernel<<<NTOK, 256>>>(p_x2, norm_w, pa_xn3, HH, 1024, 0);
    launch_fp16(pa_xn3, pw_lm, out, nullptr, NTOK, VV, HH, 0);
}

// round 12
// speedup vs baseline: 7.0325x; 1.1768x over previous
#include <cuda_runtime.h>
#include <cuda_bf16.h>
#include <cuda_fp16.h>
#include <math.h>
#include <stdint.h>

#define BBATCH 4
#define LL    2048
#define HH    1024
#define NQH   8
#define NKVH  2
#define DD    256
#define II    3584
#define VV    16384
#define NTOK  (BBATCH*LL)
#define FMIN  (-3.402823466e38f)
#define NQKV  5120          // 4096 q+gate | 512 k | 512 v
#define NGU   7168          // 3584 gate | 3584 up

// fp32 scratch
__device__ __align__(256) float g_x0    [(size_t)NTOK * HH];
__device__ __align__(256) float g_qkv   [(size_t)NTOK * NQKV];
__device__ __align__(256) float g_scores[(size_t)BBATCH * NQH * LL * LL];
__device__ __align__(256) float g_gu    [(size_t)NTOK * NGU];
__device__ __align__(256) float g_x1    [(size_t)NTOK * HH];
__device__ __align__(256) float g_x2    [(size_t)NTOK * HH];
// fp16 GEMM activation inputs
__device__ __align__(256) __half a_xcat [(size_t)NTOK * 2048];
__device__ __align__(256) __half a_xn   [(size_t)NTOK * HH];
__device__ __align__(256) __half a_ao   [(size_t)NTOK * 2048];
__device__ __align__(256) __half a_xn2  [(size_t)NTOK * HH];
__device__ __align__(256) __half a_gml  [(size_t)NTOK * II];
__device__ __align__(256) __half a_xn3  [(size_t)NTOK * HH];
// fp16 weights (qkv and gate/up packed)
__device__ __align__(256) __half w_fc   [(size_t)HH * 2048];
__device__ __align__(256) __half w_qkv  [(size_t)NQKV * HH];
__device__ __align__(256) __half w_o    [(size_t)HH * 2048];
__device__ __align__(256) __half w_gu   [(size_t)NGU * HH];
__device__ __align__(256) __half w_down [(size_t)HH * II];
__device__ __align__(256) __half w_lm   [(size_t)VV * HH];
// bf16 attention buffers
__device__ __align__(256) __nv_bfloat16 h_q [(size_t)BBATCH * NQH * LL * DD];
__device__ __align__(256) __nv_bfloat16 h_k [(size_t)BBATCH * NKVH * LL * DD];
__device__ __align__(256) __nv_bfloat16 h_vt[(size_t)BBATCH * NKVH * DD * LL];
__device__ __align__(256) __nv_bfloat16 h_p [(size_t)BBATCH * NQH * LL * LL];

// ---------------- helpers ----------------
__device__ __forceinline__ uint32_t smem_u32(const void* p) {
    uint32_t a;
    asm("{ .reg .u64 t; cvta.to.shared.u64 t, %1; cvt.u32.u64 %0, t; }" : "=r"(a) : "l"(p));
    return a;
}
#define SWZ(o) ((o) ^ (((o) >> 3) & 0x70))

__device__ __forceinline__ void cp16(uint32_t dst, const void* src) {
    asm volatile("cp.async.cg.shared.global [%0], [%1], 16;" :: "r"(dst), "l"(src));
}
__device__ __forceinline__ void cp_commit() { asm volatile("cp.async.commit_group;"); }
template<int N> __device__ __forceinline__ void cp_wait() {
    asm volatile("cp.async.wait_group %0;" :: "n"(N));
}
__device__ __forceinline__ void ldm_x4(uint32_t* r, uint32_t addr) {
    asm volatile("ldmatrix.sync.aligned.m8n8.x4.shared.b16 {%0,%1,%2,%3}, [%4];"
                 : "=r"(r[0]), "=r"(r[1]), "=r"(r[2]), "=r"(r[3]) : "r"(addr));
}
__device__ __forceinline__ void mma_fp16(float* c, const uint32_t* a, const uint32_t* b) {
    asm volatile(
        "mma.sync.aligned.m16n8k16.row.col.f32.f16.f16.f32 "
        "{%0,%1,%2,%3},{%4,%5,%6,%7},{%8,%9},{%0,%1,%2,%3};"
        : "+f"(c[0]), "+f"(c[1]), "+f"(c[2]), "+f"(c[3])
        : "r"(a[0]), "r"(a[1]), "r"(a[2]), "r"(a[3]), "r"(b[0]), "r"(b[1]));
}
__device__ __forceinline__ void mma_bf16(float* c, const uint32_t* a, const uint32_t* b) {
    asm volatile(
        "mma.sync.aligned.m16n8k16.row.col.f32.bf16.bf16.f32 "
        "{%0,%1,%2,%3},{%4,%5,%6,%7},{%8,%9},{%0,%1,%2,%3};"
        : "+f"(c[0]), "+f"(c[1]), "+f"(c[2]), "+f"(c[3])
        : "r"(a[0]), "r"(a[1]), "r"(a[2]), "r"(a[3]), "r"(b[0]), "r"(b[1]));
}

// block reduce (256 thr)
__device__ __forceinline__ float blk_sum(float v) {
    __shared__ float sh[8]; __shared__ float res;
    #pragma unroll
    for (int o = 16; o; o >>= 1) v += __shfl_xor_sync(0xffffffffu, v, o);
    if ((threadIdx.x & 31) == 0) sh[threadIdx.x >> 5] = v;
    __syncthreads();
    if (threadIdx.x < 32) {
        float x = (threadIdx.x < 8) ? sh[threadIdx.x] : 0.f;
        #pragma unroll
        for (int o = 4; o; o >>= 1) x += __shfl_xor_sync(0xffffffffu, x, o);
        if (threadIdx.x == 0) res = x;
    }
    __syncthreads();
    return res;
}
__device__ __forceinline__ float blk_max(float v) {
    __shared__ float sh[8]; __shared__ float res;
    #pragma unroll
    for (int o = 16; o; o >>= 1) v = fmaxf(v, __shfl_xor_sync(0xffffffffu, v, o));
    if ((threadIdx.x & 31) == 0) sh[threadIdx.x >> 5] = v;
    __syncthreads();
    if (threadIdx.x < 32) {
        float x = (threadIdx.x < 8) ? sh[threadIdx.x] : -INFINITY;
        #pragma unroll
        for (int o = 4; o; o >>= 1) x = fmaxf(x, __shfl_xor_sync(0xffffffffu, x, o));
        if (threadIdx.x == 0) res = x;
    }
    __syncthreads();
    return res;
}

// ---------------- fp16 mma GEMM: C[M,N] f32 = A[M,K]*B[N,K]^T ----------------
// CTA 128x256, warp 64x64. epi 0: plain  1: +R
#define STAGES 3
#define FSTAGE_BYTES (16384 + 32768)
#define FGEMM_SMEM (STAGES * FSTAGE_BYTES)

__global__ __launch_bounds__(256)
void gemm_fp16_kernel(const __half* __restrict__ A, const __half* __restrict__ B,
                      float* __restrict__ C, const float* __restrict__ R,
                      int M, int N, int K, int epi)
{
    extern __shared__ char smch[];
    int tid = threadIdx.x;
    int m0 = blockIdx.y * 128;
    int n0 = blockIdx.x * 256;

    uint32_t smu = smem_u32(smch);
    int ntiles = K / 64;

    int lr = tid >> 3;
    int lc = (tid & 7) * 16;

    auto issue = [&](int t, int slot) {
        uint32_t bA = smu + slot * FSTAGE_BYTES;
        uint32_t bB = bA + 16384;
        long long kofs = (long long)t * 128;
        #pragma unroll
        for (int j = 0; j < 4; ++j) {
            int r = lr + j * 32;
            cp16(bA + SWZ(r * 128 + lc),
                 (const char*)(A + (long long)(m0 + r) * K) + kofs + lc);
        }
        #pragma unroll
        for (int j = 0; j < 8; ++j) {
            int r = lr + j * 32;
            cp16(bB + SWZ(r * 128 + lc),
                 (const char*)(B + (long long)(n0 + r) * K) + kofs + lc);
        }
        cp_commit();
    };

    int wid = tid >> 5, lane = tid & 31;
    int warp_m = (wid & 1) * 64;
    int warp_n = (wid >> 1) * 64;
    int blk = lane >> 3;
    int arow = (blk & 1) * 8 + (lane & 7);
    int achk = (blk >> 1) * 16;
    int brow = (blk >> 1) * 8 + (lane & 7);
    int bchk = (blk & 1) * 16;

    float acc[4][8][4];
    #pragma unroll
    for (int i = 0; i < 4; i++)
        #pragma unroll
        for (int j = 0; j < 8; j++)
            #pragma unroll
            for (int q = 0; q < 4; q++) acc[i][j][q] = 0.f;

    int pre = ntiles < (STAGES - 1) ? ntiles : (STAGES - 1);
    for (int s = 0; s < pre; ++s) issue(s, s);

    for (int t = 0; t < ntiles; ++t) {
        cp_wait<STAGES - 2>();
        __syncthreads();          // all warps done with slot being re-targeted
        if (t + STAGES - 1 < ntiles) issue(t + STAGES - 1, (t + STAGES - 1) % STAGES);
        uint32_t bA = smu + (t % STAGES) * FSTAGE_BYTES;
        uint32_t bB = bA + 16384;
        #pragma unroll
        for (int kk = 0; kk < 4; ++kk) {
            uint32_t af[4][4], bf[8][2];
            #pragma unroll
            for (int mi = 0; mi < 4; ++mi) {
                int row = warp_m + mi * 16 + arow;
                ldm_x4(af[mi], bA + SWZ(row * 128 + kk * 32 + achk));
            }
            #pragma unroll
            for (int nh = 0; nh < 4; ++nh) {
                uint32_t q[4];
                int n = warp_n + nh * 16 + brow;
                ldm_x4(q, bB + SWZ(n * 128 + kk * 32 + bchk));
                bf[nh * 2 + 0][0] = q[0]; bf[nh * 2 + 0][1] = q[1];
                bf[nh * 2 + 1][0] = q[2]; bf[nh * 2 + 1][1] = q[3];
            }
            #pragma unroll
            for (int mi = 0; mi < 4; ++mi)
                #pragma unroll
                for (int ni = 0; ni < 8; ++ni)
                    mma_fp16(acc[mi][ni], af[mi], bf[ni]);
        }
    }

    int g = lane >> 2, t4 = lane & 3;
    #pragma unroll
    for (int mi = 0; mi < 4; ++mi) {
        int r0 = m0 + warp_m + mi * 16 + g;
        int r1 = r0 + 8;
        #pragma unroll
        for (int ni = 0; ni < 8; ++ni) {
            int col = n0 + warp_n + ni * 8 + t4 * 2;
            float v0 = acc[mi][ni][0], v1 = acc[mi][ni][1];
            float v2 = acc[mi][ni][2], v3 = acc[mi][ni][3];
            if (epi == 1) {
                long long o0 = (long long)r0 * N + col;
                long long o1 = (long long)r1 * N + col;
                v0 += R[o0]; v1 += R[o0 + 1]; v2 += R[o1]; v3 += R[o1 + 1];
            }
            *(float2*)&C[(long long)r0 * N + col] = make_float2(v0, v1);
            *(float2*)&C[(long long)r1 * N + col] = make_float2(v2, v3);
        }
    }
}

// ---------------- bf16 mma GEMM (attention): CTA 128x128, warp 64x32 ----------------
// epi 0: plain f32   2: scores (scale+causal, skip masked)   3: PV + sigmoid-gate -> fp16 ao
#define BSTAGE_BYTES 32768
#define BGEMM_SMEM (STAGES * BSTAGE_BYTES)

__global__ __launch_bounds__(256)
void gemm_bf16_kernel(const __nv_bfloat16* __restrict__ A, const __nv_bfloat16* __restrict__ B,
                      float* __restrict__ C,
                      const float* __restrict__ QKV, __half* __restrict__ AO,
                      int M, int N, int K,
                      long long bAel, long long bBel, long long bCel,
                      int bmode, int epi, float scale, int klimit)
{
    extern __shared__ char smch[];
    int tid = threadIdx.x;
    int z = blockIdx.z;
    int m0 = blockIdx.y * 128;
    int n0 = blockIdx.x * 128;
    if (epi == 2 && n0 > m0 + 127) return;

    const __nv_bfloat16* Ab = A + (long long)z * bAel;
    long long zb = bmode ? ((long long)(z >> 3) * 2 + ((z & 7) >> 2)) : (long long)z;
    const __nv_bfloat16* Bb = B + zb * bBel;
    float* Cb = C + (long long)z * bCel;

    uint32_t smu = smem_u32(smch);
    int Keff = klimit ? min(K, m0 + 128) : K;
    int ntiles = Keff / 64;

    int lr = tid >> 3;
    int lc = (tid & 7) * 16;

    auto issue = [&](int t, int slot) {
        uint32_t bA = smu + slot * BSTAGE_BYTES;
        uint32_t bB = bA + 16384;
        long long kofs = (long long)t * 128;
        #pragma unroll
        for (int j = 0; j < 4; ++j) {
            int r = lr + j * 32;
            cp16(bA + SWZ(r * 128 + lc),
                 (const char*)(Ab + (long long)(m0 + r) * K) + kofs + lc);
        }
        #pragma unroll
        for (int j = 0; j < 4; ++j) {
            int r = lr + j * 32;
            cp16(bB + SWZ(r * 128 + lc),
                 (const char*)(Bb + (long long)(n0 + r) * K) + kofs + lc);
        }
        cp_commit();
    };

    int wid = tid >> 5, lane = tid & 31;
    int warp_m = (wid & 1) * 64;
    int warp_n = (wid >> 1) * 32;
    int blk = lane >> 3;
    int arow = (blk & 1) * 8 + (lane & 7);
    int achk = (blk >> 1) * 16;
    int brow = (blk >> 1) * 8 + (lane & 7);
    int bchk = (blk & 1) * 16;

    float acc[4][4][4];
    #pragma unroll
    for (int i = 0; i < 4; i++)
        #pragma unroll
        for (int j = 0; j < 4; j++)
            #pragma unroll
            for (int q = 0; q < 4; q++) acc[i][j][q] = 0.f;

    int pre = ntiles < (STAGES - 1) ? ntiles : (STAGES - 1);
    for (int s = 0; s < pre; ++s) issue(s, s);

    for (int t = 0; t < ntiles; ++t) {
        cp_wait<STAGES - 2>();
        __syncthreads();
        if (t + STAGES - 1 < ntiles) issue(t + STAGES - 1, (t + STAGES - 1) % STAGES);
        uint32_t bA = smu + (t % STAGES) * BSTAGE_BYTES;
        uint32_t bB = bA + 16384;
        #pragma unroll
        for (int kk = 0; kk < 4; ++kk) {
            uint32_t af[4][4], bf[4][2];
            #pragma unroll
            for (int mi = 0; mi < 4; ++mi) {
                int row = warp_m + mi * 16 + arow;
                ldm_x4(af[mi], bA + SWZ(row * 128 + kk * 32 + achk));
            }
            #pragma unroll
            for (int nh = 0; nh < 2; ++nh) {
                uint32_t q[4];
                int n = warp_n + nh * 16 + brow;
                ldm_x4(q, bB + SWZ(n * 128 + kk * 32 + bchk));
                bf[nh * 2 + 0][0] = q[0]; bf[nh * 2 + 0][1] = q[1];
                bf[nh * 2 + 1][0] = q[2]; bf[nh * 2 + 1][1] = q[3];
            }
            #pragma unroll
            for (int mi = 0; mi < 4; ++mi)
                #pragma unroll
                for (int ni = 0; ni < 4; ++ni)
                    mma_bf16(acc[mi][ni], af[mi], bf[ni]);
        }
    }

    int g = lane >> 2, t4 = lane & 3;
    int bb = z >> 3, hh = z & 7;
    #pragma unroll
    for (int mi = 0; mi < 4; ++mi) {
        int r0 = m0 + warp_m + mi * 16 + g;
        int r1 = r0 + 8;
        #pragma unroll
        for (int ni = 0; ni < 4; ++ni) {
            int col = n0 + warp_n + ni * 8 + t4 * 2;
            float v0 = acc[mi][ni][0], v1 = acc[mi][ni][1];
            float v2 = acc[mi][ni][2], v3 = acc[mi][ni][3];
            if (epi == 2) {
                v0 *= scale; v1 *= scale; v2 *= scale; v3 *= scale;
                if (col     > r0) v0 = FMIN;
                if (col + 1 > r0) v1 = FMIN;
                if (col     > r1) v2 = FMIN;
                if (col + 1 > r1) v3 = FMIN;
                *(float2*)&Cb[(long long)r0 * N + col] = make_float2(v0, v1);
                *(float2*)&Cb[(long long)r1 * N + col] = make_float2(v2, v3);
            } else if (epi == 3) {
                long long t0 = (long long)bb * LL + r0;
                long long t1 = (long long)bb * LL + r1;
                float g0 = QKV[t0 * NQKV + hh * 512 + 256 + col];
                float g1 = QKV[t0 * NQKV + hh * 512 + 256 + col + 1];
                float g2 = QKV[t1 * NQKV + hh * 512 + 256 + col];
                float g3 = QKV[t1 * NQKV + hh * 512 + 256 + col + 1];
                __half2 o0 = __floats2half2_rn(v0 * (1.f / (1.f + expf(-g0))),
                                               v1 * (1.f / (1.f + expf(-g1))));
                __half2 o1 = __floats2half2_rn(v2 * (1.f / (1.f + expf(-g2))),
                                               v3 * (1.f / (1.f + expf(-g3))));
                *(__half2*)&AO[t0 * 2048 + hh * 256 + col] = o0;
                *(__half2*)&AO[t1 * 2048 + hh * 256 + col] = o1;
            } else {
                *(float2*)&Cb[(long long)r0 * N + col] = make_float2(v0, v1);
                *(float2*)&Cb[(long long)r1 * N + col] = make_float2(v2, v3);
            }
        }
    }
}

// ---------------- elementwise kernels ----------------
__global__ void convert_fp16_kernel(const float* __restrict__ in, __half* __restrict__ out, long n4) {
    long i = (long)blockIdx.x * 256 + threadIdx.x;
    if (i < n4) {
        float4 v = ((const float4*)in)[i];
        __half2 lo = __floats2half2_rn(v.x, v.y);
        __half2 hi = __floats2half2_rn(v.z, v.w);
        ((__half2*)out)[i * 2]     = lo;
        ((__half2*)out)[i * 2 + 1] = hi;
    }
}
__global__ void rmsnorm_h_kernel(const float* __restrict__ in, const float* __restrict__ w,
                                 __half* __restrict__ out, int width,
                                 long row_stride, long col_off) {
    long t = blockIdx.x;
    const float* x = in + t * width;
    float ss = 0.f;
    for (int i = threadIdx.x; i < width; i += 256) { float v = x[i]; ss = fmaf(v, v, ss); }
    float rms = rsqrtf(blk_sum(ss) / (float)width + 1e-6f);
    __half* y = out + t * row_stride + col_off;
    for (int i = threadIdx.x; i < width; i += 256) y[i] = __float2half(x[i] * rms * w[i]);
}
__global__ void qpost_kernel(const float* __restrict__ qkv, const float* __restrict__ qn_w,
                             __nv_bfloat16* __restrict__ qdst) {
    int t = blockIdx.x, h = blockIdx.y;
    int b = t / LL, l = t % LL;
    const float* src = qkv + (long)t * NQKV + h * 512;
    int tid = threadIdx.x;
    float v = src[tid];
    float rms = rsqrtf(blk_sum(v * v) / (float)DD + 1e-6f);
    __shared__ float sq[DD];
    sq[tid] = v * rms * qn_w[tid];
    __syncthreads();
    if (tid < 32) {
        float inv = powf(10000000.f, -2.f * (float)tid / 64.f);
        float fr = (float)l * inv;
        float c = cosf(fr), s = sinf(fr);
        float x0 = sq[2 * tid], x1 = sq[2 * tid + 1];
        sq[2 * tid]     = x0 * c - x1 * s;
        sq[2 * tid + 1] = x0 * s + x1 * c;
    }
    __syncthreads();
    long row = (long)(b * NQH + h) * LL + l;
    qdst[row * DD + tid] = __float2bfloat16(sq[tid]);
}
__global__ void kpost_kernel(const float* __restrict__ qkv, const float* __restrict__ kn_w,
                             __nv_bfloat16* __restrict__ kdst) {
    int t = blockIdx.x, h = blockIdx.y;
    int b = t / LL, l = t % LL;
    const float* src = qkv + (long)t * NQKV + 4096 + h * 256;
    int tid = threadIdx.x;
    float v = src[tid];
    float rms = rsqrtf(blk_sum(v * v) / (float)DD + 1e-6f);
    __shared__ float sq[DD];
    sq[tid] = v * rms * kn_w[tid];
    __syncthreads();
    if (tid < 32) {
        float inv = powf(10000000.f, -2.f * (float)tid / 64.f);
        float fr = (float)l * inv;
        float c = cosf(fr), s = sinf(fr);
        float x0 = sq[2 * tid], x1 = sq[2 * tid + 1];
        sq[2 * tid]     = x0 * c - x1 * s;
        sq[2 * tid + 1] = x0 * s + x1 * c;
    }
    __syncthreads();
    long row = (long)(b * NKVH + h) * LL + l;
    kdst[row * DD + tid] = __float2bfloat16(sq[tid]);
}
__global__ void vpost_kernel(const float* __restrict__ qkv, __nv_bfloat16* __restrict__ vt) {
    __shared__ float smv[32][33];
    int l0 = blockIdx.x * 32, d0 = blockIdx.y * 32, z = blockIdx.z;
    int b = z >> 1, h = z & 1;
    int tx = threadIdx.x & 31, ty = threadIdx.x >> 5;
    #pragma unroll
    for (int j = 0; j < 4; ++j) {
        int lloc = ty + j * 8;
        smv[lloc][tx] = qkv[(long)(b * LL + l0 + lloc) * NQKV + 4608 + h * 256 + d0 + tx];
    }
    __syncthreads();
    #pragma unroll
    for (int j = 0; j < 4; ++j) {
        int dd = ty + j * 8;
        vt[(long)(z * DD + d0 + dd) * LL + l0 + tx] = __float2bfloat16(smv[tx][dd]);
    }
}
__global__ void softmax_kernel(const float* __restrict__ scores, __nv_bfloat16* __restrict__ p) {
    int q = blockIdx.x, z = blockIdx.y;
    const float* row = scores + ((long)z * LL + q) * LL;
    __nv_bfloat16* prow = p + ((long)z * LL + q) * LL;
    int nwrite = ((q >> 7) + 1) << 7;
    float vals[8], mx = -INFINITY;
    #pragma unroll
    for (int i = 0; i < 8; i++) {
        int col = threadIdx.x + i * 256;
        vals[i] = (col < nwrite) ? row[col] : -INFINITY;
        mx = fmaxf(mx, vals[i]);
    }
    mx = blk_max(mx);
    float sum = 0.f;
    #pragma unroll
    for (int i = 0; i < 8; i++) { vals[i] = __expf(vals[i] - mx); sum += vals[i]; }
    sum = blk_sum(sum);
    float invs = 1.f / sum;
    #pragma unroll
    for (int i = 0; i < 8; i++) {
        int col = threadIdx.x + i * 256;
        if (col < nwrite) prow[col] = __float2bfloat16(vals[i] * invs);
    }
}
__global__ void silu_mul_kernel(const float* __restrict__ gu, __half* __restrict__ out, long n) {
    long i = (long)blockIdx.x * 256 + threadIdx.x;
    if (i < n) {
        long t = i / II;
        long c = i - t * II;
        float x = gu[t * NGU + c];
        float u = gu[t * NGU + II + c];
        out[i] = __float2half(x * (1.f / (1.f + expf(-x))) * u);
    }
}

// ---------------- launch ----------------
static void launch_fp16_s(cudaStream_t st, const __half* A, const __half* B, float* C,
                          const float* R, int M, int N, int K, int epi) {
    dim3 grid(N / 256, M / 128, 1);
    gemm_fp16_kernel<<<grid, 256, FGEMM_SMEM, st>>>(A, B, C, R, M, N, K, epi);
}

extern "C" void kernel_launch(void* const* d_in, const int* in_sizes, int n_in,
                              void* d_out, int out_size) {
    (void)in_sizes; (void)n_in; (void)out_size;
    const float* embeddings = (const float*)d_in[0];
    const float* hidden     = (const float*)d_in[1];
    const float* pre_emb_w  = (const float*)d_in[2];
    const float* pre_hid_w  = (const float*)d_in[3];
    const float* fc_w       = (const float*)d_in[4];
    const float* in_ln_w    = (const float*)d_in[5];
    const float* q_w        = (const float*)d_in[6];
    const float* k_w        = (const float*)d_in[7];
    const float* v_w        = (const float*)d_in[8];
    const float* o_w        = (const float*)d_in[9];
    const float* qn_w       = (const float*)d_in[10];
    const float* kn_w       = (const float*)d_in[11];
    const float* post_ln_w  = (const float*)d_in[12];
    const float* gate_w     = (const float*)d_in[13];
    const float* up_w       = (const float*)d_in[14];
    const float* down_w     = (const float*)d_in[15];
    const float* norm_w     = (const float*)d_in[16];
    const float* lm_w       = (const float*)d_in[17];
    float* out = (float*)d_out;

    static bool inited = false;
    static float *p_x0, *p_qkv, *p_scores, *p_gu, *p_x1, *p_x2;
    static __half *pa_xcat, *pa_xn, *pa_ao, *pa_xn2, *pa_gml, *pa_xn3;
    static __half *pw_fc, *pw_qkv, *pw_o, *pw_gu, *pw_down, *pw_lm;
    static __nv_bfloat16 *ph_q, *ph_k, *ph_vt, *ph_p;
    static cudaStream_t s2;
    static cudaEvent_t evFork, evJoin;
    if (!inited) {
        cudaGetSymbolAddress((void**)&p_x0, g_x0);      cudaGetSymbolAddress((void**)&p_qkv, g_qkv);
        cudaGetSymbolAddress((void**)&p_scores, g_scores);
        cudaGetSymbolAddress((void**)&p_gu, g_gu);
        cudaGetSymbolAddress((void**)&p_x1, g_x1);      cudaGetSymbolAddress((void**)&p_x2, g_x2);
        cudaGetSymbolAddress((void**)&pa_xcat, a_xcat); cudaGetSymbolAddress((void**)&pa_xn, a_xn);
        cudaGetSymbolAddress((void**)&pa_ao, a_ao);     cudaGetSymbolAddress((void**)&pa_xn2, a_xn2);
        cudaGetSymbolAddress((void**)&pa_gml, a_gml);   cudaGetSymbolAddress((void**)&pa_xn3, a_xn3);
        cudaGetSymbolAddress((void**)&pw_fc, w_fc);     cudaGetSymbolAddress((void**)&pw_qkv, w_qkv);
        cudaGetSymbolAddress((void**)&pw_o, w_o);       cudaGetSymbolAddress((void**)&pw_gu, w_gu);
        cudaGetSymbolAddress((void**)&pw_down, w_down); cudaGetSymbolAddress((void**)&pw_lm, w_lm);
        cudaGetSymbolAddress((void**)&ph_q, h_q);       cudaGetSymbolAddress((void**)&ph_k, h_k);
        cudaGetSymbolAddress((void**)&ph_vt, h_vt);     cudaGetSymbolAddress((void**)&ph_p, h_p);
        cudaFuncSetAttribute(gemm_fp16_kernel, cudaFuncAttributeMaxDynamicSharedMemorySize, FGEMM_SMEM);
        cudaFuncSetAttribute(gemm_bf16_kernel, cudaFuncAttributeMaxDynamicSharedMemorySize, BGEMM_SMEM);
        cudaStreamCreateWithFlags(&s2, cudaStreamNonBlocking);
        cudaEventCreateWithFlags(&evFork, cudaEventDisableTiming);
        cudaEventCreateWithFlags(&evJoin, cudaEventDisableTiming);
        inited = true;
    }

    long n4;
    // fc + qkv converts on main stream (needed immediately)
    n4 = (long)HH * 2048 / 4;  convert_fp16_kernel<<<(n4 + 255) / 256, 256>>>(fc_w,   pw_fc,   n4);
    n4 = (long)4096 * HH / 4;  convert_fp16_kernel<<<(n4 + 255) / 256, 256>>>(q_w,    pw_qkv,  n4);
    n4 = (long)512 * HH / 4;   convert_fp16_kernel<<<(n4 + 255) / 256, 256>>>(k_w,    pw_qkv + (size_t)4096 * HH, n4);
    n4 = (long)512 * HH / 4;   convert_fp16_kernel<<<(n4 + 255) / 256, 256>>>(v_w,    pw_qkv + (size_t)4608 * HH, n4);

    // fork: late-weight converts on s2, overlapped with main chain
    cudaEventRecord(evFork, 0);
    cudaStreamWaitEvent(s2, evFork, 0);
    n4 = (long)HH * 2048 / 4;  convert_fp16_kernel<<<(n4 + 255) / 256, 256, 0, s2>>>(o_w,    pw_o,    n4);
    n4 = (long)II * HH / 4;    convert_fp16_kernel<<<(n4 + 255) / 256, 256, 0, s2>>>(gate_w, pw_gu,   n4);
    n4 = (long)II * HH / 4;    convert_fp16_kernel<<<(n4 + 255) / 256, 256, 0, s2>>>(up_w,   pw_gu + (size_t)II * HH, n4);
    n4 = (long)HH * II / 4;    convert_fp16_kernel<<<(n4 + 255) / 256, 256, 0, s2>>>(down_w, pw_down, n4);
    n4 = (long)VV * HH / 4;    convert_fp16_kernel<<<(n4 + 255) / 256, 256, 0, s2>>>(lm_w,   pw_lm,   n4);
    cudaEventRecord(evJoin, s2);

    // 1. pre-norms + concat -> fp16 xcat
    rmsnorm_h_kernel<<<NTOK, 256>>>(embeddings, pre_emb_w, pa_xcat, HH, 2048, 0);
    rmsnorm_h_kernel<<<NTOK, 256>>>(hidden,     pre_hid_w, pa_xcat, HH, 2048, 1024);
    // 2. fc
    launch_fp16_s(0, pa_xcat, pw_fc, p_x0, nullptr, NTOK, HH, 2048, 0);
    // 3. in_ln
    rmsnorm_h_kernel<<<NTOK, 256>>>(p_x0, in_ln_w, pa_xn, HH, 1024, 0);
    // 4. packed qkv GEMM
    launch_fp16_s(0, pa_xn, pw_qkv, p_qkv, nullptr, NTOK, NQKV, HH, 0);
    // 5. head post -> bf16
    qpost_kernel<<<dim3(NTOK, NQH), 256>>>(p_qkv, qn_w, ph_q);
    kpost_kernel<<<dim3(NTOK, NKVH), 256>>>(p_qkv, kn_w, ph_k);
    vpost_kernel<<<dim3(LL / 32, DD / 32, BBATCH * NKVH), 256>>>(p_qkv, ph_vt);
    // 6. scores = QK^T/16 causal
    {
        dim3 grid(LL / 128, LL / 128, BBATCH * NQH);
        gemm_bf16_kernel<<<grid, 256, BGEMM_SMEM>>>(ph_q, ph_k, p_scores, nullptr, nullptr,
            LL, LL, DD, (long long)LL * DD, (long long)LL * DD, (long long)LL * LL,
            1, 2, 0.0625f, 0);
    }
    // 7. softmax -> bf16 P
    softmax_kernel<<<dim3(LL, BBATCH * NQH), 256>>>(p_scores, ph_p);
    // 8. PV + fused sigmoid gate -> fp16 ao
    {
        dim3 grid(DD / 128, LL / 128, BBATCH * NQH);
        gemm_bf16_kernel<<<grid, 256, BGEMM_SMEM>>>(ph_p, ph_vt, nullptr, p_qkv, pa_ao,
            LL, DD, LL, (long long)LL * LL, (long long)DD * LL, 0,
            1, 3, 1.f, 1);
    }
    // join: late weights must be converted before o-proj
    cudaStreamWaitEvent(0, evJoin, 0);
    // 10. o proj + residual
    launch_fp16_s(0, pa_ao, pw_o, p_x1, p_x0, NTOK, HH, 2048, 1);
    // 11. post_ln
    rmsnorm_h_kernel<<<NTOK, 256>>>(p_x1, post_ln_w, pa_xn2, HH, 1024, 0);
    // 12. packed gate/up GEMM + silu
    launch_fp16_s(0, pa_xn2, pw_gu, p_gu, nullptr, NTOK, NGU, HH, 0);
    silu_mul_kernel<<<((long)NTOK * II + 255) / 256, 256>>>(p_gu, pa_gml, (long)NTOK * II);
    launch_fp16_s(0, pa_gml, pw_down, p_x2, p_x1, NTOK, HH, II, 1);
    // 15. final norm + lm head
    rmsnorm_h_kernel<<<NTOK, 256>>>(p_x2, norm_w, pa_xn3, HH, 1024, 0);
    launch_fp16_s(0, pa_xn3, pw_lm, out, nullptr, NTOK, VV, HH, 0);
}

// round 14
// speedup vs baseline: 7.2828x; 1.0356x over previous
#include <cuda_runtime.h>
#include <cuda_bf16.h>
#include <cuda_fp16.h>
#include <math.h>
#include <stdint.h>

#define BBATCH 4
#define LL    2048
#define HH    1024
#define NQH   8
#define NKVH  2
#define DD    256
#define II    3584
#define VV    16384
#define NTOK  (BBATCH*LL)
#define FMIN  (-3.402823466e38f)
#define NQKV  5120          // 4096 q+gate | 512 k | 512 v
#define NGU   7168          // interleaved: row 2j = gate_j, row 2j+1 = up_j

// fp32 scratch
__device__ __align__(256) float g_x0    [(size_t)NTOK * HH];
__device__ __align__(256) float g_qkv   [(size_t)NTOK * NQKV];
__device__ __align__(256) float g_scores[(size_t)BBATCH * NQH * LL * LL];
__device__ __align__(256) float g_x1    [(size_t)NTOK * HH];
__device__ __align__(256) float g_x2    [(size_t)NTOK * HH];
// fp16 GEMM activation inputs
__device__ __align__(256) __half a_xcat [(size_t)NTOK * 2048];
__device__ __align__(256) __half a_xn   [(size_t)NTOK * HH];
__device__ __align__(256) __half a_ao   [(size_t)NTOK * 2048];
__device__ __align__(256) __half a_xn2  [(size_t)NTOK * HH];
__device__ __align__(256) __half a_gml  [(size_t)NTOK * II];
__device__ __align__(256) __half a_xn3  [(size_t)NTOK * HH];
// fp16 weights
__device__ __align__(256) __half w_fc   [(size_t)HH * 2048];
__device__ __align__(256) __half w_qkv  [(size_t)NQKV * HH];
__device__ __align__(256) __half w_o    [(size_t)HH * 2048];
__device__ __align__(256) __half w_gu   [(size_t)NGU * HH];     // interleaved
__device__ __align__(256) __half w_down [(size_t)HH * II];
__device__ __align__(256) __half w_lm   [(size_t)VV * HH];
// bf16 attention buffers
__device__ __align__(256) __nv_bfloat16 h_q [(size_t)BBATCH * NQH * LL * DD];
__device__ __align__(256) __nv_bfloat16 h_k [(size_t)BBATCH * NKVH * LL * DD];
__device__ __align__(256) __nv_bfloat16 h_vt[(size_t)BBATCH * NKVH * DD * LL];
__device__ __align__(256) __nv_bfloat16 h_p [(size_t)BBATCH * NQH * LL * LL];

// ---------------- helpers ----------------
__device__ __forceinline__ uint32_t smem_u32(const void* p) {
    uint32_t a;
    asm("{ .reg .u64 t; cvta.to.shared.u64 t, %1; cvt.u32.u64 %0, t; }" : "=r"(a) : "l"(p));
    return a;
}
#define SWZ(o) ((o) ^ (((o) >> 3) & 0x70))

__device__ __forceinline__ void cp16(uint32_t dst, const void* src) {
    asm volatile("cp.async.cg.shared.global [%0], [%1], 16;" :: "r"(dst), "l"(src));
}
__device__ __forceinline__ void cp_commit() { asm volatile("cp.async.commit_group;"); }
template<int N> __device__ __forceinline__ void cp_wait() {
    asm volatile("cp.async.wait_group %0;" :: "n"(N));
}
__device__ __forceinline__ void ldm_x4(uint32_t* r, uint32_t addr) {
    asm volatile("ldmatrix.sync.aligned.m8n8.x4.shared.b16 {%0,%1,%2,%3}, [%4];"
                 : "=r"(r[0]), "=r"(r[1]), "=r"(r[2]), "=r"(r[3]) : "r"(addr));
}
__device__ __forceinline__ void mma_fp16(float* c, const uint32_t* a, const uint32_t* b) {
    asm volatile(
        "mma.sync.aligned.m16n8k16.row.col.f32.f16.f16.f32 "
        "{%0,%1,%2,%3},{%4,%5,%6,%7},{%8,%9},{%0,%1,%2,%3};"
        : "+f"(c[0]), "+f"(c[1]), "+f"(c[2]), "+f"(c[3])
        : "r"(a[0]), "r"(a[1]), "r"(a[2]), "r"(a[3]), "r"(b[0]), "r"(b[1]));
}
__device__ __forceinline__ void mma_bf16(float* c, const uint32_t* a, const uint32_t* b) {
    asm volatile(
        "mma.sync.aligned.m16n8k16.row.col.f32.bf16.bf16.f32 "
        "{%0,%1,%2,%3},{%4,%5,%6,%7},{%8,%9},{%0,%1,%2,%3};"
        : "+f"(c[0]), "+f"(c[1]), "+f"(c[2]), "+f"(c[3])
        : "r"(a[0]), "r"(a[1]), "r"(a[2]), "r"(a[3]), "r"(b[0]), "r"(b[1]));
}

// block reduce (256 thr)
__device__ __forceinline__ float blk_sum(float v) {
    __shared__ float sh[8]; __shared__ float res;
    #pragma unroll
    for (int o = 16; o; o >>= 1) v += __shfl_xor_sync(0xffffffffu, v, o);
    if ((threadIdx.x & 31) == 0) sh[threadIdx.x >> 5] = v;
    __syncthreads();
    if (threadIdx.x < 32) {
        float x = (threadIdx.x < 8) ? sh[threadIdx.x] : 0.f;
        #pragma unroll
        for (int o = 4; o; o >>= 1) x += __shfl_xor_sync(0xffffffffu, x, o);
        if (threadIdx.x == 0) res = x;
    }
    __syncthreads();
    return res;
}
__device__ __forceinline__ float blk_max(float v) {
    __shared__ float sh[8]; __shared__ float res;
    #pragma unroll
    for (int o = 16; o; o >>= 1) v = fmaxf(v, __shfl_xor_sync(0xffffffffu, v, o));
    if ((threadIdx.x & 31) == 0) sh[threadIdx.x >> 5] = v;
    __syncthreads();
    if (threadIdx.x < 32) {
        float x = (threadIdx.x < 8) ? sh[threadIdx.x] : -INFINITY;
        #pragma unroll
        for (int o = 4; o; o >>= 1) x = fmaxf(x, __shfl_xor_sync(0xffffffffu, x, o));
        if (threadIdx.x == 0) res = x;
    }
    __syncthreads();
    return res;
}

// ---------------- fp16 mma GEMM: C[M,N] f32 = A[M,K]*B[N,K]^T ----------------
// CTA 128x256, warp 64x64. STAGES=4 safe: K>=1024 -> ntiles>=16 > STAGES-1.
// epi 0: plain  1: +R  4: interleaved silu -> fp16 CH [M, N/2]
#define FSTAGES 4
#define FSTAGE_BYTES (16384 + 32768)
#define FGEMM_SMEM (FSTAGES * FSTAGE_BYTES)

__global__ __launch_bounds__(256)
void gemm_fp16_kernel(const __half* __restrict__ A, const __half* __restrict__ B,
                      float* __restrict__ C, const float* __restrict__ R,
                      __half* __restrict__ CH,
                      int M, int N, int K, int epi)
{
    extern __shared__ char smch[];
    int tid = threadIdx.x;
    int m0 = blockIdx.y * 128;
    int n0 = blockIdx.x * 256;

    uint32_t smu = smem_u32(smch);
    int ntiles = K / 64;

    int lr = tid >> 3;
    int lc = (tid & 7) * 16;

    auto issue = [&](int t, int slot) {
        uint32_t bA = smu + slot * FSTAGE_BYTES;
        uint32_t bB = bA + 16384;
        long long kofs = (long long)t * 128;
        #pragma unroll
        for (int j = 0; j < 4; ++j) {
            int r = lr + j * 32;
            cp16(bA + SWZ(r * 128 + lc),
                 (const char*)(A + (long long)(m0 + r) * K) + kofs + lc);
        }
        #pragma unroll
        for (int j = 0; j < 8; ++j) {
            int r = lr + j * 32;
            cp16(bB + SWZ(r * 128 + lc),
                 (const char*)(B + (long long)(n0 + r) * K) + kofs + lc);
        }
        cp_commit();
    };

    int wid = tid >> 5, lane = tid & 31;
    int warp_m = (wid & 1) * 64;
    int warp_n = (wid >> 1) * 64;
    int blk = lane >> 3;
    int arow = (blk & 1) * 8 + (lane & 7);
    int achk = (blk >> 1) * 16;
    int brow = (blk >> 1) * 8 + (lane & 7);
    int bchk = (blk & 1) * 16;

    float acc[4][8][4];
    #pragma unroll
    for (int i = 0; i < 4; i++)
        #pragma unroll
        for (int j = 0; j < 8; j++)
            #pragma unroll
            for (int q = 0; q < 4; q++) acc[i][j][q] = 0.f;

    for (int s = 0; s < FSTAGES - 1; ++s) issue(s, s);

    for (int t = 0; t < ntiles; ++t) {
        cp_wait<FSTAGES - 2>();
        __syncthreads();
        if (t + FSTAGES - 1 < ntiles) issue(t + FSTAGES - 1, (t + FSTAGES - 1) % FSTAGES);
        uint32_t bA = smu + (t % FSTAGES) * FSTAGE_BYTES;
        uint32_t bB = bA + 16384;
        #pragma unroll
        for (int kk = 0; kk < 4; ++kk) {
            uint32_t af[4][4], bf[8][2];
            #pragma unroll
            for (int mi = 0; mi < 4; ++mi) {
                int row = warp_m + mi * 16 + arow;
                ldm_x4(af[mi], bA + SWZ(row * 128 + kk * 32 + achk));
            }
            #pragma unroll
            for (int nh = 0; nh < 4; ++nh) {
                uint32_t q[4];
                int n = warp_n + nh * 16 + brow;
                ldm_x4(q, bB + SWZ(n * 128 + kk * 32 + bchk));
                bf[nh * 2 + 0][0] = q[0]; bf[nh * 2 + 0][1] = q[1];
                bf[nh * 2 + 1][0] = q[2]; bf[nh * 2 + 1][1] = q[3];
            }
            #pragma unroll
            for (int mi = 0; mi < 4; ++mi)
                #pragma unroll
                for (int ni = 0; ni < 8; ++ni)
                    mma_fp16(acc[mi][ni], af[mi], bf[ni]);
        }
    }

    int g = lane >> 2, t4 = lane & 3;
    #pragma unroll
    for (int mi = 0; mi < 4; ++mi) {
        int r0 = m0 + warp_m + mi * 16 + g;
        int r1 = r0 + 8;
        #pragma unroll
        for (int ni = 0; ni < 8; ++ni) {
            int col = n0 + warp_n + ni * 8 + t4 * 2;
            float v0 = acc[mi][ni][0], v1 = acc[mi][ni][1];
            float v2 = acc[mi][ni][2], v3 = acc[mi][ni][3];
            if (epi == 4) {
                int oc = col >> 1;
                int halfN = N >> 1;
                float s0 = v0 * (1.f / (1.f + expf(-v0))) * v1;
                float s1 = v2 * (1.f / (1.f + expf(-v2))) * v3;
                CH[(long long)r0 * halfN + oc] = __float2half(s0);
                CH[(long long)r1 * halfN + oc] = __float2half(s1);
            } else {
                if (epi == 1) {
                    long long o0 = (long long)r0 * N + col;
                    long long o1 = (long long)r1 * N + col;
                    v0 += R[o0]; v1 += R[o0 + 1]; v2 += R[o1]; v3 += R[o1 + 1];
                }
                *(float2*)&C[(long long)r0 * N + col] = make_float2(v0, v1);
                *(float2*)&C[(long long)r1 * N + col] = make_float2(v2, v3);
            }
        }
    }
}

// ---------------- bf16 mma GEMM (attention): CTA 128x128, warp 64x32 ----------------
// STAGES=3 (MANDATORY: klimit path has ntiles as low as 2; wait<1> forces group-0 done).
// epi 2: scores (scale+causal, skip masked)   3: PV + sigmoid-gate -> fp16 ao
#define BSTAGES 3
#define BSTAGE_BYTES 32768
#define BGEMM_SMEM (BSTAGES * BSTAGE_BYTES)

__global__ __launch_bounds__(256)
void gemm_bf16_kernel(const __nv_bfloat16* __restrict__ A, const __nv_bfloat16* __restrict__ B,
                      float* __restrict__ C,
                      const float* __restrict__ QKV, __half* __restrict__ AO,
                      int M, int N, int K,
                      long long bAel, long long bBel, long long bCel,
                      int bmode, int epi, float scale, int klimit)
{
    extern __shared__ char smch[];
    int tid = threadIdx.x;
    int z = blockIdx.z;
    int m0 = blockIdx.y * 128;
    int n0 = blockIdx.x * 128;
    if (epi == 2 && n0 > m0 + 127) return;

    const __nv_bfloat16* Ab = A + (long long)z * bAel;
    long long zb = bmode ? ((long long)(z >> 3) * 2 + ((z & 7) >> 2)) : (long long)z;
    const __nv_bfloat16* Bb = B + zb * bBel;
    float* Cb = C + (long long)z * bCel;

    uint32_t smu = smem_u32(smch);
    int Keff = klimit ? min(K, m0 + 128) : K;
    int ntiles = Keff / 64;

    int lr = tid >> 3;
    int lc = (tid & 7) * 16;

    auto issue = [&](int t, int slot) {
        uint32_t bA = smu + slot * BSTAGE_BYTES;
        uint32_t bB = bA + 16384;
        long long kofs = (long long)t * 128;
        #pragma unroll
        for (int j = 0; j < 4; ++j) {
            int r = lr + j * 32;
            cp16(bA + SWZ(r * 128 + lc),
                 (const char*)(Ab + (long long)(m0 + r) * K) + kofs + lc);
        }
        #pragma unroll
        for (int j = 0; j < 4; ++j) {
            int r = lr + j * 32;
            cp16(bB + SWZ(r * 128 + lc),
                 (const char*)(Bb + (long long)(n0 + r) * K) + kofs + lc);
        }
        cp_commit();
    };

    int wid = tid >> 5, lane = tid & 31;
    int warp_m = (wid & 1) * 64;
    int warp_n = (wid >> 1) * 32;
    int blk = lane >> 3;
    int arow = (blk & 1) * 8 + (lane & 7);
    int achk = (blk >> 1) * 16;
    int brow = (blk >> 1) * 8 + (lane & 7);
    int bchk = (blk & 1) * 16;

    float acc[4][4][4];
    #pragma unroll
    for (int i = 0; i < 4; i++)
        #pragma unroll
        for (int j = 0; j < 4; j++)
            #pragma unroll
            for (int q = 0; q < 4; q++) acc[i][j][q] = 0.f;

    int pre = ntiles < (BSTAGES - 1) ? ntiles : (BSTAGES - 1);
    for (int s = 0; s < pre; ++s) issue(s, s);

    for (int t = 0; t < ntiles; ++t) {
        cp_wait<BSTAGES - 2>();
        __syncthreads();
        if (t + BSTAGES - 1 < ntiles) issue(t + BSTAGES - 1, (t + BSTAGES - 1) % BSTAGES);
        uint32_t bA = smu + (t % BSTAGES) * BSTAGE_BYTES;
        uint32_t bB = bA + 16384;
        #pragma unroll
        for (int kk = 0; kk < 4; ++kk) {
            uint32_t af[4][4], bf[4][2];
            #pragma unroll
            for (int mi = 0; mi < 4; ++mi) {
                int row = warp_m + mi * 16 + arow;
                ldm_x4(af[mi], bA + SWZ(row * 128 + kk * 32 + achk));
            }
            #pragma unroll
            for (int nh = 0; nh < 2; ++nh) {
                uint32_t q[4];
                int n = warp_n + nh * 16 + brow;
                ldm_x4(q, bB + SWZ(n * 128 + kk * 32 + bchk));
                bf[nh * 2 + 0][0] = q[0]; bf[nh * 2 + 0][1] = q[1];
                bf[nh * 2 + 1][0] = q[2]; bf[nh * 2 + 1][1] = q[3];
            }
            #pragma unroll
            for (int mi = 0; mi < 4; ++mi)
                #pragma unroll
                for (int ni = 0; ni < 4; ++ni)
                    mma_bf16(acc[mi][ni], af[mi], bf[ni]);
        }
    }

    int g = lane >> 2, t4 = lane & 3;
    int bb = z >> 3, hh = z & 7;
    #pragma unroll
    for (int mi = 0; mi < 4; ++mi) {
        int r0 = m0 + warp_m + mi * 16 + g;
        int r1 = r0 + 8;
        #pragma unroll
        for (int ni = 0; ni < 4; ++ni) {
            int col = n0 + warp_n + ni * 8 + t4 * 2;
            float v0 = acc[mi][ni][0], v1 = acc[mi][ni][1];
            float v2 = acc[mi][ni][2], v3 = acc[mi][ni][3];
            if (epi == 2) {
                v0 *= scale; v1 *= scale; v2 *= scale; v3 *= scale;
                if (col     > r0) v0 = FMIN;
                if (col + 1 > r0) v1 = FMIN;
                if (col     > r1) v2 = FMIN;
                if (col + 1 > r1) v3 = FMIN;
                *(float2*)&Cb[(long long)r0 * N + col] = make_float2(v0, v1);
                *(float2*)&Cb[(long long)r1 * N + col] = make_float2(v2, v3);
            } else {   // epi 3
                long long t0 = (long long)bb * LL + r0;
                long long t1 = (long long)bb * LL + r1;
                float g0 = QKV[t0 * NQKV + hh * 512 + 256 + col];
                float g1 = QKV[t0 * NQKV + hh * 512 + 256 + col + 1];
                float g2 = QKV[t1 * NQKV + hh * 512 + 256 + col];
                float g3 = QKV[t1 * NQKV + hh * 512 + 256 + col + 1];
                __half2 o0 = __floats2half2_rn(v0 * (1.f / (1.f + expf(-g0))),
                                               v1 * (1.f / (1.f + expf(-g1))));
                __half2 o1 = __floats2half2_rn(v2 * (1.f / (1.f + expf(-g2))),
                                               v3 * (1.f / (1.f + expf(-g3))));
                *(__half2*)&AO[t0 * 2048 + hh * 256 + col] = o0;
                *(__half2*)&AO[t1 * 2048 + hh * 256 + col] = o1;
            }
        }
    }
}

// ---------------- elementwise kernels ----------------
__global__ void convert_fp16_kernel(const float* __restrict__ in, __half* __restrict__ out, long n4) {
    long i = (long)blockIdx.x * 256 + threadIdx.x;
    if (i < n4) {
        float4 v = ((const float4*)in)[i];
        ((__half2*)out)[i * 2]     = __floats2half2_rn(v.x, v.y);
        ((__half2*)out)[i * 2 + 1] = __floats2half2_rn(v.z, v.w);
    }
}
__global__ void convert_ileave_kernel(const float* __restrict__ in, __half* __restrict__ out,
                                      long n4, int phase) {
    long i = (long)blockIdx.x * 256 + threadIdx.x;
    if (i < n4) {
        float4 v = ((const float4*)in)[i];
        long e = i * 4;
        long row = e >> 10;
        long col = e & 1023;
        __half* dst = out + ((row * 2 + phase) << 10) + col;
        ((__half2*)dst)[0] = __floats2half2_rn(v.x, v.y);
        ((__half2*)dst)[1] = __floats2half2_rn(v.z, v.w);
    }
}
__global__ void rmsnorm_h_kernel(const float* __restrict__ in, const float* __restrict__ w,
                                 __half* __restrict__ out, int width,
                                 long row_stride, long col_off) {
    long t = blockIdx.x;
    const float* x = in + t * width;
    float ss = 0.f;
    for (int i = threadIdx.x; i < width; i += 256) { float v = x[i]; ss = fmaf(v, v, ss); }
    float rms = rsqrtf(blk_sum(ss) / (float)width + 1e-6f);
    __half* y = out + t * row_stride + col_off;
    for (int i = threadIdx.x; i < width; i += 256) y[i] = __float2half(x[i] * rms * w[i]);
}
__global__ void qpost_kernel(const float* __restrict__ qkv, const float* __restrict__ qn_w,
                             __nv_bfloat16* __restrict__ qdst) {
    int t = blockIdx.x, h = blockIdx.y;
    int b = t / LL, l = t % LL;
    const float* src = qkv + (long)t * NQKV + h * 512;
    int tid = threadIdx.x;
    float v = src[tid];
    float rms = rsqrtf(blk_sum(v * v) / (float)DD + 1e-6f);
    __shared__ float sq[DD];
    sq[tid] = v * rms * qn_w[tid];
    __syncthreads();
    if (tid < 32) {
        float inv = powf(10000000.f, -2.f * (float)tid / 64.f);
        float fr = (float)l * inv;
        float c = cosf(fr), s = sinf(fr);
        float x0 = sq[2 * tid], x1 = sq[2 * tid + 1];
        sq[2 * tid]     = x0 * c - x1 * s;
        sq[2 * tid + 1] = x0 * s + x1 * c;
    }
    __syncthreads();
    long row = (long)(b * NQH + h) * LL + l;
    qdst[row * DD + tid] = __float2bfloat16(sq[tid]);
}
__global__ void kpost_kernel(const float* __restrict__ qkv, const float* __restrict__ kn_w,
                             __nv_bfloat16* __restrict__ kdst) {
    int t = blockIdx.x, h = blockIdx.y;
    int b = t / LL, l = t % LL;
    const float* src = qkv + (long)t * NQKV + 4096 + h * 256;
    int tid = threadIdx.x;
    float v = src[tid];
    float rms = rsqrtf(blk_sum(v * v) / (float)DD + 1e-6f);
    __shared__ float sq[DD];
    sq[tid] = v * rms * kn_w[tid];
    __syncthreads();
    if (tid < 32) {
        float inv = powf(10000000.f, -2.f * (float)tid / 64.f);
        float fr = (float)l * inv;
        float c = cosf(fr), s = sinf(fr);
        float x0 = sq[2 * tid], x1 = sq[2 * tid + 1];
        sq[2 * tid]     = x0 * c - x1 * s;
        sq[2 * tid + 1] = x0 * s + x1 * c;
    }
    __syncthreads();
    long row = (long)(b * NKVH + h) * LL + l;
    kdst[row * DD + tid] = __float2bfloat16(sq[tid]);
}
__global__ void vpost_kernel(const float* __restrict__ qkv, __nv_bfloat16* __restrict__ vt) {
    __shared__ float smv[32][33];
    int l0 = blockIdx.x * 32, d0 = blockIdx.y * 32, z = blockIdx.z;
    int b = z >> 1, h = z & 1;
    int tx = threadIdx.x & 31, ty = threadIdx.x >> 5;
    #pragma unroll
    for (int j = 0; j < 4; ++j) {
        int lloc = ty + j * 8;
        smv[lloc][tx] = qkv[(long)(b * LL + l0 + lloc) * NQKV + 4608 + h * 256 + d0 + tx];
    }
    __syncthreads();
    #pragma unroll
    for (int j = 0; j < 4; ++j) {
        int dd = ty + j * 8;
        vt[(long)(z * DD + d0 + dd) * LL + l0 + tx] = __float2bfloat16(smv[tx][dd]);
    }
}
__global__ void softmax_kernel(const float* __restrict__ scores, __nv_bfloat16* __restrict__ p) {
    int q = blockIdx.x, z = blockIdx.y;
    const float* row = scores + ((long)z * LL + q) * LL;
    __nv_bfloat16* prow = p + ((long)z * LL + q) * LL;
    int nwrite = ((q >> 7) + 1) << 7;
    float vals[8], mx = -INFINITY;
    #pragma unroll
    for (int i = 0; i < 8; i++) {
        int col = threadIdx.x + i * 256;
        vals[i] = (col < nwrite) ? row[col] : -INFINITY;
        mx = fmaxf(mx, vals[i]);
    }
    mx = blk_max(mx);
    float sum = 0.f;
    #pragma unroll
    for (int i = 0; i < 8; i++) { vals[i] = __expf(vals[i] - mx); sum += vals[i]; }
    sum = blk_sum(sum);
    float invs = 1.f / sum;
    #pragma unroll
    for (int i = 0; i < 8; i++) {
        int col = threadIdx.x + i * 256;
        if (col < nwrite) prow[col] = __float2bfloat16(vals[i] * invs);
    }
}

// ---------------- launch ----------------
static void launch_fp16_s(cudaStream_t st, const __half* A, const __half* B, float* C,
                          const float* R, __half* CH, int M, int N, int K, int epi) {
    dim3 grid(N / 256, M / 128, 1);
    gemm_fp16_kernel<<<grid, 256, FGEMM_SMEM, st>>>(A, B, C, R, CH, M, N, K, epi);
}

extern "C" void kernel_launch(void* const* d_in, const int* in_sizes, int n_in,
                              void* d_out, int out_size) {
    (void)in_sizes; (void)n_in; (void)out_size;
    const float* embeddings = (const float*)d_in[0];
    const float* hidden     = (const float*)d_in[1];
    const float* pre_emb_w  = (const float*)d_in[2];
    const float* pre_hid_w  = (const float*)d_in[3];
    const float* fc_w       = (const float*)d_in[4];
    const float* in_ln_w    = (const float*)d_in[5];
    const float* q_w        = (const float*)d_in[6];
    const float* k_w        = (const float*)d_in[7];
    const float* v_w        = (const float*)d_in[8];
    const float* o_w        = (const float*)d_in[9];
    const float* qn_w       = (const float*)d_in[10];
    const float* kn_w       = (const float*)d_in[11];
    const float* post_ln_w  = (const float*)d_in[12];
    const float* gate_w     = (const float*)d_in[13];
    const float* up_w       = (const float*)d_in[14];
    const float* down_w     = (const float*)d_in[15];
    const float* norm_w     = (const float*)d_in[16];
    const float* lm_w       = (const float*)d_in[17];
    float* out = (float*)d_out;

    static bool inited = false;
    static float *p_x0, *p_qkv, *p_scores, *p_x1, *p_x2;
    static __half *pa_xcat, *pa_xn, *pa_ao, *pa_xn2, *pa_gml, *pa_xn3;
    static __half *pw_fc, *pw_qkv, *pw_o, *pw_gu, *pw_down, *pw_lm;
    static __nv_bfloat16 *ph_q, *ph_k, *ph_vt, *ph_p;
    static cudaStream_t s2;
    static cudaEvent_t evFork, evJoin;
    if (!inited) {
        cudaGetSymbolAddress((void**)&p_x0, g_x0);      cudaGetSymbolAddress((void**)&p_qkv, g_qkv);
        cudaGetSymbolAddress((void**)&p_scores, g_scores);
        cudaGetSymbolAddress((void**)&p_x1, g_x1);      cudaGetSymbolAddress((void**)&p_x2, g_x2);
        cudaGetSymbolAddress((void**)&pa_xcat, a_xcat); cudaGetSymbolAddress((void**)&pa_xn, a_xn);
        cudaGetSymbolAddress((void**)&pa_ao, a_ao);     cudaGetSymbolAddress((void**)&pa_xn2, a_xn2);
        cudaGetSymbolAddress((void**)&pa_gml, a_gml);   cudaGetSymbolAddress((void**)&pa_xn3, a_xn3);
        cudaGetSymbolAddress((void**)&pw_fc, w_fc);     cudaGetSymbolAddress((void**)&pw_qkv, w_qkv);
        cudaGetSymbolAddress((void**)&pw_o, w_o);       cudaGetSymbolAddress((void**)&pw_gu, w_gu);
        cudaGetSymbolAddress((void**)&pw_down, w_down); cudaGetSymbolAddress((void**)&pw_lm, w_lm);
        cudaGetSymbolAddress((void**)&ph_q, h_q);       cudaGetSymbolAddress((void**)&ph_k, h_k);
        cudaGetSymbolAddress((void**)&ph_vt, h_vt);     cudaGetSymbolAddress((void**)&ph_p, h_p);
        cudaFuncSetAttribute(gemm_fp16_kernel, cudaFuncAttributeMaxDynamicSharedMemorySize, FGEMM_SMEM);
        cudaFuncSetAttribute(gemm_bf16_kernel, cudaFuncAttributeMaxDynamicSharedMemorySize, BGEMM_SMEM);
        cudaStreamCreateWithFlags(&s2, cudaStreamNonBlocking);
        cudaEventCreateWithFlags(&evFork, cudaEventDisableTiming);
        cudaEventCreateWithFlags(&evJoin, cudaEventDisableTiming);
        inited = true;
    }

    long n4;
    n4 = (long)HH * 2048 / 4;  convert_fp16_kernel<<<(n4 + 255) / 256, 256>>>(fc_w, pw_fc, n4);
    n4 = (long)4096 * HH / 4;  convert_fp16_kernel<<<(n4 + 255) / 256, 256>>>(q_w, pw_qkv, n4);
    n4 = (long)512 * HH / 4;   convert_fp16_kernel<<<(n4 + 255) / 256, 256>>>(k_w, pw_qkv + (size_t)4096 * HH, n4);
    n4 = (long)512 * HH / 4;   convert_fp16_kernel<<<(n4 + 255) / 256, 256>>>(v_w, pw_qkv + (size_t)4608 * HH, n4);

    cudaEventRecord(evFork, 0);
    cudaStreamWaitEvent(s2, evFork, 0);
    n4 = (long)HH * 2048 / 4;  convert_fp16_kernel<<<(n4 + 255) / 256, 256, 0, s2>>>(o_w, pw_o, n4);
    n4 = (long)II * HH / 4;    convert_ileave_kernel<<<(n4 + 255) / 256, 256, 0, s2>>>(gate_w, pw_gu, n4, 0);
    n4 = (long)II * HH / 4;    convert_ileave_kernel<<<(n4 + 255) / 256, 256, 0, s2>>>(up_w,   pw_gu, n4, 1);
    n4 = (long)HH * II / 4;    convert_fp16_kernel<<<(n4 + 255) / 256, 256, 0, s2>>>(down_w, pw_down, n4);
    n4 = (long)VV * HH / 4;    convert_fp16_kernel<<<(n4 + 255) / 256, 256, 0, s2>>>(lm_w, pw_lm, n4);
    cudaEventRecord(evJoin, s2);

    rmsnorm_h_kernel<<<NTOK, 256>>>(embeddings, pre_emb_w, pa_xcat, HH, 2048, 0);
    rmsnorm_h_kernel<<<NTOK, 256>>>(hidden,     pre_hid_w, pa_xcat, HH, 2048, 1024);
    launch_fp16_s(0, pa_xcat, pw_fc, p_x0, nullptr, nullptr, NTOK, HH, 2048, 0);
    rmsnorm_h_kernel<<<NTOK, 256>>>(p_x0, in_ln_w, pa_xn, HH, 1024, 0);
    launch_fp16_s(0, pa_xn, pw_qkv, p_qkv, nullptr, nullptr, NTOK, NQKV, HH, 0);
    qpost_kernel<<<dim3(NTOK, NQH), 256>>>(p_qkv, qn_w, ph_q);
    kpost_kernel<<<dim3(NTOK, NKVH), 256>>>(p_qkv, kn_w, ph_k);
    vpost_kernel<<<dim3(LL / 32, DD / 32, BBATCH * NKVH), 256>>>(p_qkv, ph_vt);
    {
        dim3 grid(LL / 128, LL / 128, BBATCH * NQH);
        gemm_bf16_kernel<<<grid, 256, BGEMM_SMEM>>>(ph_q, ph_k, p_scores, nullptr, nullptr,
            LL, LL, DD, (long long)LL * DD, (long long)LL * DD, (long long)LL * LL,
            1, 2, 0.0625f, 0);
    }
    softmax_kernel<<<dim3(LL, BBATCH * NQH), 256>>>(p_scores, ph_p);
    {
        dim3 grid(DD / 128, LL / 128, BBATCH * NQH);
        gemm_bf16_kernel<<<grid, 256, BGEMM_SMEM>>>(ph_p, ph_vt, nullptr, p_qkv, pa_ao,
            LL, DD, LL, (long long)LL * LL, (long long)DD * LL, 0,
            1, 3, 1.f, 1);
    }
    cudaStreamWaitEvent(0, evJoin, 0);
    launch_fp16_s(0, pa_ao, pw_o, p_x1, p_x0, nullptr, NTOK, HH, 2048, 1);
    rmsnorm_h_kernel<<<NTOK, 256>>>(p_x1, post_ln_w, pa_xn2, HH, 1024, 0);
    launch_fp16_s(0, pa_xn2, pw_gu, nullptr, nullptr, pa_gml, NTOK, NGU, HH, 4);
    launch_fp16_s(0, pa_gml, pw_down, p_x2, p_x1, nullptr, NTOK, HH, II, 1);
    rmsnorm_h_kernel<<<NTOK, 256>>>(p_x2, norm_w, pa_xn3, HH, 1024, 0);
    launch_fp16_s(0, pa_xn3, pw_lm, out, nullptr, nullptr, NTOK, VV, HH, 0);
}